// round 8
// baseline (speedup 1.0000x reference)
#include <cuda_runtime.h>
#include <cuda_bf16.h>
#include <math.h>
#include <stdint.h>

// Problem constants
#define BB   2
#define TT   2048
#define CC   1024
#define NH   16
#define LAT  512
#define DHR  64
#define MR   (BB*TT)        // 4096 rows

// ---------------------------------------------------------------------------
// Scratch (static device globals)
// ---------------------------------------------------------------------------
__device__ float g_kr [MR * 64];
__device__ float g_qr [MR * 1024];
__device__ float g_kv [MR * 2048];   // k cols 0..1023, v cols 1024..2047
__device__ float g_q  [MR * 1024];

// bf16 hi/lo split pairs (x ~= hi + lo)
__device__ __nv_bfloat16 g_xh[MR*1024],  g_xl[MR*1024];
__device__ __nv_bfloat16 g_hh[MR*1024],  g_hl[MR*1024];
__device__ __nv_bfloat16 g_ath[MR*1024], g_atl[MR*1024];
// transposed+split weights [N,K]
__device__ __nv_bfloat16 g_w1h [1024*1024], g_w1l [1024*1024];
__device__ __nv_bfloat16 g_wkrh[64*1024],   g_wkrl[64*1024];
__device__ __nv_bfloat16 g_wqrh[1024*1024], g_wqrl[1024*1024];
__device__ __nv_bfloat16 g_wkvh[2048*512],  g_wkvl[2048*512];
__device__ __nv_bfloat16 g_wqh [1024*512],  g_wql [1024*512];
__device__ __nv_bfloat16 g_woh [1024*1024], g_wol [1024*1024];

// ---------------------------------------------------------------------------
// helpers
// ---------------------------------------------------------------------------
__device__ __forceinline__ uint32_t f2tf(float f) {
    uint32_t u;
    asm("cvt.rna.tf32.f32 %0, %1;" : "=r"(u) : "f"(f));
    return u;
}
__device__ __forceinline__ void mma8(float* c,
                                     uint32_t a0, uint32_t a1, uint32_t a2, uint32_t a3,
                                     uint32_t b0, uint32_t b1) {
    asm volatile(
        "mma.sync.aligned.m16n8k8.row.col.f32.tf32.tf32.f32 "
        "{%0,%1,%2,%3},{%4,%5,%6,%7},{%8,%9},{%0,%1,%2,%3};"
        : "+f"(c[0]), "+f"(c[1]), "+f"(c[2]), "+f"(c[3])
        : "r"(a0), "r"(a1), "r"(a2), "r"(a3), "r"(b0), "r"(b1));
}
__device__ __forceinline__ void mma16(float* c, const uint32_t* a,
                                      uint32_t b0, uint32_t b1) {
    asm volatile(
        "mma.sync.aligned.m16n8k16.row.col.f32.bf16.bf16.f32 "
        "{%0,%1,%2,%3},{%4,%5,%6,%7},{%8,%9},{%0,%1,%2,%3};"
        : "+f"(c[0]), "+f"(c[1]), "+f"(c[2]), "+f"(c[3])
        : "r"(a[0]), "r"(a[1]), "r"(a[2]), "r"(a[3]), "r"(b0), "r"(b1));
}
// ldmatrix x4 (non-trans). For f32 operands: one 8x8 b16 matrix = 8x4 f32 block.
__device__ __forceinline__ void ldsm4(uint32_t& r0, uint32_t& r1,
                                      uint32_t& r2, uint32_t& r3, uint32_t addr) {
    asm volatile("ldmatrix.sync.aligned.m8n8.x4.shared.b16 {%0,%1,%2,%3}, [%4];"
                 : "=r"(r0), "=r"(r1), "=r"(r2), "=r"(r3) : "r"(addr));
}
__device__ __forceinline__ void split2(float x, float y, uint32_t& hi, uint32_t& lo) {
    uint32_t h, l;
    asm("cvt.rn.bf16x2.f32 %0, %1, %2;" : "=r"(h) : "f"(y), "f"(x));
    float hx = __uint_as_float(h << 16);
    float hy = __uint_as_float(h & 0xffff0000u);
    float lx = x - hx;
    float ly = y - hy;
    asm("cvt.rn.bf16x2.f32 %0, %1, %2;" : "=r"(l) : "f"(ly), "f"(lx));
    hi = h; lo = l;
}
__device__ __forceinline__ uint32_t sptr(const void* p) {
    return (uint32_t)__cvta_generic_to_shared(p);
}
__device__ __forceinline__ void cp16(uint32_t dst, const void* src) {
    asm volatile("cp.async.cg.shared.global [%0], [%1], 16;" :: "r"(dst), "l"(src));
}
__device__ __forceinline__ void cp_commit() {
    asm volatile("cp.async.commit_group;");
}
template<int N> __device__ __forceinline__ void cp_wait() {
    asm volatile("cp.async.wait_group %0;" :: "n"(N));
}

// ---------------------------------------------------------------------------
// Weight transpose + split: W[K,N] fp32 -> Wh,Wl[N,K] bf16
// ---------------------------------------------------------------------------
__global__ void wsplit_kernel(const float* __restrict__ W, int K, int N,
                              __nv_bfloat16* __restrict__ Wh,
                              __nv_bfloat16* __restrict__ Wl)
{
    __shared__ float tile[32][33];
    int n0 = blockIdx.x * 32, k0 = blockIdx.y * 32;
    int tx = threadIdx.x, ty = threadIdx.y;
#pragma unroll
    for (int i = 0; i < 32; i += 8)
        tile[ty + i][tx] = W[(size_t)(k0 + ty + i) * N + n0 + tx];
    __syncthreads();
#pragma unroll
    for (int i = 0; i < 32; i += 8) {
        int n = n0 + ty + i, k = k0 + tx;
        float v = tile[tx][ty + i];
        __nv_bfloat16 h = __float2bfloat16(v);
        float lo = v - __bfloat162float(h);
        Wh[(size_t)n * K + k] = h;
        Wl[(size_t)n * K + k] = __float2bfloat16(lo);
    }
}

__global__ void asplit_kernel(const float4* __restrict__ X,
                              uint2* __restrict__ Xh, uint2* __restrict__ Xl, int n4)
{
    int i = blockIdx.x * blockDim.x + threadIdx.x;
    if (i >= n4) return;
    float4 v = X[i];
    uint32_t h0, l0, h1, l1;
    split2(v.x, v.y, h0, l0);
    split2(v.z, v.w, h1, l1);
    Xh[i] = make_uint2(h0, h1);
    Xl[i] = make_uint2(l0, l1);
}

// ---------------------------------------------------------------------------
// Split-bf16 3-pass mma.sync GEMM, pre-split operands, ldmatrix fragments.
// ---------------------------------------------------------------------------
template<int BN, bool SPLIT_OUT, bool TF32O>
__global__ __launch_bounds__(256, 2)
void gemm_bf16_3x(int N, int K,
                  const __nv_bfloat16* __restrict__ Agh,
                  const __nv_bfloat16* __restrict__ Agl, int lda,
                  const __nv_bfloat16* __restrict__ Bgh,
                  const __nv_bfloat16* __restrict__ Bgl,
                  const float* __restrict__ bias, float oscale,
                  float* __restrict__ C,
                  __nv_bfloat16* __restrict__ Ch,
                  __nv_bfloat16* __restrict__ Cl)
{
    constexpr int BM   = 128;
    constexpr int WM   = BM / 4;
    constexpr int WN   = BN / 2;
    constexpr int MT   = WM / 16;
    constexpr int NT   = WN / 8;
    constexpr int STR  = 40;
    constexpr int ASL  = BM * STR;            // elems
    constexpr int BSL  = BN * STR;
    constexpr int STG  = 2 * ASL + 2 * BSL;
    constexpr int NAC  = (BM * 4) / 256;
    constexpr int NBC  = (BN * 4) / 256;

    extern __shared__ __nv_bfloat16 smb[];

    const int tid  = threadIdx.x;
    const int lane = tid & 31;
    const int warp = tid >> 5;
    const int g    = lane >> 2;
    const int t    = lane & 3;
    const int lq   = lane >> 3;      // ldmatrix quadrant
    const int li   = lane & 7;
    const int wm   = warp >> 1;
    const int wn   = warp & 1;
    const int bRow = blockIdx.y * BM;
    const int bCol = blockIdx.x * BN;

    float acc[MT][NT][4];
#pragma unroll
    for (int mt = 0; mt < MT; mt++)
#pragma unroll
        for (int nt = 0; nt < NT; nt++)
#pragma unroll
            for (int i = 0; i < 4; i++) acc[mt][nt][i] = 0.f;

    auto issue = [&](int k0, int s) {
        __nv_bfloat16* st = smb + s * STG;
#pragma unroll
        for (int i = 0; i < NAC; i++) {
            int idx = tid + i * 256;
            int r = idx >> 2, c = idx & 3;
            uint32_t d = sptr(st + r * STR + c * 8);
            cp16(d, Agh + (size_t)(bRow + r) * lda + k0 + c * 8);
            cp16(d + ASL * 2, Agl + (size_t)(bRow + r) * lda + k0 + c * 8);
        }
#pragma unroll
        for (int i = 0; i < NBC; i++) {
            int idx = tid + i * 256;
            int r = idx >> 2, c = idx & 3;
            uint32_t d = sptr(st + 2 * ASL + r * STR + c * 8);
            cp16(d, Bgh + (size_t)(bCol + r) * K + k0 + c * 8);
            cp16(d + BSL * 2, Bgl + (size_t)(bCol + r) * K + k0 + c * 8);
        }
        cp_commit();
    };

    // per-lane ldmatrix byte offsets within a stage
    const uint32_t smbase = sptr(smb);
    const uint32_t aLane = (uint32_t)((((lq & 1) * 8 + li + wm * WM) * STR) * 2 + (lq >> 1) * 16);
    const uint32_t bLane = (uint32_t)(4 * ASL + (((lq & 1) * 8 + li + wn * WN) * STR) * 2 + (lq >> 1) * 16);

    const int iters = K / 32;
    issue(0, 0);

    for (int it = 0; it < iters; it++) {
        const int cur = it & 1;
        if (it + 1 < iters) { issue((it + 1) * 32, cur ^ 1); cp_wait<1>(); }
        else                { cp_wait<0>(); }
        __syncthreads();

        const uint32_t stg = smbase + cur * (STG * 2);

#pragma unroll
        for (int s = 0; s < 2; s++) {
            uint32_t ah[MT][4], al[MT][4];
#pragma unroll
            for (int mt = 0; mt < MT; mt++) {
                uint32_t ad = stg + aLane + mt * (16 * STR * 2) + s * 32;
                ldsm4(ah[mt][0], ah[mt][1], ah[mt][2], ah[mt][3], ad);
                ldsm4(al[mt][0], al[mt][1], al[mt][2], al[mt][3], ad + 2 * ASL);
            }
#pragma unroll
            for (int ntp = 0; ntp < NT / 2; ntp++) {
                uint32_t bd = stg + bLane + ntp * (16 * STR * 2) + s * 32;
                uint32_t bh0e, bh0o, bh1e, bh1o, bl0e, bl0o, bl1e, bl1o;
                ldsm4(bh0e, bh0o, bh1e, bh1o, bd);
                ldsm4(bl0e, bl0o, bl1e, bl1o, bd + 2 * BSL);
#pragma unroll
                for (int mt = 0; mt < MT; mt++) {
                    mma16(acc[mt][2*ntp],   ah[mt], bh0e, bh1e);
                    mma16(acc[mt][2*ntp],   ah[mt], bl0e, bl1e);
                    mma16(acc[mt][2*ntp],   al[mt], bh0e, bh1e);
                    mma16(acc[mt][2*ntp+1], ah[mt], bh0o, bh1o);
                    mma16(acc[mt][2*ntp+1], ah[mt], bl0o, bl1o);
                    mma16(acc[mt][2*ntp+1], al[mt], bh0o, bh1o);
                }
            }
        }
        __syncthreads();
    }

#pragma unroll
    for (int mt = 0; mt < MT; mt++) {
        int r0 = bRow + wm * WM + mt * 16 + g;
#pragma unroll
        for (int nt = 0; nt < NT; nt++) {
            int col = bCol + wn * WN + nt * 8 + 2 * t;
            float bx = bias[col], by = bias[col + 1];
            float v00 = (acc[mt][nt][0] + bx) * oscale, v01 = (acc[mt][nt][1] + by) * oscale;
            float v10 = (acc[mt][nt][2] + bx) * oscale, v11 = (acc[mt][nt][3] + by) * oscale;
            if (TF32O) {
                v00 = __uint_as_float(f2tf(v00)); v01 = __uint_as_float(f2tf(v01));
                v10 = __uint_as_float(f2tf(v10)); v11 = __uint_as_float(f2tf(v11));
            }
            if (!SPLIT_OUT) {
                float2 a = {v00, v01}, b = {v10, v11};
                *reinterpret_cast<float2*>(C + (size_t)r0 * N + col)       = a;
                *reinterpret_cast<float2*>(C + (size_t)(r0 + 8) * N + col) = b;
            } else {
                uint32_t h0, l0, h1, l1;
                split2(v00, v01, h0, l0);
                split2(v10, v11, h1, l1);
                *reinterpret_cast<uint32_t*>(&Ch[(size_t)r0 * N + col])       = h0;
                *reinterpret_cast<uint32_t*>(&Cl[(size_t)r0 * N + col])       = l0;
                *reinterpret_cast<uint32_t*>(&Ch[(size_t)(r0 + 8) * N + col]) = h1;
                *reinterpret_cast<uint32_t*>(&Cl[(size_t)(r0 + 8) * N + col]) = l1;
            }
        }
    }
}

// ---------------------------------------------------------------------------
// RoPE in-place; output rounded to tf32 grid.
// ---------------------------------------------------------------------------
__global__ void rope_kernel(float* __restrict__ x, int D)
{
    const int pairs = D / 2;
    int idx = blockIdx.x * blockDim.x + threadIdx.x;
    if (idx >= MR * pairs) return;
    int row = idx / pairs;
    int i   = idx - row * pairs;
    int t   = row & (TT - 1);

    float theta = expf(-2.0f * (float)i / (float)D * 9.2103403719761836f);
    float ang   = (float)(t + 1) * theta;
    float sn, cs;
    sincosf(ang, &sn, &cs);

    float* p = x + (size_t)row * D + 2*i;
    float e = p[0], o = p[1];
    p[0] = __uint_as_float(f2tf(e * cs - o * sn));
    p[1] = __uint_as_float(f2tf(o * cs + e * sn));
}

// ---------------------------------------------------------------------------
// Causal flash attention, tf32 mma.sync + ldmatrix fragments.
// ---------------------------------------------------------------------------
#define QST 132
#define KST 132
#define VST 72
#define PST 68

#define OFF_K (128 * QST)
#define OFF_V (OFF_K + 2 * 64 * KST)
#define OFF_P (OFF_V + 2 * 64 * VST)
#define ATT_WORDS (OFF_P + 128 * PST)   // 206848 B

__global__ __launch_bounds__(256, 1)
void attn_tc_kernel()
{
    extern __shared__ float sm[];
    float* Qs = sm;
    float* Ps = sm + OFF_P;

    const int tid  = threadIdx.x;
    const int lane = tid & 31;
    const int warp = tid >> 5;
    const int g    = lane >> 2;
    const int t    = lane & 3;
    const int lq   = lane >> 3;
    const int li   = lane & 7;
    const int qt   = (gridDim.x - 1) - blockIdx.x;   // heavy blocks first
    const int hh   = blockIdx.y;
    const int b    = blockIdx.z;
    const int rowBase = b * TT + qt * 128;

    auto issueKV = [&](int j, int s) {
        float* Kt = sm + OFF_K + s * 64 * KST;
        float* Vt = sm + OFF_V + s * 64 * VST;
        const int kbase = b * TT + j * 64;
#pragma unroll
        for (int i = 0; i < 8; i++) {
            int idx = tid + i * 256;
            int r = idx >> 5, c = idx & 31;
            uint32_t d = sptr(Kt + r * KST + c * 4);
            if (c < 16) cp16(d, g_kv + (size_t)(kbase + r) * 2048 + hh * 64 + c * 4);
            else        cp16(d, g_kr + (size_t)(kbase + r) * 64 + (c - 16) * 4);
        }
#pragma unroll
        for (int i = 0; i < 4; i++) {
            int idx = tid + i * 256;
            int r = idx >> 4, c = idx & 15;
            cp16(sptr(Vt + r * VST + c * 4),
                 g_kv + (size_t)(kbase + r) * 2048 + 1024 + hh * 64 + c * 4);
        }
        cp_commit();
    };

    // Q tile + first K/V tile
#pragma unroll
    for (int i = 0; i < 16; i++) {
        int idx = tid + i * 256;
        int r = idx >> 5, c = idx & 31;
        uint32_t d = sptr(Qs + r * QST + c * 4);
        if (c < 16) cp16(d, g_q  + (size_t)(rowBase + r) * 1024 + hh * 64 + c * 4);
        else        cp16(d, g_qr + (size_t)(rowBase + r) * 1024 + hh * 64 + (c - 16) * 4);
    }
    issueKV(0, 0);

    // per-lane ldmatrix byte addresses
    const uint32_t qBase = sptr(Qs) + (((warp * 16 + (lq & 1) * 8 + li) * QST) + (lq >> 1) * 4) * 4;
    const uint32_t pBase = sptr(Ps) + (((warp * 16 + (lq & 1) * 8 + li) * PST) + (lq >> 1) * 4) * 4;
    const uint32_t kLane = (((lq & 1) * 8 + li) * KST + (lq >> 1) * 4) * 4;

    const int rloc0 = warp * 16 + g;
    float m0 = -1e30f, m1 = -1e30f, l0 = 0.f, l1 = 0.f;
    float o[8][4];
#pragma unroll
    for (int nt = 0; nt < 8; nt++)
#pragma unroll
        for (int i = 0; i < 4; i++) o[nt][i] = 0.f;

    const int nkt = 2 * qt + 2;
    for (int j = 0; j < nkt; j++) {
        const int s = j & 1;
        if (j + 1 < nkt) { issueKV(j + 1, s ^ 1); cp_wait<1>(); }
        else             { cp_wait<0>(); }
        __syncthreads();

        const uint32_t kBufBase = sptr(sm + OFF_K + s * 64 * KST);
        const float* Vt = sm + OFF_V + s * 64 * VST;

        // --- S = Q @ K^T -----------------------------------------------------
        float sc[8][4];
#pragma unroll
        for (int nt = 0; nt < 8; nt++)
#pragma unroll
            for (int i = 0; i < 4; i++) sc[nt][i] = 0.f;

#pragma unroll
        for (int ks = 0; ks < 16; ks++) {
            uint32_t a0, a1, a2, a3;
            ldsm4(a0, a1, a2, a3, qBase + ks * 32);
#pragma unroll
            for (int ntp = 0; ntp < 4; ntp++) {
                uint32_t b0e, b0o, b1e, b1o;
                ldsm4(b0e, b0o, b1e, b1o,
                      kBufBase + kLane + ntp * (16 * KST * 4) + ks * 32);
                mma8(sc[2*ntp],   a0, a1, a2, a3, b0e, b1e);
                mma8(sc[2*ntp+1], a0, a1, a2, a3, b0o, b1o);
            }
        }

        // --- causal mask -----------------------------------------------------
        if (j >= 2 * qt) {
            int rg0 = qt * 128 + rloc0;
            int k0 = j * 64;
#pragma unroll
            for (int nt = 0; nt < 8; nt++) {
                int cg = k0 + nt * 8 + 2 * t;
                if (cg     > rg0)     sc[nt][0] = -1e30f;
                if (cg + 1 > rg0)     sc[nt][1] = -1e30f;
                if (cg     > rg0 + 8) sc[nt][2] = -1e30f;
                if (cg + 1 > rg0 + 8) sc[nt][3] = -1e30f;
            }
        }

        // --- online softmax (registers + 4-lane shfl) ------------------------
        float mx0 = -1e30f, mx1 = -1e30f;
#pragma unroll
        for (int nt = 0; nt < 8; nt++) {
            mx0 = fmaxf(mx0, fmaxf(sc[nt][0], sc[nt][1]));
            mx1 = fmaxf(mx1, fmaxf(sc[nt][2], sc[nt][3]));
        }
        mx0 = fmaxf(mx0, __shfl_xor_sync(0xffffffffu, mx0, 1));
        mx0 = fmaxf(mx0, __shfl_xor_sync(0xffffffffu, mx0, 2));
        mx1 = fmaxf(mx1, __shfl_xor_sync(0xffffffffu, mx1, 1));
        mx1 = fmaxf(mx1, __shfl_xor_sync(0xffffffffu, mx1, 2));

        float mn0 = fmaxf(m0, mx0), mn1 = fmaxf(m1, mx1);
        float al0 = __expf(m0 - mn0), al1 = __expf(m1 - mn1);
        m0 = mn0; m1 = mn1;

        float sum0 = 0.f, sum1 = 0.f;
#pragma unroll
        for (int nt = 0; nt < 8; nt++) {
            float p0 = __expf(sc[nt][0] - mn0);
            float p1 = __expf(sc[nt][1] - mn0);
            float p2 = __expf(sc[nt][2] - mn1);
            float p3 = __expf(sc[nt][3] - mn1);
            sum0 += p0 + p1; sum1 += p2 + p3;
            float2 w0 = {__uint_as_float(f2tf(p0)), __uint_as_float(f2tf(p1))};
            float2 w1 = {__uint_as_float(f2tf(p2)), __uint_as_float(f2tf(p3))};
            *reinterpret_cast<float2*>(&Ps[(rloc0)     * PST + nt * 8 + 2 * t]) = w0;
            *reinterpret_cast<float2*>(&Ps[(rloc0 + 8) * PST + nt * 8 + 2 * t]) = w1;
        }
        sum0 += __shfl_xor_sync(0xffffffffu, sum0, 1);
        sum0 += __shfl_xor_sync(0xffffffffu, sum0, 2);
        sum1 += __shfl_xor_sync(0xffffffffu, sum1, 1);
        sum1 += __shfl_xor_sync(0xffffffffu, sum1, 2);
        l0 = l0 * al0 + sum0;
        l1 = l1 * al1 + sum1;

#pragma unroll
        for (int nt = 0; nt < 8; nt++) {
            o[nt][0] *= al0; o[nt][1] *= al0;
            o[nt][2] *= al1; o[nt][3] *= al1;
        }
        __syncwarp();   // Ps exchange is intra-warp only

        // --- O += P @ V ------------------------------------------------------
#pragma unroll
        for (int ks = 0; ks < 8; ks++) {
            uint32_t a0, a1, a2, a3;
            ldsm4(a0, a1, a2, a3, pBase + ks * 32);
#pragma unroll
            for (int nt = 0; nt < 8; nt++) {
                uint32_t b0 = __float_as_uint(Vt[(ks * 8 + t)     * VST + nt * 8 + g]);
                uint32_t b1 = __float_as_uint(Vt[(ks * 8 + t + 4) * VST + nt * 8 + g]);
                mma8(o[nt], a0, a1, a2, a3, b0, b1);
            }
        }
        __syncthreads();   // done with buf s before next iter overwrites it
    }

    // finalize + store split bf16 (att feeds only the wo GEMM)
    float inv0 = 1.0f / l0, inv1 = 1.0f / l1;
    int rg = rowBase + rloc0;
#pragma unroll
    for (int nt = 0; nt < 8; nt++) {
        int col = hh * 64 + nt * 8 + 2 * t;
        uint32_t h0, l0u, h1, l1u;
        split2(o[nt][0] * inv0, o[nt][1] * inv0, h0, l0u);
        split2(o[nt][2] * inv1, o[nt][3] * inv1, h1, l1u);
        *reinterpret_cast<uint32_t*>(&g_ath[(size_t)rg       * 1024 + col]) = h0;
        *reinterpret_cast<uint32_t*>(&g_atl[(size_t)rg       * 1024 + col]) = l0u;
        *reinterpret_cast<uint32_t*>(&g_ath[(size_t)(rg + 8) * 1024 + col]) = h1;
        *reinterpret_cast<uint32_t*>(&g_atl[(size_t)(rg + 8) * 1024 + col]) = l1u;
    }
}

// ---------------------------------------------------------------------------
// Launch
// ---------------------------------------------------------------------------
extern "C" void kernel_launch(void* const* d_in, const int* in_sizes, int n_in,
                              void* d_out, int out_size)
{
    (void)in_sizes; (void)n_in; (void)out_size;
    const float* x   = (const float*)d_in[0];
    const float* w1  = (const float*)d_in[1];
    const float* b1  = (const float*)d_in[2];
    const float* wkr = (const float*)d_in[3];
    const float* bkr = (const float*)d_in[4];
    const float* wqr = (const float*)d_in[5];
    const float* bqr = (const float*)d_in[6];
    const float* wkv = (const float*)d_in[7];
    const float* bkv = (const float*)d_in[8];
    const float* wq  = (const float*)d_in[9];
    const float* bq  = (const float*)d_in[10];
    const float* wo  = (const float*)d_in[11];
    const float* bo  = (const float*)d_in[12];
    float* out = (float*)d_out;
    const float scale = 0.08838834764831845f;   // 128^-0.5

    float *kr_, *qr_, *kv_, *q_;
    __nv_bfloat16 *xh_, *xl_, *hh_, *hl_, *ath_, *atl_;
    __nv_bfloat16 *w1h_, *w1l_, *wkrh_, *wkrl_, *wqrh_, *wqrl_;
    __nv_bfloat16 *wkvh_, *wkvl_, *wqh_, *wql_, *woh_, *wol_;
    cudaGetSymbolAddress((void**)&kr_,  g_kr);
    cudaGetSymbolAddress((void**)&qr_,  g_qr);
    cudaGetSymbolAddress((void**)&kv_,  g_kv);
    cudaGetSymbolAddress((void**)&q_,   g_q);
    cudaGetSymbolAddress((void**)&xh_,  g_xh);  cudaGetSymbolAddress((void**)&xl_,  g_xl);
    cudaGetSymbolAddress((void**)&hh_,  g_hh);  cudaGetSymbolAddress((void**)&hl_,  g_hl);
    cudaGetSymbolAddress((void**)&ath_, g_ath); cudaGetSymbolAddress((void**)&atl_, g_atl);
    cudaGetSymbolAddress((void**)&w1h_, g_w1h);  cudaGetSymbolAddress((void**)&w1l_, g_w1l);
    cudaGetSymbolAddress((void**)&wkrh_, g_wkrh); cudaGetSymbolAddress((void**)&wkrl_, g_wkrl);
    cudaGetSymbolAddress((void**)&wqrh_, g_wqrh); cudaGetSymbolAddress((void**)&wqrl_, g_wqrl);
    cudaGetSymbolAddress((void**)&wkvh_, g_wkvh); cudaGetSymbolAddress((void**)&wkvl_, g_wkvl);
    cudaGetSymbolAddress((void**)&wqh_, g_wqh);   cudaGetSymbolAddress((void**)&wql_, g_wql);
    cudaGetSymbolAddress((void**)&woh_, g_woh);   cudaGetSymbolAddress((void**)&wol_, g_wol);

    const int SMG128 = 2 * (2 * 128 * 40 + 2 * 128 * 40) * 2;   // 81920
    const int SMG64  = 2 * (2 * 128 * 40 + 2 * 64  * 40) * 2;   // 61440
    const int SMAT   = ATT_WORDS * 4;                            // 206848
    cudaFuncSetAttribute(gemm_bf16_3x<128, true,  false>, cudaFuncAttributeMaxDynamicSharedMemorySize, SMG128);
    cudaFuncSetAttribute(gemm_bf16_3x<128, false, true>,  cudaFuncAttributeMaxDynamicSharedMemorySize, SMG128);
    cudaFuncSetAttribute(gemm_bf16_3x<128, false, false>, cudaFuncAttributeMaxDynamicSharedMemorySize, SMG128);
    cudaFuncSetAttribute(gemm_bf16_3x<64,  false, false>, cudaFuncAttributeMaxDynamicSharedMemorySize, SMG64);
    cudaFuncSetAttribute(attn_tc_kernel, cudaFuncAttributeMaxDynamicSharedMemorySize, SMAT);

    dim3 wsb(32, 8);
    wsplit_kernel<<<dim3(1024/32, 1024/32), wsb>>>(w1,  1024, 1024, w1h_,  w1l_);
    wsplit_kernel<<<dim3(64/32,   1024/32), wsb>>>(wkr, 1024, 64,   wkrh_, wkrl_);
    wsplit_kernel<<<dim3(1024/32, 1024/32), wsb>>>(wqr, 1024, 1024, wqrh_, wqrl_);
    wsplit_kernel<<<dim3(2048/32, 512/32),  wsb>>>(wkv, 512,  2048, wkvh_, wkvl_);
    wsplit_kernel<<<dim3(1024/32, 512/32),  wsb>>>(wq,  512,  1024, wqh_,  wql_);
    wsplit_kernel<<<dim3(1024/32, 1024/32), wsb>>>(wo,  1024, 1024, woh_,  wol_);
    asplit_kernel<<<(MR * 1024 / 4 + 255) / 256, 256>>>(
        (const float4*)x, (uint2*)xh_, (uint2*)xl_, MR * 1024 / 4);

    // 1) h = x @ w1 + b1  -> split bf16 h
    gemm_bf16_3x<128, true, false><<<dim3(8, 32), 256, SMG128>>>(
        1024, 1024, xh_, xl_, 1024, w1h_, w1l_, b1, 1.f, nullptr, hh_, hl_);

    // 2) kr = rope(h @ wkr + bkr)   (rope rounds to tf32)
    gemm_bf16_3x<64, false, false><<<dim3(1, 32), 256, SMG64>>>(
        64, 1024, hh_, hl_, 1024, wkrh_, wkrl_, bkr, 1.f, kr_, nullptr, nullptr);
    rope_kernel<<<(MR * 32 + 255) / 256, 256>>>(kr_, 64);

    // 3) qr = rope((h @ wqr + bqr) * scale)  (scale folded; rope rounds to tf32)
    gemm_bf16_3x<128, false, false><<<dim3(8, 32), 256, SMG128>>>(
        1024, 1024, hh_, hl_, 1024, wqrh_, wqrl_, bqr, scale, qr_, nullptr, nullptr);
    rope_kernel<<<(MR * 512 + 255) / 256, 256>>>(qr_, 1024);

    // 4) kv = cKV @ wkv + bkv  -> tf32-rounded
    gemm_bf16_3x<128, false, true><<<dim3(16, 32), 256, SMG128>>>(
        2048, 512, hh_, hl_, 1024, wkvh_, wkvl_, bkv, 1.f, kv_, nullptr, nullptr);

    // 5) q = (cq @ wq + bq) * scale  -> tf32-rounded
    gemm_bf16_3x<128, false, true><<<dim3(8, 32), 256, SMG128>>>(
        1024, 512, hh_ + 512, hl_ + 512, 1024, wqh_, wql_, bq, scale, q_, nullptr, nullptr);

    // 6) attention -> split bf16 att
    attn_tc_kernel<<<dim3(16, NH, BB), 256, SMAT>>>();

    // 7) out = att @ wo + bo
    gemm_bf16_3x<128, false, false><<<dim3(8, 32), 256, SMG128>>>(
        1024, 1024, ath_, atl_, 1024, woh_, wol_, bo, 1.f, out, nullptr, nullptr);
}

// round 9
// speedup vs baseline: 1.2256x; 1.2256x over previous
#include <cuda_runtime.h>
#include <cuda_bf16.h>
#include <cuda_fp16.h>
#include <math.h>
#include <stdint.h>

// Problem constants
#define BB   2
#define TT   2048
#define CC   1024
#define NH   16
#define LAT  512
#define DHR  64
#define MR   (BB*TT)        // 4096 rows

// ---------------------------------------------------------------------------
// Scratch (static device globals)
// ---------------------------------------------------------------------------
__device__ float g_kr [MR * 64];     // rope staging (fp32)
__device__ float g_qr [MR * 1024];   // rope staging (fp32)

// fp16 attention operands
__device__ __half g_qh [MR * 1024];  // q * scale (fp16)
__device__ __half g_qrh[MR * 1024];  // rope(qr) * scale (fp16)
__device__ __half g_krh[MR * 64];    // rope(kr) (fp16)
__device__ __half g_kvh[MR * 2048];  // k cols 0..1023, v cols 1024..2047 (fp16)

// bf16 hi/lo split pairs (x ~= hi + lo)
__device__ __nv_bfloat16 g_xh[MR*1024],  g_xl[MR*1024];
__device__ __nv_bfloat16 g_hh[MR*1024],  g_hl[MR*1024];
__device__ __nv_bfloat16 g_ath[MR*1024], g_atl[MR*1024];
// transposed+split weights [N,K]
__device__ __nv_bfloat16 g_w1h [1024*1024], g_w1l [1024*1024];
__device__ __nv_bfloat16 g_wkrh[64*1024],   g_wkrl[64*1024];
__device__ __nv_bfloat16 g_wqrh[1024*1024], g_wqrl[1024*1024];
__device__ __nv_bfloat16 g_wkvh[2048*512],  g_wkvl[2048*512];
__device__ __nv_bfloat16 g_wqh [1024*512],  g_wql [1024*512];
__device__ __nv_bfloat16 g_woh [1024*1024], g_wol [1024*1024];

// ---------------------------------------------------------------------------
// helpers
// ---------------------------------------------------------------------------
__device__ __forceinline__ void mmah(float* c,
                                     uint32_t a0, uint32_t a1, uint32_t a2, uint32_t a3,
                                     uint32_t b0, uint32_t b1) {
    asm volatile(
        "mma.sync.aligned.m16n8k16.row.col.f32.f16.f16.f32 "
        "{%0,%1,%2,%3},{%4,%5,%6,%7},{%8,%9},{%0,%1,%2,%3};"
        : "+f"(c[0]), "+f"(c[1]), "+f"(c[2]), "+f"(c[3])
        : "r"(a0), "r"(a1), "r"(a2), "r"(a3), "r"(b0), "r"(b1));
}
__device__ __forceinline__ void mma16(float* c, const uint32_t* a,
                                      uint32_t b0, uint32_t b1) {
    asm volatile(
        "mma.sync.aligned.m16n8k16.row.col.f32.bf16.bf16.f32 "
        "{%0,%1,%2,%3},{%4,%5,%6,%7},{%8,%9},{%0,%1,%2,%3};"
        : "+f"(c[0]), "+f"(c[1]), "+f"(c[2]), "+f"(c[3])
        : "r"(a[0]), "r"(a[1]), "r"(a[2]), "r"(a[3]), "r"(b0), "r"(b1));
}
// ldmatrix x4 transposed (for V: [key][dv] -> k-major B fragments)
__device__ __forceinline__ void ldsm4t(uint32_t& r0, uint32_t& r1,
                                       uint32_t& r2, uint32_t& r3, uint32_t addr) {
    asm volatile("ldmatrix.sync.aligned.m8n8.x4.trans.shared.b16 {%0,%1,%2,%3}, [%4];"
                 : "=r"(r0), "=r"(r1), "=r"(r2), "=r"(r3) : "r"(addr));
}
// pack two fp32 -> fp16x2 (x in low half)
__device__ __forceinline__ uint32_t h2pack(float x, float y) {
    uint32_t u;
    asm("cvt.rn.f16x2.f32 %0, %1, %2;" : "=r"(u) : "f"(y), "f"(x));
    return u;
}
// Dekker bf16 split of a pair: hi = bf16x2(x low, y high), lo = residuals
__device__ __forceinline__ void split2(float x, float y, uint32_t& hi, uint32_t& lo) {
    uint32_t h, l;
    asm("cvt.rn.bf16x2.f32 %0, %1, %2;" : "=r"(h) : "f"(y), "f"(x));
    float hx = __uint_as_float(h << 16);
    float hy = __uint_as_float(h & 0xffff0000u);
    float lx = x - hx;
    float ly = y - hy;
    asm("cvt.rn.bf16x2.f32 %0, %1, %2;" : "=r"(l) : "f"(ly), "f"(lx));
    hi = h; lo = l;
}
__device__ __forceinline__ uint32_t sptr(const void* p) {
    return (uint32_t)__cvta_generic_to_shared(p);
}
__device__ __forceinline__ void cp16(uint32_t dst, const void* src) {
    asm volatile("cp.async.cg.shared.global [%0], [%1], 16;" :: "r"(dst), "l"(src));
}
__device__ __forceinline__ void cp_commit() {
    asm volatile("cp.async.commit_group;");
}
template<int N> __device__ __forceinline__ void cp_wait() {
    asm volatile("cp.async.wait_group %0;" :: "n"(N));
}

// ---------------------------------------------------------------------------
// Weight transpose + split: W[K,N] fp32 -> Wh,Wl[N,K] bf16
// ---------------------------------------------------------------------------
__global__ void wsplit_kernel(const float* __restrict__ W, int K, int N,
                              __nv_bfloat16* __restrict__ Wh,
                              __nv_bfloat16* __restrict__ Wl)
{
    __shared__ float tile[32][33];
    int n0 = blockIdx.x * 32, k0 = blockIdx.y * 32;
    int tx = threadIdx.x, ty = threadIdx.y;
#pragma unroll
    for (int i = 0; i < 32; i += 8)
        tile[ty + i][tx] = W[(size_t)(k0 + ty + i) * N + n0 + tx];
    __syncthreads();
#pragma unroll
    for (int i = 0; i < 32; i += 8) {
        int n = n0 + ty + i, k = k0 + tx;
        float v = tile[tx][ty + i];
        __nv_bfloat16 h = __float2bfloat16(v);
        float lo = v - __bfloat162float(h);
        Wh[(size_t)n * K + k] = h;
        Wl[(size_t)n * K + k] = __float2bfloat16(lo);
    }
}

__global__ void asplit_kernel(const float4* __restrict__ X,
                              uint2* __restrict__ Xh, uint2* __restrict__ Xl, int n4)
{
    int i = blockIdx.x * blockDim.x + threadIdx.x;
    if (i >= n4) return;
    float4 v = X[i];
    uint32_t h0, l0, h1, l1;
    split2(v.x, v.y, h0, l0);
    split2(v.z, v.w, h1, l1);
    Xh[i] = make_uint2(h0, h1);
    Xl[i] = make_uint2(l0, l1);
}

// ---------------------------------------------------------------------------
// Split-bf16 3-pass mma.sync GEMM, pre-split operands (R7-winning form).
// OUT: 0 = fp32 C, 1 = split bf16 (Ch/Cl), 2 = packed fp16 (H)
// ---------------------------------------------------------------------------
template<int BN, int OUT>
__global__ __launch_bounds__(256, 2)
void gemm_bf16_3x(int N, int K,
                  const __nv_bfloat16* __restrict__ Agh,
                  const __nv_bfloat16* __restrict__ Agl, int lda,
                  const __nv_bfloat16* __restrict__ Bgh,
                  const __nv_bfloat16* __restrict__ Bgl,
                  const float* __restrict__ bias, float oscale,
                  float* __restrict__ C,
                  __nv_bfloat16* __restrict__ Ch,
                  __nv_bfloat16* __restrict__ Cl,
                  __half* __restrict__ H)
{
    constexpr int BM   = 128;
    constexpr int WM   = BM / 4;
    constexpr int WN   = BN / 2;
    constexpr int MT   = WM / 16;
    constexpr int NT   = WN / 8;
    constexpr int STR  = 40;
    constexpr int ASL  = BM * STR;
    constexpr int BSL  = BN * STR;
    constexpr int STG  = 2 * ASL + 2 * BSL;
    constexpr int NAC  = (BM * 4) / 256;
    constexpr int NBC  = (BN * 4) / 256;

    extern __shared__ __nv_bfloat16 smb[];

    const int tid  = threadIdx.x;
    const int lane = tid & 31;
    const int warp = tid >> 5;
    const int g    = lane >> 2;
    const int t    = lane & 3;
    const int wm   = warp >> 1;
    const int wn   = warp & 1;
    const int bRow = blockIdx.y * BM;
    const int bCol = blockIdx.x * BN;

    float acc[MT][NT][4];
#pragma unroll
    for (int mt = 0; mt < MT; mt++)
#pragma unroll
        for (int nt = 0; nt < NT; nt++)
#pragma unroll
            for (int i = 0; i < 4; i++) acc[mt][nt][i] = 0.f;

    auto issue = [&](int k0, int s) {
        __nv_bfloat16* st = smb + s * STG;
#pragma unroll
        for (int i = 0; i < NAC; i++) {
            int idx = tid + i * 256;
            int r = idx >> 2, c = idx & 3;
            uint32_t d = sptr(st + r * STR + c * 8);
            cp16(d, Agh + (size_t)(bRow + r) * lda + k0 + c * 8);
            cp16(d + ASL * 2, Agl + (size_t)(bRow + r) * lda + k0 + c * 8);
        }
#pragma unroll
        for (int i = 0; i < NBC; i++) {
            int idx = tid + i * 256;
            int r = idx >> 2, c = idx & 3;
            uint32_t d = sptr(st + 2 * ASL + r * STR + c * 8);
            cp16(d, Bgh + (size_t)(bCol + r) * K + k0 + c * 8);
            cp16(d + BSL * 2, Bgl + (size_t)(bCol + r) * K + k0 + c * 8);
        }
        cp_commit();
    };

    const int iters = K / 32;
    issue(0, 0);

    for (int it = 0; it < iters; it++) {
        const int cur = it & 1;
        if (it + 1 < iters) { issue((it + 1) * 32, cur ^ 1); cp_wait<1>(); }
        else                { cp_wait<0>(); }
        __syncthreads();

        const __nv_bfloat16* Ah = smb + cur * STG;
        const __nv_bfloat16* Al = Ah + ASL;
        const __nv_bfloat16* Bh = Ah + 2 * ASL;
        const __nv_bfloat16* Bl = Bh + BSL;

#pragma unroll
        for (int s = 0; s < 2; s++) {
            const int kb = 16 * s + 2 * t;
            uint32_t ah[MT][4], al[MT][4];
#pragma unroll
            for (int mt = 0; mt < MT; mt++) {
                int r0 = wm * WM + mt * 16 + g;
                int r1 = r0 + 8;
                ah[mt][0] = *reinterpret_cast<const uint32_t*>(&Ah[r0 * STR + kb]);
                ah[mt][1] = *reinterpret_cast<const uint32_t*>(&Ah[r1 * STR + kb]);
                ah[mt][2] = *reinterpret_cast<const uint32_t*>(&Ah[r0 * STR + kb + 8]);
                ah[mt][3] = *reinterpret_cast<const uint32_t*>(&Ah[r1 * STR + kb + 8]);
                al[mt][0] = *reinterpret_cast<const uint32_t*>(&Al[r0 * STR + kb]);
                al[mt][1] = *reinterpret_cast<const uint32_t*>(&Al[r1 * STR + kb]);
                al[mt][2] = *reinterpret_cast<const uint32_t*>(&Al[r0 * STR + kb + 8]);
                al[mt][3] = *reinterpret_cast<const uint32_t*>(&Al[r1 * STR + kb + 8]);
            }
#pragma unroll
            for (int nt = 0; nt < NT; nt++) {
                int nb = wn * WN + nt * 8 + g;
                uint32_t bh0 = *reinterpret_cast<const uint32_t*>(&Bh[nb * STR + kb]);
                uint32_t bh1 = *reinterpret_cast<const uint32_t*>(&Bh[nb * STR + kb + 8]);
                uint32_t bl0 = *reinterpret_cast<const uint32_t*>(&Bl[nb * STR + kb]);
                uint32_t bl1 = *reinterpret_cast<const uint32_t*>(&Bl[nb * STR + kb + 8]);
#pragma unroll
                for (int mt = 0; mt < MT; mt++) {
                    mma16(acc[mt][nt], ah[mt], bh0, bh1);
                    mma16(acc[mt][nt], ah[mt], bl0, bl1);
                    mma16(acc[mt][nt], al[mt], bh0, bh1);
                }
            }
        }
        __syncthreads();
    }

#pragma unroll
    for (int mt = 0; mt < MT; mt++) {
        int r0 = bRow + wm * WM + mt * 16 + g;
#pragma unroll
        for (int nt = 0; nt < NT; nt++) {
            int col = bCol + wn * WN + nt * 8 + 2 * t;
            float bx = bias[col], by = bias[col + 1];
            float v00 = (acc[mt][nt][0] + bx) * oscale, v01 = (acc[mt][nt][1] + by) * oscale;
            float v10 = (acc[mt][nt][2] + bx) * oscale, v11 = (acc[mt][nt][3] + by) * oscale;
            if (OUT == 0) {
                float2 a = {v00, v01}, b = {v10, v11};
                *reinterpret_cast<float2*>(C + (size_t)r0 * N + col)       = a;
                *reinterpret_cast<float2*>(C + (size_t)(r0 + 8) * N + col) = b;
            } else if (OUT == 1) {
                uint32_t h0, l0, h1, l1;
                split2(v00, v01, h0, l0);
                split2(v10, v11, h1, l1);
                *reinterpret_cast<uint32_t*>(&Ch[(size_t)r0 * N + col])       = h0;
                *reinterpret_cast<uint32_t*>(&Cl[(size_t)r0 * N + col])       = l0;
                *reinterpret_cast<uint32_t*>(&Ch[(size_t)(r0 + 8) * N + col]) = h1;
                *reinterpret_cast<uint32_t*>(&Cl[(size_t)(r0 + 8) * N + col]) = l1;
            } else {
                *reinterpret_cast<uint32_t*>(&H[(size_t)r0 * N + col])       = h2pack(v00, v01);
                *reinterpret_cast<uint32_t*>(&H[(size_t)(r0 + 8) * N + col]) = h2pack(v10, v11);
            }
        }
    }
}

// ---------------------------------------------------------------------------
// RoPE: read fp32, write packed fp16 pairs.
// ---------------------------------------------------------------------------
__global__ void rope_half_kernel(const float* __restrict__ x,
                                 uint32_t* __restrict__ outp, int D)
{
    const int pairs = D / 2;
    int idx = blockIdx.x * blockDim.x + threadIdx.x;
    if (idx >= MR * pairs) return;
    int row = idx / pairs;
    int i   = idx - row * pairs;
    int t   = row & (TT - 1);

    float theta = expf(-2.0f * (float)i / (float)D * 9.2103403719761836f);
    float ang   = (float)(t + 1) * theta;
    float sn, cs;
    sincosf(ang, &sn, &cs);

    const float* p = x + (size_t)row * D + 2*i;
    float e = p[0], o = p[1];
    outp[(size_t)row * pairs + i] = h2pack(e * cs - o * sn, o * cs + e * sn);
}

// ---------------------------------------------------------------------------
// Causal flash attention, fp16 mma.sync m16n8k16, 2 CTAs/SM.
// Q/K/P pairs k-contiguous (plain 32-bit LDS); V via ldmatrix.x4.trans.
// ---------------------------------------------------------------------------
#define QSTH 136   // halfs (68 words: conflict-free frag reads)
#define KSTH 136
#define VSTH 72    // 36 words
#define PSTH 72

#define OFFH_K (128 * QSTH)                 // 17408
#define OFFH_V (OFFH_K + 2 * 64 * KSTH)     // 34816
#define OFFH_P (OFFH_V + 2 * 64 * VSTH)     // 44032
#define ATT_HALFS (OFFH_P + 128 * PSTH)     // 53248 halfs = 106496 B

__global__ __launch_bounds__(256, 2)
void attn_fp16_kernel()
{
    extern __shared__ __half smh[];
    __half* Qh = smh;
    __half* Ph = smh + OFFH_P;

    const int tid  = threadIdx.x;
    const int lane = tid & 31;
    const int warp = tid >> 5;
    const int g    = lane >> 2;
    const int t    = lane & 3;
    const int qt   = (gridDim.x - 1) - blockIdx.x;   // heavy blocks first
    const int hh   = blockIdx.y;
    const int b    = blockIdx.z;
    const int rowBase = b * TT + qt * 128;

    auto issueKV = [&](int j, int s) {
        __half* Kt = smh + OFFH_K + s * 64 * KSTH;
        __half* Vt = smh + OFFH_V + s * 64 * VSTH;
        const int kbase = b * TT + j * 64;
        // K: 64 rows x 128 d fp16 = 16 chunks of 8 halfs per row
#pragma unroll
        for (int i = 0; i < 4; i++) {
            int idx = tid + i * 256;
            int r = idx >> 4, c = idx & 15;
            uint32_t d = sptr(Kt + r * KSTH + c * 8);
            if (c < 8) cp16(d, g_kvh + (size_t)(kbase + r) * 2048 + hh * 64 + c * 8);
            else       cp16(d, g_krh + (size_t)(kbase + r) * 64 + (c - 8) * 8);
        }
        // V: 64 rows x 64 dv fp16 = 8 chunks per row
#pragma unroll
        for (int i = 0; i < 2; i++) {
            int idx = tid + i * 256;
            int r = idx >> 3, c = idx & 7;
            cp16(sptr(Vt + r * VSTH + c * 8),
                 g_kvh + (size_t)(kbase + r) * 2048 + 1024 + hh * 64 + c * 8);
        }
        cp_commit();
    };

    // Q tile (128 rows x 128 d fp16) + first K/V tile
#pragma unroll
    for (int i = 0; i < 8; i++) {
        int idx = tid + i * 256;
        int r = idx >> 4, c = idx & 15;
        uint32_t d = sptr(Qh + r * QSTH + c * 8);
        if (c < 8) cp16(d, g_qh  + (size_t)(rowBase + r) * 1024 + hh * 64 + c * 8);
        else       cp16(d, g_qrh + (size_t)(rowBase + r) * 1024 + hh * 64 + (c - 8) * 8);
    }
    issueKV(0, 0);

    // per-lane ldmatrix.trans address component for V (halfs)
    const int vrow = (lane & 7) + ((lane >> 3) & 1) * 8;
    const int vcol = (lane >> 4) * 8;
    const uint32_t vLaneByte = (uint32_t)(vrow * VSTH + vcol) * 2;

    const int rloc0 = warp * 16 + g;
    float m0 = -1e30f, m1 = -1e30f, l0 = 0.f, l1 = 0.f;
    float o[8][4];
#pragma unroll
    for (int nt = 0; nt < 8; nt++)
#pragma unroll
        for (int i = 0; i < 4; i++) o[nt][i] = 0.f;

    const int nkt = 2 * qt + 2;
    for (int j = 0; j < nkt; j++) {
        const int s = j & 1;
        if (j + 1 < nkt) { issueKV(j + 1, s ^ 1); cp_wait<1>(); }
        else             { cp_wait<0>(); }
        __syncthreads();

        const __half* Kt = smh + OFFH_K + s * 64 * KSTH;
        const uint32_t vBuf = sptr(smh + OFFH_V + s * 64 * VSTH);

        // --- S = Q @ K^T  (fp16 m16n8k16, 8 k-chunks of 16) -----------------
        float sc[8][4];
#pragma unroll
        for (int nt = 0; nt < 8; nt++)
#pragma unroll
            for (int i = 0; i < 4; i++) sc[nt][i] = 0.f;

#pragma unroll
        for (int ks = 0; ks < 8; ks++) {
            const int kb = ks * 16 + 2 * t;
            uint32_t a0 = *reinterpret_cast<const uint32_t*>(&Qh[(rloc0)     * QSTH + kb]);
            uint32_t a1 = *reinterpret_cast<const uint32_t*>(&Qh[(rloc0 + 8) * QSTH + kb]);
            uint32_t a2 = *reinterpret_cast<const uint32_t*>(&Qh[(rloc0)     * QSTH + kb + 8]);
            uint32_t a3 = *reinterpret_cast<const uint32_t*>(&Qh[(rloc0 + 8) * QSTH + kb + 8]);
#pragma unroll
            for (int nt = 0; nt < 8; nt++) {
                uint32_t b0 = *reinterpret_cast<const uint32_t*>(&Kt[(nt * 8 + g) * KSTH + kb]);
                uint32_t b1 = *reinterpret_cast<const uint32_t*>(&Kt[(nt * 8 + g) * KSTH + kb + 8]);
                mmah(sc[nt], a0, a1, a2, a3, b0, b1);
            }
        }

        // --- causal mask -----------------------------------------------------
        if (j >= 2 * qt) {
            int rg0 = qt * 128 + rloc0;
            int k0 = j * 64;
#pragma unroll
            for (int nt = 0; nt < 8; nt++) {
                int cg = k0 + nt * 8 + 2 * t;
                if (cg     > rg0)     sc[nt][0] = -1e30f;
                if (cg + 1 > rg0)     sc[nt][1] = -1e30f;
                if (cg     > rg0 + 8) sc[nt][2] = -1e30f;
                if (cg + 1 > rg0 + 8) sc[nt][3] = -1e30f;
            }
        }

        // --- online softmax (registers + 4-lane shfl) ------------------------
        float mx0 = -1e30f, mx1 = -1e30f;
#pragma unroll
        for (int nt = 0; nt < 8; nt++) {
            mx0 = fmaxf(mx0, fmaxf(sc[nt][0], sc[nt][1]));
            mx1 = fmaxf(mx1, fmaxf(sc[nt][2], sc[nt][3]));
        }
        mx0 = fmaxf(mx0, __shfl_xor_sync(0xffffffffu, mx0, 1));
        mx0 = fmaxf(mx0, __shfl_xor_sync(0xffffffffu, mx0, 2));
        mx1 = fmaxf(mx1, __shfl_xor_sync(0xffffffffu, mx1, 1));
        mx1 = fmaxf(mx1, __shfl_xor_sync(0xffffffffu, mx1, 2));

        float mn0 = fmaxf(m0, mx0), mn1 = fmaxf(m1, mx1);
        float al0 = __expf(m0 - mn0), al1 = __expf(m1 - mn1);
        m0 = mn0; m1 = mn1;

        float sum0 = 0.f, sum1 = 0.f;
#pragma unroll
        for (int nt = 0; nt < 8; nt++) {
            float p0 = __expf(sc[nt][0] - mn0);
            float p1 = __expf(sc[nt][1] - mn0);
            float p2 = __expf(sc[nt][2] - mn1);
            float p3 = __expf(sc[nt][3] - mn1);
            sum0 += p0 + p1; sum1 += p2 + p3;
            *reinterpret_cast<uint32_t*>(&Ph[(rloc0)     * PSTH + nt * 8 + 2 * t]) = h2pack(p0, p1);
            *reinterpret_cast<uint32_t*>(&Ph[(rloc0 + 8) * PSTH + nt * 8 + 2 * t]) = h2pack(p2, p3);
        }
        sum0 += __shfl_xor_sync(0xffffffffu, sum0, 1);
        sum0 += __shfl_xor_sync(0xffffffffu, sum0, 2);
        sum1 += __shfl_xor_sync(0xffffffffu, sum1, 1);
        sum1 += __shfl_xor_sync(0xffffffffu, sum1, 2);
        l0 = l0 * al0 + sum0;
        l1 = l1 * al1 + sum1;

#pragma unroll
        for (int nt = 0; nt < 8; nt++) {
            o[nt][0] *= al0; o[nt][1] *= al0;
            o[nt][2] *= al1; o[nt][3] *= al1;
        }
        __syncwarp();   // Ps exchange is intra-warp only

        // --- O += P @ V  (fp16 m16n8k16; V via ldmatrix.trans) ---------------
#pragma unroll
        for (int ks = 0; ks < 4; ks++) {
            const int kb = ks * 16 + 2 * t;
            uint32_t a0 = *reinterpret_cast<const uint32_t*>(&Ph[(rloc0)     * PSTH + kb]);
            uint32_t a1 = *reinterpret_cast<const uint32_t*>(&Ph[(rloc0 + 8) * PSTH + kb]);
            uint32_t a2 = *reinterpret_cast<const uint32_t*>(&Ph[(rloc0)     * PSTH + kb + 8]);
            uint32_t a3 = *reinterpret_cast<const uint32_t*>(&Ph[(rloc0 + 8) * PSTH + kb + 8]);
#pragma unroll
            for (int ntp = 0; ntp < 4; ntp++) {
                uint32_t b0, b1, b2, b3;
                ldsm4t(b0, b1, b2, b3,
                       vBuf + vLaneByte + (uint32_t)(ks * 16 * VSTH + ntp * 16) * 2);
                mmah(o[2*ntp],     a0, a1, a2, a3, b0, b1);
                mmah(o[2*ntp + 1], a0, a1, a2, a3, b2, b3);
            }
        }
        __syncthreads();   // done with buf s before next iter overwrites it
    }

    // finalize + store split bf16 (att feeds only the wo GEMM)
    float inv0 = 1.0f / l0, inv1 = 1.0f / l1;
    int rg = rowBase + rloc0;
#pragma unroll
    for (int nt = 0; nt < 8; nt++) {
        int col = hh * 64 + nt * 8 + 2 * t;
        uint32_t h0, l0u, h1, l1u;
        split2(o[nt][0] * inv0, o[nt][1] * inv0, h0, l0u);
        split2(o[nt][2] * inv1, o[nt][3] * inv1, h1, l1u);
        *reinterpret_cast<uint32_t*>(&g_ath[(size_t)rg       * 1024 + col]) = h0;
        *reinterpret_cast<uint32_t*>(&g_atl[(size_t)rg       * 1024 + col]) = l0u;
        *reinterpret_cast<uint32_t*>(&g_ath[(size_t)(rg + 8) * 1024 + col]) = h1;
        *reinterpret_cast<uint32_t*>(&g_atl[(size_t)(rg + 8) * 1024 + col]) = l1u;
    }
}

// ---------------------------------------------------------------------------
// Launch
// ---------------------------------------------------------------------------
extern "C" void kernel_launch(void* const* d_in, const int* in_sizes, int n_in,
                              void* d_out, int out_size)
{
    (void)in_sizes; (void)n_in; (void)out_size;
    const float* x   = (const float*)d_in[0];
    const float* w1  = (const float*)d_in[1];
    const float* b1  = (const float*)d_in[2];
    const float* wkr = (const float*)d_in[3];
    const float* bkr = (const float*)d_in[4];
    const float* wqr = (const float*)d_in[5];
    const float* bqr = (const float*)d_in[6];
    const float* wkv = (const float*)d_in[7];
    const float* bkv = (const float*)d_in[8];
    const float* wq  = (const float*)d_in[9];
    const float* bq  = (const float*)d_in[10];
    const float* wo  = (const float*)d_in[11];
    const float* bo  = (const float*)d_in[12];
    float* out = (float*)d_out;
    const float scale = 0.08838834764831845f;   // 128^-0.5

    float *kr_, *qr_;
    __half *qh_, *qrh_, *krh_, *kvh_;
    __nv_bfloat16 *xh_, *xl_, *hh_, *hl_, *ath_, *atl_;
    __nv_bfloat16 *w1h_, *w1l_, *wkrh_, *wkrl_, *wqrh_, *wqrl_;
    __nv_bfloat16 *wkvh_, *wkvl_, *wqh_, *wql_, *woh_, *wol_;
    cudaGetSymbolAddress((void**)&kr_,  g_kr);
    cudaGetSymbolAddress((void**)&qr_,  g_qr);
    cudaGetSymbolAddress((void**)&qh_,  g_qh);
    cudaGetSymbolAddress((void**)&qrh_, g_qrh);
    cudaGetSymbolAddress((void**)&krh_, g_krh);
    cudaGetSymbolAddress((void**)&kvh_, g_kvh);
    cudaGetSymbolAddress((void**)&xh_,  g_xh);  cudaGetSymbolAddress((void**)&xl_,  g_xl);
    cudaGetSymbolAddress((void**)&hh_,  g_hh);  cudaGetSymbolAddress((void**)&hl_,  g_hl);
    cudaGetSymbolAddress((void**)&ath_, g_ath); cudaGetSymbolAddress((void**)&atl_, g_atl);
    cudaGetSymbolAddress((void**)&w1h_, g_w1h);  cudaGetSymbolAddress((void**)&w1l_, g_w1l);
    cudaGetSymbolAddress((void**)&wkrh_, g_wkrh); cudaGetSymbolAddress((void**)&wkrl_, g_wkrl);
    cudaGetSymbolAddress((void**)&wqrh_, g_wqrh); cudaGetSymbolAddress((void**)&wqrl_, g_wqrl);
    cudaGetSymbolAddress((void**)&wkvh_, g_wkvh); cudaGetSymbolAddress((void**)&wkvl_, g_wkvl);
    cudaGetSymbolAddress((void**)&wqh_, g_wqh);   cudaGetSymbolAddress((void**)&wql_, g_wql);
    cudaGetSymbolAddress((void**)&woh_, g_woh);   cudaGetSymbolAddress((void**)&wol_, g_wol);

    const int SMG128 = 2 * (2 * 128 * 40 + 2 * 128 * 40) * 2;   // 81920
    const int SMG64  = 2 * (2 * 128 * 40 + 2 * 64  * 40) * 2;   // 61440
    const int SMAT   = ATT_HALFS * 2;                            // 106496
    cudaFuncSetAttribute(gemm_bf16_3x<128, 0>, cudaFuncAttributeMaxDynamicSharedMemorySize, SMG128);
    cudaFuncSetAttribute(gemm_bf16_3x<128, 1>, cudaFuncAttributeMaxDynamicSharedMemorySize, SMG128);
    cudaFuncSetAttribute(gemm_bf16_3x<128, 2>, cudaFuncAttributeMaxDynamicSharedMemorySize, SMG128);
    cudaFuncSetAttribute(gemm_bf16_3x<64,  0>, cudaFuncAttributeMaxDynamicSharedMemorySize, SMG64);
    cudaFuncSetAttribute(attn_fp16_kernel, cudaFuncAttributeMaxDynamicSharedMemorySize, SMAT);

    dim3 wsb(32, 8);
    wsplit_kernel<<<dim3(1024/32, 1024/32), wsb>>>(w1,  1024, 1024, w1h_,  w1l_);
    wsplit_kernel<<<dim3(64/32,   1024/32), wsb>>>(wkr, 1024, 64,   wkrh_, wkrl_);
    wsplit_kernel<<<dim3(1024/32, 1024/32), wsb>>>(wqr, 1024, 1024, wqrh_, wqrl_);
    wsplit_kernel<<<dim3(2048/32, 512/32),  wsb>>>(wkv, 512,  2048, wkvh_, wkvl_);
    wsplit_kernel<<<dim3(1024/32, 512/32),  wsb>>>(wq,  512,  1024, wqh_,  wql_);
    wsplit_kernel<<<dim3(1024/32, 1024/32), wsb>>>(wo,  1024, 1024, woh_,  wol_);
    asplit_kernel<<<(MR * 1024 / 4 + 255) / 256, 256>>>(
        (const float4*)x, (uint2*)xh_, (uint2*)xl_, MR * 1024 / 4);

    // 1) h = x @ w1 + b1  -> split bf16 h
    gemm_bf16_3x<128, 1><<<dim3(8, 32), 256, SMG128>>>(
        1024, 1024, xh_, xl_, 1024, w1h_, w1l_, b1, 1.f, nullptr, hh_, hl_, nullptr);

    // 2) kr = rope(h @ wkr + bkr)  -> fp16
    gemm_bf16_3x<64, 0><<<dim3(1, 32), 256, SMG64>>>(
        64, 1024, hh_, hl_, 1024, wkrh_, wkrl_, bkr, 1.f, kr_, nullptr, nullptr, nullptr);
    rope_half_kernel<<<(MR * 32 + 255) / 256, 256>>>(kr_, (uint32_t*)krh_, 64);

    // 3) qr = rope((h @ wqr + bqr) * scale)  -> fp16
    gemm_bf16_3x<128, 0><<<dim3(8, 32), 256, SMG128>>>(
        1024, 1024, hh_, hl_, 1024, wqrh_, wqrl_, bqr, scale, qr_, nullptr, nullptr, nullptr);
    rope_half_kernel<<<(MR * 512 + 255) / 256, 256>>>(qr_, (uint32_t*)qrh_, 1024);

    // 4) kv = cKV @ wkv + bkv  -> fp16
    gemm_bf16_3x<128, 2><<<dim3(16, 32), 256, SMG128>>>(
        2048, 512, hh_, hl_, 1024, wkvh_, wkvl_, bkv, 1.f, nullptr, nullptr, nullptr, kvh_);

    // 5) q = (cq @ wq + bq) * scale  -> fp16
    gemm_bf16_3x<128, 2><<<dim3(8, 32), 256, SMG128>>>(
        1024, 512, hh_ + 512, hl_ + 512, 1024, wqh_, wql_, bq, scale, nullptr, nullptr, nullptr, qh_);

    // 6) attention (fp16 mma) -> split bf16 att
    attn_fp16_kernel<<<dim3(16, NH, BB), 256, SMAT>>>();

    // 7) out = att @ wo + bo
    gemm_bf16_3x<128, 0><<<dim3(8, 32), 256, SMG128>>>(
        1024, 1024, ath_, atl_, 1024, woh_, wol_, bo, 1.f, out, nullptr, nullptr, nullptr);
}

// round 10
// speedup vs baseline: 1.3816x; 1.1273x over previous
#include <cuda_runtime.h>
#include <cuda_bf16.h>
#include <cuda_fp16.h>
#include <math.h>
#include <stdint.h>

// Problem constants
#define BB   2
#define TT   2048
#define CC   1024
#define NH   16
#define LAT  512
#define DHR  64
#define MR   (BB*TT)        // 4096 rows

// ---------------------------------------------------------------------------
// Scratch (static device globals)
// ---------------------------------------------------------------------------
// fp16 attention operands
__device__ __half g_qh [MR * 1024];  // q * scale (fp16)
__device__ __half g_qrh[MR * 1024];  // rope(qr) * scale (fp16)
__device__ __half g_krh[MR * 64];    // rope(kr) (fp16)
__device__ __half g_kvh[MR * 2048];  // k cols 0..1023, v cols 1024..2047 (fp16)

// bf16 hi/lo split pairs (x ~= hi + lo)
__device__ __nv_bfloat16 g_xh[MR*1024],  g_xl[MR*1024];
__device__ __nv_bfloat16 g_hh[MR*1024],  g_hl[MR*1024];
__device__ __nv_bfloat16 g_ath[MR*1024], g_atl[MR*1024];
// transposed+split weights [N,K]
__device__ __nv_bfloat16 g_w1h [1024*1024], g_w1l [1024*1024];
__device__ __nv_bfloat16 g_wkrh[64*1024],   g_wkrl[64*1024];
__device__ __nv_bfloat16 g_wqrh[1024*1024], g_wqrl[1024*1024];
__device__ __nv_bfloat16 g_wkvh[2048*512],  g_wkvl[2048*512];
__device__ __nv_bfloat16 g_wqh [1024*512],  g_wql [1024*512];
__device__ __nv_bfloat16 g_woh [1024*1024], g_wol [1024*1024];

// ---------------------------------------------------------------------------
// helpers
// ---------------------------------------------------------------------------
__device__ __forceinline__ void mmah(float* c,
                                     uint32_t a0, uint32_t a1, uint32_t a2, uint32_t a3,
                                     uint32_t b0, uint32_t b1) {
    asm volatile(
        "mma.sync.aligned.m16n8k16.row.col.f32.f16.f16.f32 "
        "{%0,%1,%2,%3},{%4,%5,%6,%7},{%8,%9},{%0,%1,%2,%3};"
        : "+f"(c[0]), "+f"(c[1]), "+f"(c[2]), "+f"(c[3])
        : "r"(a0), "r"(a1), "r"(a2), "r"(a3), "r"(b0), "r"(b1));
}
__device__ __forceinline__ void mma16(float* c, const uint32_t* a,
                                      uint32_t b0, uint32_t b1) {
    asm volatile(
        "mma.sync.aligned.m16n8k16.row.col.f32.bf16.bf16.f32 "
        "{%0,%1,%2,%3},{%4,%5,%6,%7},{%8,%9},{%0,%1,%2,%3};"
        : "+f"(c[0]), "+f"(c[1]), "+f"(c[2]), "+f"(c[3])
        : "r"(a[0]), "r"(a[1]), "r"(a[2]), "r"(a[3]), "r"(b0), "r"(b1));
}
__device__ __forceinline__ void ldsm4t(uint32_t& r0, uint32_t& r1,
                                       uint32_t& r2, uint32_t& r3, uint32_t addr) {
    asm volatile("ldmatrix.sync.aligned.m8n8.x4.trans.shared.b16 {%0,%1,%2,%3}, [%4];"
                 : "=r"(r0), "=r"(r1), "=r"(r2), "=r"(r3) : "r"(addr));
}
__device__ __forceinline__ uint32_t h2pack(float x, float y) {
    uint32_t u;
    asm("cvt.rn.f16x2.f32 %0, %1, %2;" : "=r"(u) : "f"(y), "f"(x));
    return u;
}
__device__ __forceinline__ void split2(float x, float y, uint32_t& hi, uint32_t& lo) {
    uint32_t h, l;
    asm("cvt.rn.bf16x2.f32 %0, %1, %2;" : "=r"(h) : "f"(y), "f"(x));
    float hx = __uint_as_float(h << 16);
    float hy = __uint_as_float(h & 0xffff0000u);
    float lx = x - hx;
    float ly = y - hy;
    asm("cvt.rn.bf16x2.f32 %0, %1, %2;" : "=r"(l) : "f"(ly), "f"(lx));
    hi = h; lo = l;
}
__device__ __forceinline__ uint32_t sptr(const void* p) {
    return (uint32_t)__cvta_generic_to_shared(p);
}
__device__ __forceinline__ void cp16(uint32_t dst, const void* src) {
    asm volatile("cp.async.cg.shared.global [%0], [%1], 16;" :: "r"(dst), "l"(src));
}
__device__ __forceinline__ void cp_commit() {
    asm volatile("cp.async.commit_group;");
}
template<int N> __device__ __forceinline__ void cp_wait() {
    asm volatile("cp.async.wait_group %0;" :: "n"(N));
}

// ---------------------------------------------------------------------------
// Weight transpose + split: W[K,N] fp32 -> Wh,Wl[N,K] bf16
// ---------------------------------------------------------------------------
__global__ void wsplit_kernel(const float* __restrict__ W, int K, int N,
                              __nv_bfloat16* __restrict__ Wh,
                              __nv_bfloat16* __restrict__ Wl)
{
    __shared__ float tile[32][33];
    int n0 = blockIdx.x * 32, k0 = blockIdx.y * 32;
    int tx = threadIdx.x, ty = threadIdx.y;
#pragma unroll
    for (int i = 0; i < 32; i += 8)
        tile[ty + i][tx] = W[(size_t)(k0 + ty + i) * N + n0 + tx];
    __syncthreads();
#pragma unroll
    for (int i = 0; i < 32; i += 8) {
        int n = n0 + ty + i, k = k0 + tx;
        float v = tile[tx][ty + i];
        __nv_bfloat16 h = __float2bfloat16(v);
        float lo = v - __bfloat162float(h);
        Wh[(size_t)n * K + k] = h;
        Wl[(size_t)n * K + k] = __float2bfloat16(lo);
    }
}

__global__ void asplit_kernel(const float4* __restrict__ X,
                              uint2* __restrict__ Xh, uint2* __restrict__ Xl, int n4)
{
    int i = blockIdx.x * blockDim.x + threadIdx.x;
    if (i >= n4) return;
    float4 v = X[i];
    uint32_t h0, l0, h1, l1;
    split2(v.x, v.y, h0, l0);
    split2(v.z, v.w, h1, l1);
    Xh[i] = make_uint2(h0, h1);
    Xl[i] = make_uint2(l0, l1);
}

// ---------------------------------------------------------------------------
// Split-bf16 3-pass mma.sync GEMM, pre-split operands.
// OUT: 0 = fp32 C, 1 = split bf16 (Ch/Cl), 2 = packed fp16 (H),
//      3 = packed fp16 with fused RoPE (rotary dim = RD)
// ---------------------------------------------------------------------------
template<int BN, int OUT, int RD>
__global__ __launch_bounds__(256, 2)
void gemm_bf16_3x(int N, int K,
                  const __nv_bfloat16* __restrict__ Agh,
                  const __nv_bfloat16* __restrict__ Agl, int lda,
                  const __nv_bfloat16* __restrict__ Bgh,
                  const __nv_bfloat16* __restrict__ Bgl,
                  const float* __restrict__ bias, float oscale,
                  float* __restrict__ C,
                  __nv_bfloat16* __restrict__ Ch,
                  __nv_bfloat16* __restrict__ Cl,
                  __half* __restrict__ H)
{
    constexpr int BM   = 128;
    constexpr int WM   = BM / 4;
    constexpr int WN   = BN / 2;
    constexpr int MT   = WM / 16;
    constexpr int NT   = WN / 8;
    constexpr int STR  = 40;
    constexpr int ASL  = BM * STR;
    constexpr int BSL  = BN * STR;
    constexpr int STG  = 2 * ASL + 2 * BSL;
    constexpr int NAC  = (BM * 4) / 256;
    constexpr int NBC  = (BN * 4) / 256;

    extern __shared__ __nv_bfloat16 smb[];

    const int tid  = threadIdx.x;
    const int lane = tid & 31;
    const int warp = tid >> 5;
    const int g    = lane >> 2;
    const int t    = lane & 3;
    const int wm   = warp >> 1;
    const int wn   = warp & 1;
    const int bRow = blockIdx.y * BM;
    const int bCol = blockIdx.x * BN;

    float acc[MT][NT][4];
#pragma unroll
    for (int mt = 0; mt < MT; mt++)
#pragma unroll
        for (int nt = 0; nt < NT; nt++)
#pragma unroll
            for (int i = 0; i < 4; i++) acc[mt][nt][i] = 0.f;

    auto issue = [&](int k0, int s) {
        __nv_bfloat16* st = smb + s * STG;
#pragma unroll
        for (int i = 0; i < NAC; i++) {
            int idx = tid + i * 256;
            int r = idx >> 2, c = idx & 3;
            uint32_t d = sptr(st + r * STR + c * 8);
            cp16(d, Agh + (size_t)(bRow + r) * lda + k0 + c * 8);
            cp16(d + ASL * 2, Agl + (size_t)(bRow + r) * lda + k0 + c * 8);
        }
#pragma unroll
        for (int i = 0; i < NBC; i++) {
            int idx = tid + i * 256;
            int r = idx >> 2, c = idx & 3;
            uint32_t d = sptr(st + 2 * ASL + r * STR + c * 8);
            cp16(d, Bgh + (size_t)(bCol + r) * K + k0 + c * 8);
            cp16(d + BSL * 2, Bgl + (size_t)(bCol + r) * K + k0 + c * 8);
        }
        cp_commit();
    };

    const int iters = K / 32;
    issue(0, 0);

    for (int it = 0; it < iters; it++) {
        const int cur = it & 1;
        if (it + 1 < iters) { issue((it + 1) * 32, cur ^ 1); cp_wait<1>(); }
        else                { cp_wait<0>(); }
        __syncthreads();

        const __nv_bfloat16* Ah = smb + cur * STG;
        const __nv_bfloat16* Al = Ah + ASL;
        const __nv_bfloat16* Bh = Ah + 2 * ASL;
        const __nv_bfloat16* Bl = Bh + BSL;

#pragma unroll
        for (int s = 0; s < 2; s++) {
            const int kb = 16 * s + 2 * t;
            uint32_t ah[MT][4], al[MT][4];
#pragma unroll
            for (int mt = 0; mt < MT; mt++) {
                int r0 = wm * WM + mt * 16 + g;
                int r1 = r0 + 8;
                ah[mt][0] = *reinterpret_cast<const uint32_t*>(&Ah[r0 * STR + kb]);
                ah[mt][1] = *reinterpret_cast<const uint32_t*>(&Ah[r1 * STR + kb]);
                ah[mt][2] = *reinterpret_cast<const uint32_t*>(&Ah[r0 * STR + kb + 8]);
                ah[mt][3] = *reinterpret_cast<const uint32_t*>(&Ah[r1 * STR + kb + 8]);
                al[mt][0] = *reinterpret_cast<const uint32_t*>(&Al[r0 * STR + kb]);
                al[mt][1] = *reinterpret_cast<const uint32_t*>(&Al[r1 * STR + kb]);
                al[mt][2] = *reinterpret_cast<const uint32_t*>(&Al[r0 * STR + kb + 8]);
                al[mt][3] = *reinterpret_cast<const uint32_t*>(&Al[r1 * STR + kb + 8]);
            }
#pragma unroll
            for (int nt = 0; nt < NT; nt++) {
                int nb = wn * WN + nt * 8 + g;
                uint32_t bh0 = *reinterpret_cast<const uint32_t*>(&Bh[nb * STR + kb]);
                uint32_t bh1 = *reinterpret_cast<const uint32_t*>(&Bh[nb * STR + kb + 8]);
                uint32_t bl0 = *reinterpret_cast<const uint32_t*>(&Bl[nb * STR + kb]);
                uint32_t bl1 = *reinterpret_cast<const uint32_t*>(&Bl[nb * STR + kb + 8]);
#pragma unroll
                for (int mt = 0; mt < MT; mt++) {
                    mma16(acc[mt][nt], ah[mt], bh0, bh1);
                    mma16(acc[mt][nt], ah[mt], bl0, bl1);
                    mma16(acc[mt][nt], al[mt], bh0, bh1);
                }
            }
        }
        __syncthreads();
    }

#pragma unroll
    for (int mt = 0; mt < MT; mt++) {
        int r0 = bRow + wm * WM + mt * 16 + g;
#pragma unroll
        for (int nt = 0; nt < NT; nt++) {
            int col = bCol + wn * WN + nt * 8 + 2 * t;
            float bx = bias[col], by = bias[col + 1];
            float v00 = (acc[mt][nt][0] + bx) * oscale, v01 = (acc[mt][nt][1] + by) * oscale;
            float v10 = (acc[mt][nt][2] + bx) * oscale, v11 = (acc[mt][nt][3] + by) * oscale;
            if (OUT == 0) {
                float2 a = {v00, v01}, b = {v10, v11};
                *reinterpret_cast<float2*>(C + (size_t)r0 * N + col)       = a;
                *reinterpret_cast<float2*>(C + (size_t)(r0 + 8) * N + col) = b;
            } else if (OUT == 1) {
                uint32_t h0, l0, h1, l1;
                split2(v00, v01, h0, l0);
                split2(v10, v11, h1, l1);
                *reinterpret_cast<uint32_t*>(&Ch[(size_t)r0 * N + col])       = h0;
                *reinterpret_cast<uint32_t*>(&Cl[(size_t)r0 * N + col])       = l0;
                *reinterpret_cast<uint32_t*>(&Ch[(size_t)(r0 + 8) * N + col]) = h1;
                *reinterpret_cast<uint32_t*>(&Cl[(size_t)(r0 + 8) * N + col]) = l1;
            } else if (OUT == 2) {
                *reinterpret_cast<uint32_t*>(&H[(size_t)r0 * N + col])       = h2pack(v00, v01);
                *reinterpret_cast<uint32_t*>(&H[(size_t)(r0 + 8) * N + col]) = h2pack(v10, v11);
            } else {
                // fused RoPE (rotary dim RD); (col, col+1) is a rope pair
                float th = expf(-2.0f * (float)(col >> 1) / (float)RD * 9.2103403719761836f);
                int tt0 = r0 & (TT - 1);
                float sn0, cs0, sn1, cs1;
                sincosf((float)(tt0 + 1) * th, &sn0, &cs0);
                sincosf((float)(tt0 + 9) * th, &sn1, &cs1);
                float e0 = v00 * cs0 - v01 * sn0;
                float o0 = v01 * cs0 + v00 * sn0;
                float e1 = v10 * cs1 - v11 * sn1;
                float o1 = v11 * cs1 + v10 * sn1;
                *reinterpret_cast<uint32_t*>(&H[(size_t)r0 * N + col])       = h2pack(e0, o0);
                *reinterpret_cast<uint32_t*>(&H[(size_t)(r0 + 8) * N + col]) = h2pack(e1, o1);
            }
        }
    }
}

// ---------------------------------------------------------------------------
// Causal flash attention, fp16 mma.sync m16n8k16, 2 CTAs/SM. (R9 form)
// ---------------------------------------------------------------------------
#define QSTH 136
#define KSTH 136
#define VSTH 72
#define PSTH 72

#define OFFH_K (128 * QSTH)
#define OFFH_V (OFFH_K + 2 * 64 * KSTH)
#define OFFH_P (OFFH_V + 2 * 64 * VSTH)
#define ATT_HALFS (OFFH_P + 128 * PSTH)     // 53248 halfs = 106496 B

__global__ __launch_bounds__(256, 2)
void attn_fp16_kernel()
{
    extern __shared__ __half smh[];
    __half* Qh = smh;
    __half* Ph = smh + OFFH_P;

    const int tid  = threadIdx.x;
    const int lane = tid & 31;
    const int warp = tid >> 5;
    const int g    = lane >> 2;
    const int t    = lane & 3;
    const int qt   = (gridDim.x - 1) - blockIdx.x;
    const int hh   = blockIdx.y;
    const int b    = blockIdx.z;
    const int rowBase = b * TT + qt * 128;

    auto issueKV = [&](int j, int s) {
        __half* Kt = smh + OFFH_K + s * 64 * KSTH;
        __half* Vt = smh + OFFH_V + s * 64 * VSTH;
        const int kbase = b * TT + j * 64;
#pragma unroll
        for (int i = 0; i < 4; i++) {
            int idx = tid + i * 256;
            int r = idx >> 4, c = idx & 15;
            uint32_t d = sptr(Kt + r * KSTH + c * 8);
            if (c < 8) cp16(d, g_kvh + (size_t)(kbase + r) * 2048 + hh * 64 + c * 8);
            else       cp16(d, g_krh + (size_t)(kbase + r) * 64 + (c - 8) * 8);
        }
#pragma unroll
        for (int i = 0; i < 2; i++) {
            int idx = tid + i * 256;
            int r = idx >> 3, c = idx & 7;
            cp16(sptr(Vt + r * VSTH + c * 8),
                 g_kvh + (size_t)(kbase + r) * 2048 + 1024 + hh * 64 + c * 8);
        }
        cp_commit();
    };

#pragma unroll
    for (int i = 0; i < 8; i++) {
        int idx = tid + i * 256;
        int r = idx >> 4, c = idx & 15;
        uint32_t d = sptr(Qh + r * QSTH + c * 8);
        if (c < 8) cp16(d, g_qh  + (size_t)(rowBase + r) * 1024 + hh * 64 + c * 8);
        else       cp16(d, g_qrh + (size_t)(rowBase + r) * 1024 + hh * 64 + (c - 8) * 8);
    }
    issueKV(0, 0);

    const int vrow = (lane & 7) + ((lane >> 3) & 1) * 8;
    const int vcol = (lane >> 4) * 8;
    const uint32_t vLaneByte = (uint32_t)(vrow * VSTH + vcol) * 2;

    const int rloc0 = warp * 16 + g;
    float m0 = -1e30f, m1 = -1e30f, l0 = 0.f, l1 = 0.f;
    float o[8][4];
#pragma unroll
    for (int nt = 0; nt < 8; nt++)
#pragma unroll
        for (int i = 0; i < 4; i++) o[nt][i] = 0.f;

    const int nkt = 2 * qt + 2;
    for (int j = 0; j < nkt; j++) {
        const int s = j & 1;
        if (j + 1 < nkt) { issueKV(j + 1, s ^ 1); cp_wait<1>(); }
        else             { cp_wait<0>(); }
        __syncthreads();

        const __half* Kt = smh + OFFH_K + s * 64 * KSTH;
        const uint32_t vBuf = sptr(smh + OFFH_V + s * 64 * VSTH);

        float sc[8][4];
#pragma unroll
        for (int nt = 0; nt < 8; nt++)
#pragma unroll
            for (int i = 0; i < 4; i++) sc[nt][i] = 0.f;

#pragma unroll
        for (int ks = 0; ks < 8; ks++) {
            const int kb = ks * 16 + 2 * t;
            uint32_t a0 = *reinterpret_cast<const uint32_t*>(&Qh[(rloc0)     * QSTH + kb]);
            uint32_t a1 = *reinterpret_cast<const uint32_t*>(&Qh[(rloc0 + 8) * QSTH + kb]);
            uint32_t a2 = *reinterpret_cast<const uint32_t*>(&Qh[(rloc0)     * QSTH + kb + 8]);
            uint32_t a3 = *reinterpret_cast<const uint32_t*>(&Qh[(rloc0 + 8) * QSTH + kb + 8]);
#pragma unroll
            for (int nt = 0; nt < 8; nt++) {
                uint32_t b0 = *reinterpret_cast<const uint32_t*>(&Kt[(nt * 8 + g) * KSTH + kb]);
                uint32_t b1 = *reinterpret_cast<const uint32_t*>(&Kt[(nt * 8 + g) * KSTH + kb + 8]);
                mmah(sc[nt], a0, a1, a2, a3, b0, b1);
            }
        }

        if (j >= 2 * qt) {
            int rg0 = qt * 128 + rloc0;
            int k0 = j * 64;
#pragma unroll
            for (int nt = 0; nt < 8; nt++) {
                int cg = k0 + nt * 8 + 2 * t;
                if (cg     > rg0)     sc[nt][0] = -1e30f;
                if (cg + 1 > rg0)     sc[nt][1] = -1e30f;
                if (cg     > rg0 + 8) sc[nt][2] = -1e30f;
                if (cg + 1 > rg0 + 8) sc[nt][3] = -1e30f;
            }
        }

        float mx0 = -1e30f, mx1 = -1e30f;
#pragma unroll
        for (int nt = 0; nt < 8; nt++) {
            mx0 = fmaxf(mx0, fmaxf(sc[nt][0], sc[nt][1]));
            mx1 = fmaxf(mx1, fmaxf(sc[nt][2], sc[nt][3]));
        }
        mx0 = fmaxf(mx0, __shfl_xor_sync(0xffffffffu, mx0, 1));
        mx0 = fmaxf(mx0, __shfl_xor_sync(0xffffffffu, mx0, 2));
        mx1 = fmaxf(mx1, __shfl_xor_sync(0xffffffffu, mx1, 1));
        mx1 = fmaxf(mx1, __shfl_xor_sync(0xffffffffu, mx1, 2));

        float mn0 = fmaxf(m0, mx0), mn1 = fmaxf(m1, mx1);
        float al0 = __expf(m0 - mn0), al1 = __expf(m1 - mn1);
        m0 = mn0; m1 = mn1;

        float sum0 = 0.f, sum1 = 0.f;
#pragma unroll
        for (int nt = 0; nt < 8; nt++) {
            float p0 = __expf(sc[nt][0] - mn0);
            float p1 = __expf(sc[nt][1] - mn0);
            float p2 = __expf(sc[nt][2] - mn1);
            float p3 = __expf(sc[nt][3] - mn1);
            sum0 += p0 + p1; sum1 += p2 + p3;
            *reinterpret_cast<uint32_t*>(&Ph[(rloc0)     * PSTH + nt * 8 + 2 * t]) = h2pack(p0, p1);
            *reinterpret_cast<uint32_t*>(&Ph[(rloc0 + 8) * PSTH + nt * 8 + 2 * t]) = h2pack(p2, p3);
        }
        sum0 += __shfl_xor_sync(0xffffffffu, sum0, 1);
        sum0 += __shfl_xor_sync(0xffffffffu, sum0, 2);
        sum1 += __shfl_xor_sync(0xffffffffu, sum1, 1);
        sum1 += __shfl_xor_sync(0xffffffffu, sum1, 2);
        l0 = l0 * al0 + sum0;
        l1 = l1 * al1 + sum1;

#pragma unroll
        for (int nt = 0; nt < 8; nt++) {
            o[nt][0] *= al0; o[nt][1] *= al0;
            o[nt][2] *= al1; o[nt][3] *= al1;
        }
        __syncwarp();

#pragma unroll
        for (int ks = 0; ks < 4; ks++) {
            const int kb = ks * 16 + 2 * t;
            uint32_t a0 = *reinterpret_cast<const uint32_t*>(&Ph[(rloc0)     * PSTH + kb]);
            uint32_t a1 = *reinterpret_cast<const uint32_t*>(&Ph[(rloc0 + 8) * PSTH + kb]);
            uint32_t a2 = *reinterpret_cast<const uint32_t*>(&Ph[(rloc0)     * PSTH + kb + 8]);
            uint32_t a3 = *reinterpret_cast<const uint32_t*>(&Ph[(rloc0 + 8) * PSTH + kb + 8]);
#pragma unroll
            for (int ntp = 0; ntp < 4; ntp++) {
                uint32_t b0, b1, b2, b3;
                ldsm4t(b0, b1, b2, b3,
                       vBuf + vLaneByte + (uint32_t)(ks * 16 * VSTH + ntp * 16) * 2);
                mmah(o[2*ntp],     a0, a1, a2, a3, b0, b1);
                mmah(o[2*ntp + 1], a0, a1, a2, a3, b2, b3);
            }
        }
        __syncthreads();
    }

    float inv0 = 1.0f / l0, inv1 = 1.0f / l1;
    int rg = rowBase + rloc0;
#pragma unroll
    for (int nt = 0; nt < 8; nt++) {
        int col = hh * 64 + nt * 8 + 2 * t;
        uint32_t h0, l0u, h1, l1u;
        split2(o[nt][0] * inv0, o[nt][1] * inv0, h0, l0u);
        split2(o[nt][2] * inv1, o[nt][3] * inv1, h1, l1u);
        *reinterpret_cast<uint32_t*>(&g_ath[(size_t)rg       * 1024 + col]) = h0;
        *reinterpret_cast<uint32_t*>(&g_atl[(size_t)rg       * 1024 + col]) = l0u;
        *reinterpret_cast<uint32_t*>(&g_ath[(size_t)(rg + 8) * 1024 + col]) = h1;
        *reinterpret_cast<uint32_t*>(&g_atl[(size_t)(rg + 8) * 1024 + col]) = l1u;
    }
}

// ---------------------------------------------------------------------------
// Launch — stream fork/join inside the captured graph.
// ---------------------------------------------------------------------------
extern "C" void kernel_launch(void* const* d_in, const int* in_sizes, int n_in,
                              void* d_out, int out_size)
{
    (void)in_sizes; (void)n_in; (void)out_size;
    const float* x   = (const float*)d_in[0];
    const float* w1  = (const float*)d_in[1];
    const float* b1  = (const float*)d_in[2];
    const float* wkr = (const float*)d_in[3];
    const float* bkr = (const float*)d_in[4];
    const float* wqr = (const float*)d_in[5];
    const float* bqr = (const float*)d_in[6];
    const float* wkv = (const float*)d_in[7];
    const float* bkv = (const float*)d_in[8];
    const float* wq  = (const float*)d_in[9];
    const float* bq  = (const float*)d_in[10];
    const float* wo  = (const float*)d_in[11];
    const float* bo  = (const float*)d_in[12];
    float* out = (float*)d_out;
    const float scale = 0.08838834764831845f;   // 128^-0.5

    __half *qh_, *qrh_, *krh_, *kvh_;
    __nv_bfloat16 *xh_, *xl_, *hh_, *hl_, *ath_, *atl_;
    __nv_bfloat16 *w1h_, *w1l_, *wkrh_, *wkrl_, *wqrh_, *wqrl_;
    __nv_bfloat16 *wkvh_, *wkvl_, *wqh_, *wql_, *woh_, *wol_;
    cudaGetSymbolAddress((void**)&qh_,  g_qh);
    cudaGetSymbolAddress((void**)&qrh_, g_qrh);
    cudaGetSymbolAddress((void**)&krh_, g_krh);
    cudaGetSymbolAddress((void**)&kvh_, g_kvh);
    cudaGetSymbolAddress((void**)&xh_,  g_xh);  cudaGetSymbolAddress((void**)&xl_,  g_xl);
    cudaGetSymbolAddress((void**)&hh_,  g_hh);  cudaGetSymbolAddress((void**)&hl_,  g_hl);
    cudaGetSymbolAddress((void**)&ath_, g_ath); cudaGetSymbolAddress((void**)&atl_, g_atl);
    cudaGetSymbolAddress((void**)&w1h_, g_w1h);  cudaGetSymbolAddress((void**)&w1l_, g_w1l);
    cudaGetSymbolAddress((void**)&wkrh_, g_wkrh); cudaGetSymbolAddress((void**)&wkrl_, g_wkrl);
    cudaGetSymbolAddress((void**)&wqrh_, g_wqrh); cudaGetSymbolAddress((void**)&wqrl_, g_wqrl);
    cudaGetSymbolAddress((void**)&wkvh_, g_wkvh); cudaGetSymbolAddress((void**)&wkvl_, g_wkvl);
    cudaGetSymbolAddress((void**)&wqh_, g_wqh);   cudaGetSymbolAddress((void**)&wql_, g_wql);
    cudaGetSymbolAddress((void**)&woh_, g_woh);   cudaGetSymbolAddress((void**)&wol_, g_wol);

    const int SMG128 = 2 * (2 * 128 * 40 + 2 * 128 * 40) * 2;   // 81920
    const int SMG64  = 2 * (2 * 128 * 40 + 2 * 64  * 40) * 2;   // 61440
    const int SMAT   = ATT_HALFS * 2;                            // 106496
    cudaFuncSetAttribute(gemm_bf16_3x<128, 0, 0>,    cudaFuncAttributeMaxDynamicSharedMemorySize, SMG128);
    cudaFuncSetAttribute(gemm_bf16_3x<128, 1, 0>,    cudaFuncAttributeMaxDynamicSharedMemorySize, SMG128);
    cudaFuncSetAttribute(gemm_bf16_3x<128, 2, 0>,    cudaFuncAttributeMaxDynamicSharedMemorySize, SMG128);
    cudaFuncSetAttribute(gemm_bf16_3x<128, 3, 1024>, cudaFuncAttributeMaxDynamicSharedMemorySize, SMG128);
    cudaFuncSetAttribute(gemm_bf16_3x<64,  3, 64>,   cudaFuncAttributeMaxDynamicSharedMemorySize, SMG64);
    cudaFuncSetAttribute(attn_fp16_kernel, cudaFuncAttributeMaxDynamicSharedMemorySize, SMAT);

    // streams/events created once (first call = correctness run, not captured)
    static cudaStream_t s1 = nullptr, s2 = nullptr, s3 = nullptr;
    static cudaEvent_t evFork, evX, evH, evD1, evD2, evD3;
    if (s1 == nullptr) {
        cudaStreamCreateWithFlags(&s1, cudaStreamNonBlocking);
        cudaStreamCreateWithFlags(&s2, cudaStreamNonBlocking);
        cudaStreamCreateWithFlags(&s3, cudaStreamNonBlocking);
        cudaEventCreateWithFlags(&evFork, cudaEventDisableTiming);
        cudaEventCreateWithFlags(&evX,    cudaEventDisableTiming);
        cudaEventCreateWithFlags(&evH,    cudaEventDisableTiming);
        cudaEventCreateWithFlags(&evD1,   cudaEventDisableTiming);
        cudaEventCreateWithFlags(&evD2,   cudaEventDisableTiming);
        cudaEventCreateWithFlags(&evD3,   cudaEventDisableTiming);
    }

    dim3 wsb(32, 8);

    // fork
    cudaEventRecord(evFork, 0);
    cudaStreamWaitEvent(s1, evFork, 0);
    cudaStreamWaitEvent(s2, evFork, 0);
    cudaStreamWaitEvent(s3, evFork, 0);

    // main: w1 split; s1: x split (feeds h GEMM)
    wsplit_kernel<<<dim3(1024/32, 1024/32), wsb, 0, 0>>>(w1, 1024, 1024, w1h_, w1l_);
    asplit_kernel<<<(MR * 1024 / 4 + 255) / 256, 256, 0, s1>>>(
        (const float4*)x, (uint2*)xh_, (uint2*)xl_, MR * 1024 / 4);
    cudaEventRecord(evX, s1);

    // other weight splits overlap h GEMM
    wsplit_kernel<<<dim3(1024/32, 1024/32), wsb, 0, s1>>>(wqr, 1024, 1024, wqrh_, wqrl_);
    wsplit_kernel<<<dim3(2048/32, 512/32),  wsb, 0, s2>>>(wkv, 512,  2048, wkvh_, wkvl_);
    wsplit_kernel<<<dim3(1024/32, 512/32),  wsb, 0, s3>>>(wq,  512,  1024, wqh_,  wql_);
    wsplit_kernel<<<dim3(64/32,   1024/32), wsb, 0, s3>>>(wkr, 1024, 64,   wkrh_, wkrl_);
    wsplit_kernel<<<dim3(1024/32, 1024/32), wsb, 0, s3>>>(wo,  1024, 1024, woh_,  wol_);

    // 1) h = x @ w1 + b1 -> split bf16 (main stream)
    cudaStreamWaitEvent(0, evX, 0);
    gemm_bf16_3x<128, 1, 0><<<dim3(8, 32), 256, SMG128, 0>>>(
        1024, 1024, xh_, xl_, 1024, w1h_, w1l_, b1, 1.f, nullptr, hh_, hl_, nullptr);
    cudaEventRecord(evH, 0);

    // 3) qr = rope((h @ wqr + bqr) * scale) -> fp16   (s1)
    cudaStreamWaitEvent(s1, evH, 0);
    gemm_bf16_3x<128, 3, 1024><<<dim3(8, 32), 256, SMG128, s1>>>(
        1024, 1024, hh_, hl_, 1024, wqrh_, wqrl_, bqr, scale, nullptr, nullptr, nullptr, qrh_);
    cudaEventRecord(evD1, s1);

    // 4) kv = cKV @ wkv + bkv -> fp16                 (s2)
    cudaStreamWaitEvent(s2, evH, 0);
    gemm_bf16_3x<128, 2, 0><<<dim3(16, 32), 256, SMG128, s2>>>(
        2048, 512, hh_, hl_, 1024, wkvh_, wkvl_, bkv, 1.f, nullptr, nullptr, nullptr, kvh_);
    cudaEventRecord(evD2, s2);

    // 5) q = (cq @ wq + bq) * scale -> fp16 ; 2) kr = rope(h @ wkr + bkr) -> fp16   (s3)
    cudaStreamWaitEvent(s3, evH, 0);
    gemm_bf16_3x<128, 2, 0><<<dim3(8, 32), 256, SMG128, s3>>>(
        1024, 512, hh_ + 512, hl_ + 512, 1024, wqh_, wql_, bq, scale, nullptr, nullptr, nullptr, qh_);
    gemm_bf16_3x<64, 3, 64><<<dim3(1, 32), 256, SMG64, s3>>>(
        64, 1024, hh_, hl_, 1024, wkrh_, wkrl_, bkr, 1.f, nullptr, nullptr, nullptr, krh_);
    cudaEventRecord(evD3, s3);

    // join -> attention -> wo (main stream)
    cudaStreamWaitEvent(0, evD1, 0);
    cudaStreamWaitEvent(0, evD2, 0);
    cudaStreamWaitEvent(0, evD3, 0);

    attn_fp16_kernel<<<dim3(16, NH, BB), 256, SMAT, 0>>>();

    gemm_bf16_3x<128, 0, 0><<<dim3(8, 32), 256, SMG128, 0>>>(
        1024, 1024, ath_, atl_, 1024, woh_, wol_, bo, 1.f, out, nullptr, nullptr, nullptr);
}

// round 12
// speedup vs baseline: 1.7286x; 1.2512x over previous
#include <cuda_runtime.h>
#include <cuda_bf16.h>
#include <cuda_fp16.h>
#include <math.h>
#include <stdint.h>

// Problem constants
#define BB   2
#define TT   2048
#define CC   1024
#define NH   16
#define LAT  512
#define DHR  64
#define MR   (BB*TT)        // 4096 rows

// ---------------------------------------------------------------------------
// Scratch (static device globals)
// ---------------------------------------------------------------------------
__device__ __half g_qh [MR * 1024];
__device__ __half g_qrh[MR * 1024];
__device__ __half g_krh[MR * 64];
__device__ __half g_kvh[MR * 2048];   // k cols 0..1023, v cols 1024..2047

// fp16 hi/lo split pairs (x ~= hi + lo, residual ~2^-22)
__device__ __half g_xh[MR*1024],  g_xl[MR*1024];
__device__ __half g_hh[MR*1024],  g_hl[MR*1024];
__device__ __half g_ath[MR*1024], g_atl[MR*1024];
// transposed weights [N,K], single fp16
__device__ __half g_w1f [1024*1024];
__device__ __half g_wkrf[64*1024];
__device__ __half g_wqrf[1024*1024];
__device__ __half g_wkvf[2048*512];
__device__ __half g_wqf [1024*512];
__device__ __half g_wof [1024*1024];

// ---------------------------------------------------------------------------
// helpers
// ---------------------------------------------------------------------------
__device__ __forceinline__ void mmah(float* c, const uint32_t* a,
                                     uint32_t b0, uint32_t b1) {
    asm volatile(
        "mma.sync.aligned.m16n8k16.row.col.f32.f16.f16.f32 "
        "{%0,%1,%2,%3},{%4,%5,%6,%7},{%8,%9},{%0,%1,%2,%3};"
        : "+f"(c[0]), "+f"(c[1]), "+f"(c[2]), "+f"(c[3])
        : "r"(a[0]), "r"(a[1]), "r"(a[2]), "r"(a[3]), "r"(b0), "r"(b1));
}
__device__ __forceinline__ void mmah4(float* c,
                                      uint32_t a0, uint32_t a1, uint32_t a2, uint32_t a3,
                                      uint32_t b0, uint32_t b1) {
    asm volatile(
        "mma.sync.aligned.m16n8k16.row.col.f32.f16.f16.f32 "
        "{%0,%1,%2,%3},{%4,%5,%6,%7},{%8,%9},{%0,%1,%2,%3};"
        : "+f"(c[0]), "+f"(c[1]), "+f"(c[2]), "+f"(c[3])
        : "r"(a0), "r"(a1), "r"(a2), "r"(a3), "r"(b0), "r"(b1));
}
__device__ __forceinline__ void ldsm4t(uint32_t& r0, uint32_t& r1,
                                       uint32_t& r2, uint32_t& r3, uint32_t addr) {
    asm volatile("ldmatrix.sync.aligned.m8n8.x4.trans.shared.b16 {%0,%1,%2,%3}, [%4];"
                 : "=r"(r0), "=r"(r1), "=r"(r2), "=r"(r3) : "r"(addr));
}
// pack two fp32 -> fp16x2 (x in low half)
__device__ __forceinline__ uint32_t h2pack(float x, float y) {
    uint32_t u;
    asm("cvt.rn.f16x2.f32 %0, %1, %2;" : "=r"(u) : "f"(y), "f"(x));
    return u;
}
// fp16 Dekker split of a pair: hi = f16x2(x,y), lo = f16x2 of residuals
__device__ __forceinline__ void split2h(float x, float y, uint32_t& hi, uint32_t& lo) {
    uint32_t h = h2pack(x, y);
    __half2 hv = *reinterpret_cast<__half2*>(&h);
    float hx = __half2float(hv.x);
    float hy = __half2float(hv.y);
    hi = h;
    lo = h2pack(x - hx, y - hy);
}
__device__ __forceinline__ uint32_t sptr(const void* p) {
    return (uint32_t)__cvta_generic_to_shared(p);
}
__device__ __forceinline__ void cp16(uint32_t dst, const void* src) {
    asm volatile("cp.async.cg.shared.global [%0], [%1], 16;" :: "r"(dst), "l"(src));
}
__device__ __forceinline__ void cp_commit() {
    asm volatile("cp.async.commit_group;");
}
template<int N> __device__ __forceinline__ void cp_wait() {
    asm volatile("cp.async.wait_group %0;" :: "n"(N));
}

// ---------------------------------------------------------------------------
// Weight transpose: W[K,N] fp32 -> Wf[N,K] fp16
// ---------------------------------------------------------------------------
__global__ void wsplit_kernel(const float* __restrict__ W, int K, int N,
                              __half* __restrict__ Wf)
{
    __shared__ float tile[32][33];
    int n0 = blockIdx.x * 32, k0 = blockIdx.y * 32;
    int tx = threadIdx.x, ty = threadIdx.y;
#pragma unroll
    for (int i = 0; i < 32; i += 8)
        tile[ty + i][tx] = W[(size_t)(k0 + ty + i) * N + n0 + tx];
    __syncthreads();
#pragma unroll
    for (int i = 0; i < 32; i += 8) {
        int n = n0 + ty + i, k = k0 + tx;
        Wf[(size_t)n * K + k] = __float2half_rn(tile[tx][ty + i]);
    }
}

// x split: fp32 -> fp16 hi/lo
__global__ void asplit_kernel(const float4* __restrict__ X,
                              uint2* __restrict__ Xh, uint2* __restrict__ Xl, int n4)
{
    int i = blockIdx.x * blockDim.x + threadIdx.x;
    if (i >= n4) return;
    float4 v = X[i];
    uint32_t h0, l0, h1, l1;
    split2h(v.x, v.y, h0, l0);
    split2h(v.z, v.w, h1, l1);
    Xh[i] = make_uint2(h0, h1);
    Xl[i] = make_uint2(l0, l1);
}

// ---------------------------------------------------------------------------
// 2-pass fp16 mma.sync GEMM: C = (Ah+Al)[M,K] @ B[N,K]^T + bias
// A exact (fp16 Dekker pair), B single fp16 (weight rounding ~2^-12).
// OUT: 0 = fp32 C, 1 = split fp16 (Ch/Cl), 2 = packed fp16 (H),
//      3 = packed fp16 with fused RoPE (rotary dim = RD)
// ---------------------------------------------------------------------------
template<int BN, int OUT, int RD>
__global__ __launch_bounds__(256, 2)
void gemm_f16_2x(int N, int K,
                 const __half* __restrict__ Agh,
                 const __half* __restrict__ Agl, int lda,
                 const __half* __restrict__ Bg,
                 const float* __restrict__ bias, float oscale,
                 float* __restrict__ C,
                 __half* __restrict__ Ch,
                 __half* __restrict__ Cl,
                 __half* __restrict__ H)
{
    constexpr int BM   = 128;
    constexpr int WM   = BM / 4;
    constexpr int WN   = BN / 2;
    constexpr int MT   = WM / 16;
    constexpr int NT   = WN / 8;
    constexpr int STR  = 40;              // padded row stride (halfs)
    constexpr int ASL  = BM * STR;        // halfs per A slab
    constexpr int BSL  = BN * STR;
    constexpr int STG  = 2 * ASL + BSL;   // halfs per stage
    constexpr int NAC  = (BM * 4) / 256;  // 16B chunks per thread
    constexpr int NBC  = (BN * 4) / 256;

    extern __shared__ __half smb[];

    const int tid  = threadIdx.x;
    const int lane = tid & 31;
    const int warp = tid >> 5;
    const int g    = lane >> 2;
    const int t    = lane & 3;
    const int wm   = warp >> 1;
    const int wn   = warp & 1;
    const int bRow = blockIdx.y * BM;
    const int bCol = blockIdx.x * BN;

    float acc[MT][NT][4];
#pragma unroll
    for (int mt = 0; mt < MT; mt++)
#pragma unroll
        for (int nt = 0; nt < NT; nt++)
#pragma unroll
            for (int i = 0; i < 4; i++) acc[mt][nt][i] = 0.f;

    auto issue = [&](int k0, int s) {
        __half* st = smb + s * STG;
#pragma unroll
        for (int i = 0; i < NAC; i++) {
            int idx = tid + i * 256;
            int r = idx >> 2, c = idx & 3;          // 4 x 16B chunks per 64B row
            uint32_t d = sptr(st + r * STR + c * 8);
            cp16(d, Agh + (size_t)(bRow + r) * lda + k0 + c * 8);
            cp16(d + ASL * 2, Agl + (size_t)(bRow + r) * lda + k0 + c * 8);
        }
#pragma unroll
        for (int i = 0; i < NBC; i++) {
            int idx = tid + i * 256;
            int r = idx >> 2, c = idx & 3;
            cp16(sptr(st + 2 * ASL + r * STR + c * 8),
                 Bg + (size_t)(bCol + r) * K + k0 + c * 8);
        }
        cp_commit();
    };

    const int iters = K / 32;
    issue(0, 0);

    for (int it = 0; it < iters; it++) {
        const int cur = it & 1;
        if (it + 1 < iters) { issue((it + 1) * 32, cur ^ 1); cp_wait<1>(); }
        else                { cp_wait<0>(); }
        __syncthreads();

        const __half* Ah = smb + cur * STG;
        const __half* Al = Ah + ASL;
        const __half* Bs = Ah + 2 * ASL;

#pragma unroll
        for (int s = 0; s < 2; s++) {
            const int kb = 16 * s + 2 * t;
            uint32_t ah[MT][4], al[MT][4];
#pragma unroll
            for (int mt = 0; mt < MT; mt++) {
                int r0 = wm * WM + mt * 16 + g;
                int r1 = r0 + 8;
                ah[mt][0] = *reinterpret_cast<const uint32_t*>(&Ah[r0 * STR + kb]);
                ah[mt][1] = *reinterpret_cast<const uint32_t*>(&Ah[r1 * STR + kb]);
                ah[mt][2] = *reinterpret_cast<const uint32_t*>(&Ah[r0 * STR + kb + 8]);
                ah[mt][3] = *reinterpret_cast<const uint32_t*>(&Ah[r1 * STR + kb + 8]);
                al[mt][0] = *reinterpret_cast<const uint32_t*>(&Al[r0 * STR + kb]);
                al[mt][1] = *reinterpret_cast<const uint32_t*>(&Al[r1 * STR + kb]);
                al[mt][2] = *reinterpret_cast<const uint32_t*>(&Al[r0 * STR + kb + 8]);
                al[mt][3] = *reinterpret_cast<const uint32_t*>(&Al[r1 * STR + kb + 8]);
            }
#pragma unroll
            for (int nt = 0; nt < NT; nt++) {
                int nb = wn * WN + nt * 8 + g;
                uint32_t b0 = *reinterpret_cast<const uint32_t*>(&Bs[nb * STR + kb]);
                uint32_t b1 = *reinterpret_cast<const uint32_t*>(&Bs[nb * STR + kb + 8]);
#pragma unroll
                for (int mt = 0; mt < MT; mt++) {
                    mmah(acc[mt][nt], ah[mt], b0, b1);
                    mmah(acc[mt][nt], al[mt], b0, b1);
                }
            }
        }
        __syncthreads();
    }

#pragma unroll
    for (int mt = 0; mt < MT; mt++) {
        int r0 = bRow + wm * WM + mt * 16 + g;
#pragma unroll
        for (int nt = 0; nt < NT; nt++) {
            int col = bCol + wn * WN + nt * 8 + 2 * t;
            float bx = bias[col], by = bias[col + 1];
            float v00 = (acc[mt][nt][0] + bx) * oscale, v01 = (acc[mt][nt][1] + by) * oscale;
            float v10 = (acc[mt][nt][2] + bx) * oscale, v11 = (acc[mt][nt][3] + by) * oscale;
            if (OUT == 0) {
                float2 a = {v00, v01}, b = {v10, v11};
                *reinterpret_cast<float2*>(C + (size_t)r0 * N + col)       = a;
                *reinterpret_cast<float2*>(C + (size_t)(r0 + 8) * N + col) = b;
            } else if (OUT == 1) {
                uint32_t h0, l0, h1, l1;
                split2h(v00, v01, h0, l0);
                split2h(v10, v11, h1, l1);
                *reinterpret_cast<uint32_t*>(&Ch[(size_t)r0 * N + col])       = h0;
                *reinterpret_cast<uint32_t*>(&Cl[(size_t)r0 * N + col])       = l0;
                *reinterpret_cast<uint32_t*>(&Ch[(size_t)(r0 + 8) * N + col]) = h1;
                *reinterpret_cast<uint32_t*>(&Cl[(size_t)(r0 + 8) * N + col]) = l1;
            } else if (OUT == 2) {
                *reinterpret_cast<uint32_t*>(&H[(size_t)r0 * N + col])       = h2pack(v00, v01);
                *reinterpret_cast<uint32_t*>(&H[(size_t)(r0 + 8) * N + col]) = h2pack(v10, v11);
            } else {
                // fused RoPE (rotary dim RD); (col, col+1) is a rope pair
                float th = expf(-2.0f * (float)(col >> 1) / (float)RD * 9.2103403719761836f);
                int tt0 = r0 & (TT - 1);
                float sn0, cs0, sn1, cs1;
                sincosf((float)(tt0 + 1) * th, &sn0, &cs0);
                sincosf((float)(tt0 + 9) * th, &sn1, &cs1);
                float e0 = v00 * cs0 - v01 * sn0;
                float o0 = v01 * cs0 + v00 * sn0;
                float e1 = v10 * cs1 - v11 * sn1;
                float o1 = v11 * cs1 + v10 * sn1;
                *reinterpret_cast<uint32_t*>(&H[(size_t)r0 * N + col])       = h2pack(e0, o0);
                *reinterpret_cast<uint32_t*>(&H[(size_t)(r0 + 8) * N + col]) = h2pack(e1, o1);
            }
        }
    }
}

// ---------------------------------------------------------------------------
// Causal flash attention, fp16 mma.sync m16n8k16, 2 CTAs/SM. (R9/R10 form)
// ---------------------------------------------------------------------------
#define QSTH 136
#define KSTH 136
#define VSTH 72
#define PSTH 72

#define OFFH_K (128 * QSTH)
#define OFFH_V (OFFH_K + 2 * 64 * KSTH)
#define OFFH_P (OFFH_V + 2 * 64 * VSTH)
#define ATT_HALFS (OFFH_P + 128 * PSTH)     // 53248 halfs = 106496 B

__global__ __launch_bounds__(256, 2)
void attn_fp16_kernel()
{
    extern __shared__ __half smh[];
    __half* Qh = smh;
    __half* Ph = smh + OFFH_P;

    const int tid  = threadIdx.x;
    const int lane = tid & 31;
    const int warp = tid >> 5;
    const int g    = lane >> 2;
    const int t    = lane & 3;
    const int qt   = (gridDim.x - 1) - blockIdx.x;
    const int hh   = blockIdx.y;
    const int b    = blockIdx.z;
    const int rowBase = b * TT + qt * 128;

    auto issueKV = [&](int j, int s) {
        __half* Kt = smh + OFFH_K + s * 64 * KSTH;
        __half* Vt = smh + OFFH_V + s * 64 * VSTH;
        const int kbase = b * TT + j * 64;
#pragma unroll
        for (int i = 0; i < 4; i++) {
            int idx = tid + i * 256;
            int r = idx >> 4, c = idx & 15;
            uint32_t d = sptr(Kt + r * KSTH + c * 8);
            if (c < 8) cp16(d, g_kvh + (size_t)(kbase + r) * 2048 + hh * 64 + c * 8);
            else       cp16(d, g_krh + (size_t)(kbase + r) * 64 + (c - 8) * 8);
        }
#pragma unroll
        for (int i = 0; i < 2; i++) {
            int idx = tid + i * 256;
            int r = idx >> 3, c = idx & 7;
            cp16(sptr(Vt + r * VSTH + c * 8),
                 g_kvh + (size_t)(kbase + r) * 2048 + 1024 + hh * 64 + c * 8);
        }
        cp_commit();
    };

#pragma unroll
    for (int i = 0; i < 8; i++) {
        int idx = tid + i * 256;
        int r = idx >> 4, c = idx & 15;
        uint32_t d = sptr(Qh + r * QSTH + c * 8);
        if (c < 8) cp16(d, g_qh  + (size_t)(rowBase + r) * 1024 + hh * 64 + c * 8);
        else       cp16(d, g_qrh + (size_t)(rowBase + r) * 1024 + hh * 64 + (c - 8) * 8);
    }
    issueKV(0, 0);

    const int vrow = (lane & 7) + ((lane >> 3) & 1) * 8;
    const int vcol = (lane >> 4) * 8;
    const uint32_t vLaneByte = (uint32_t)(vrow * VSTH + vcol) * 2;

    const int rloc0 = warp * 16 + g;
    float m0 = -1e30f, m1 = -1e30f, l0 = 0.f, l1 = 0.f;
    float o[8][4];
#pragma unroll
    for (int nt = 0; nt < 8; nt++)
#pragma unroll
        for (int i = 0; i < 4; i++) o[nt][i] = 0.f;

    const int nkt = 2 * qt + 2;
    for (int j = 0; j < nkt; j++) {
        const int s = j & 1;
        if (j + 1 < nkt) { issueKV(j + 1, s ^ 1); cp_wait<1>(); }
        else             { cp_wait<0>(); }
        __syncthreads();

        const __half* Kt = smh + OFFH_K + s * 64 * KSTH;
        const uint32_t vBuf = sptr(smh + OFFH_V + s * 64 * VSTH);

        float sc[8][4];
#pragma unroll
        for (int nt = 0; nt < 8; nt++)
#pragma unroll
            for (int i = 0; i < 4; i++) sc[nt][i] = 0.f;

#pragma unroll
        for (int ks = 0; ks < 8; ks++) {
            const int kb = ks * 16 + 2 * t;
            uint32_t a0 = *reinterpret_cast<const uint32_t*>(&Qh[(rloc0)     * QSTH + kb]);
            uint32_t a1 = *reinterpret_cast<const uint32_t*>(&Qh[(rloc0 + 8) * QSTH + kb]);
            uint32_t a2 = *reinterpret_cast<const uint32_t*>(&Qh[(rloc0)     * QSTH + kb + 8]);
            uint32_t a3 = *reinterpret_cast<const uint32_t*>(&Qh[(rloc0 + 8) * QSTH + kb + 8]);
#pragma unroll
            for (int nt = 0; nt < 8; nt++) {
                uint32_t b0 = *reinterpret_cast<const uint32_t*>(&Kt[(nt * 8 + g) * KSTH + kb]);
                uint32_t b1 = *reinterpret_cast<const uint32_t*>(&Kt[(nt * 8 + g) * KSTH + kb + 8]);
                mmah4(sc[nt], a0, a1, a2, a3, b0, b1);
            }
        }

        if (j >= 2 * qt) {
            int rg0 = qt * 128 + rloc0;
            int k0 = j * 64;
#pragma unroll
            for (int nt = 0; nt < 8; nt++) {
                int cg = k0 + nt * 8 + 2 * t;
                if (cg     > rg0)     sc[nt][0] = -1e30f;
                if (cg + 1 > rg0)     sc[nt][1] = -1e30f;
                if (cg     > rg0 + 8) sc[nt][2] = -1e30f;
                if (cg + 1 > rg0 + 8) sc[nt][3] = -1e30f;
            }
        }

        float mx0 = -1e30f, mx1 = -1e30f;
#pragma unroll
        for (int nt = 0; nt < 8; nt++) {
            mx0 = fmaxf(mx0, fmaxf(sc[nt][0], sc[nt][1]));
            mx1 = fmaxf(mx1, fmaxf(sc[nt][2], sc[nt][3]));
        }
        mx0 = fmaxf(mx0, __shfl_xor_sync(0xffffffffu, mx0, 1));
        mx0 = fmaxf(mx0, __shfl_xor_sync(0xffffffffu, mx0, 2));
        mx1 = fmaxf(mx1, __shfl_xor_sync(0xffffffffu, mx1, 1));
        mx1 = fmaxf(mx1, __shfl_xor_sync(0xffffffffu, mx1, 2));

        float mn0 = fmaxf(m0, mx0), mn1 = fmaxf(m1, mx1);
        float al0 = __expf(m0 - mn0), al1 = __expf(m1 - mn1);
        m0 = mn0; m1 = mn1;

        float sum0 = 0.f, sum1 = 0.f;
#pragma unroll
        for (int nt = 0; nt < 8; nt++) {
            float p0 = __expf(sc[nt][0] - mn0);
            float p1 = __expf(sc[nt][1] - mn0);
            float p2 = __expf(sc[nt][2] - mn1);
            float p3 = __expf(sc[nt][3] - mn1);
            sum0 += p0 + p1; sum1 += p2 + p3;
            *reinterpret_cast<uint32_t*>(&Ph[(rloc0)     * PSTH + nt * 8 + 2 * t]) = h2pack(p0, p1);
            *reinterpret_cast<uint32_t*>(&Ph[(rloc0 + 8) * PSTH + nt * 8 + 2 * t]) = h2pack(p2, p3);
        }
        sum0 += __shfl_xor_sync(0xffffffffu, sum0, 1);
        sum0 += __shfl_xor_sync(0xffffffffu, sum0, 2);
        sum1 += __shfl_xor_sync(0xffffffffu, sum1, 1);
        sum1 += __shfl_xor_sync(0xffffffffu, sum1, 2);
        l0 = l0 * al0 + sum0;
        l1 = l1 * al1 + sum1;

#pragma unroll
        for (int nt = 0; nt < 8; nt++) {
            o[nt][0] *= al0; o[nt][1] *= al0;
            o[nt][2] *= al1; o[nt][3] *= al1;
        }
        __syncwarp();

#pragma unroll
        for (int ks = 0; ks < 4; ks++) {
            const int kb = ks * 16 + 2 * t;
            uint32_t a0 = *reinterpret_cast<const uint32_t*>(&Ph[(rloc0)     * PSTH + kb]);
            uint32_t a1 = *reinterpret_cast<const uint32_t*>(&Ph[(rloc0 + 8) * PSTH + kb]);
            uint32_t a2 = *reinterpret_cast<const uint32_t*>(&Ph[(rloc0)     * PSTH + kb + 8]);
            uint32_t a3 = *reinterpret_cast<const uint32_t*>(&Ph[(rloc0 + 8) * PSTH + kb + 8]);
#pragma unroll
            for (int ntp = 0; ntp < 4; ntp++) {
                uint32_t b0, b1, b2, b3;
                ldsm4t(b0, b1, b2, b3,
                       vBuf + vLaneByte + (uint32_t)(ks * 16 * VSTH + ntp * 16) * 2);
                mmah4(o[2*ntp],     a0, a1, a2, a3, b0, b1);
                mmah4(o[2*ntp + 1], a0, a1, a2, a3, b2, b3);
            }
        }
        __syncthreads();
    }

    // finalize + store split fp16 (att feeds only the wo GEMM)
    float inv0 = 1.0f / l0, inv1 = 1.0f / l1;
    int rg = rowBase + rloc0;
#pragma unroll
    for (int nt = 0; nt < 8; nt++) {
        int col = hh * 64 + nt * 8 + 2 * t;
        uint32_t h0, l0u, h1, l1u;
        split2h(o[nt][0] * inv0, o[nt][1] * inv0, h0, l0u);
        split2h(o[nt][2] * inv1, o[nt][3] * inv1, h1, l1u);
        *reinterpret_cast<uint32_t*>(&g_ath[(size_t)rg       * 1024 + col]) = h0;
        *reinterpret_cast<uint32_t*>(&g_atl[(size_t)rg       * 1024 + col]) = l0u;
        *reinterpret_cast<uint32_t*>(&g_ath[(size_t)(rg + 8) * 1024 + col]) = h1;
        *reinterpret_cast<uint32_t*>(&g_atl[(size_t)(rg + 8) * 1024 + col]) = l1u;
    }
}

// ---------------------------------------------------------------------------
// Launch — R10 topology (known-good graph shape).
// ---------------------------------------------------------------------------
extern "C" void kernel_launch(void* const* d_in, const int* in_sizes, int n_in,
                              void* d_out, int out_size)
{
    (void)in_sizes; (void)n_in; (void)out_size;
    const float* x   = (const float*)d_in[0];
    const float* w1  = (const float*)d_in[1];
    const float* b1  = (const float*)d_in[2];
    const float* wkr = (const float*)d_in[3];
    const float* bkr = (const float*)d_in[4];
    const float* wqr = (const float*)d_in[5];
    const float* bqr = (const float*)d_in[6];
    const float* wkv = (const float*)d_in[7];
    const float* bkv = (const float*)d_in[8];
    const float* wq  = (const float*)d_in[9];
    const float* bq  = (const float*)d_in[10];
    const float* wo  = (const float*)d_in[11];
    const float* bo  = (const float*)d_in[12];
    float* out = (float*)d_out;
    const float scale = 0.08838834764831845f;   // 128^-0.5

    __half *qh_, *qrh_, *krh_, *kvh_;
    __half *xh_, *xl_, *hh_, *hl_, *ath_, *atl_;
    __half *w1f_, *wkrf_, *wqrf_, *wkvf_, *wqf_, *wof_;
    cudaGetSymbolAddress((void**)&qh_,  g_qh);
    cudaGetSymbolAddress((void**)&qrh_, g_qrh);
    cudaGetSymbolAddress((void**)&krh_, g_krh);
    cudaGetSymbolAddress((void**)&kvh_, g_kvh);
    cudaGetSymbolAddress((void**)&xh_,  g_xh);  cudaGetSymbolAddress((void**)&xl_,  g_xl);
    cudaGetSymbolAddress((void**)&hh_,  g_hh);  cudaGetSymbolAddress((void**)&hl_,  g_hl);
    cudaGetSymbolAddress((void**)&ath_, g_ath); cudaGetSymbolAddress((void**)&atl_, g_atl);
    cudaGetSymbolAddress((void**)&w1f_,  g_w1f);
    cudaGetSymbolAddress((void**)&wkrf_, g_wkrf);
    cudaGetSymbolAddress((void**)&wqrf_, g_wqrf);
    cudaGetSymbolAddress((void**)&wkvf_, g_wkvf);
    cudaGetSymbolAddress((void**)&wqf_,  g_wqf);
    cudaGetSymbolAddress((void**)&wof_,  g_wof);

    const int SMG128 = 2 * (2 * 128 * 40 + 128 * 40) * 2;   // 61440
    const int SMG64  = 2 * (2 * 128 * 40 + 64  * 40) * 2;   // 51200
    const int SMAT   = ATT_HALFS * 2;                        // 106496
    cudaFuncSetAttribute(gemm_f16_2x<128, 0, 0>,    cudaFuncAttributeMaxDynamicSharedMemorySize, SMG128);
    cudaFuncSetAttribute(gemm_f16_2x<128, 1, 0>,    cudaFuncAttributeMaxDynamicSharedMemorySize, SMG128);
    cudaFuncSetAttribute(gemm_f16_2x<128, 2, 0>,    cudaFuncAttributeMaxDynamicSharedMemorySize, SMG128);
    cudaFuncSetAttribute(gemm_f16_2x<128, 3, 1024>, cudaFuncAttributeMaxDynamicSharedMemorySize, SMG128);
    cudaFuncSetAttribute(gemm_f16_2x<64,  3, 64>,   cudaFuncAttributeMaxDynamicSharedMemorySize, SMG64);
    cudaFuncSetAttribute(attn_fp16_kernel, cudaFuncAttributeMaxDynamicSharedMemorySize, SMAT);

    // streams/events created once (first call = correctness run, not captured)
    static cudaStream_t s1 = nullptr, s2 = nullptr, s3 = nullptr;
    static cudaEvent_t evFork, evX, evH, evD1, evD2, evD3;
    if (s1 == nullptr) {
        cudaStreamCreateWithFlags(&s1, cudaStreamNonBlocking);
        cudaStreamCreateWithFlags(&s2, cudaStreamNonBlocking);
        cudaStreamCreateWithFlags(&s3, cudaStreamNonBlocking);
        cudaEventCreateWithFlags(&evFork, cudaEventDisableTiming);
        cudaEventCreateWithFlags(&evX,    cudaEventDisableTiming);
        cudaEventCreateWithFlags(&evH,    cudaEventDisableTiming);
        cudaEventCreateWithFlags(&evD1,   cudaEventDisableTiming);
        cudaEventCreateWithFlags(&evD2,   cudaEventDisableTiming);
        cudaEventCreateWithFlags(&evD3,   cudaEventDisableTiming);
    }

    dim3 wsb(32, 8);

    // fork
    cudaEventRecord(evFork, 0);
    cudaStreamWaitEvent(s1, evFork, 0);
    cudaStreamWaitEvent(s2, evFork, 0);
    cudaStreamWaitEvent(s3, evFork, 0);

    // main: w1 transpose; s1: x split (feeds h GEMM)
    wsplit_kernel<<<dim3(1024/32, 1024/32), wsb, 0, 0>>>(w1, 1024, 1024, w1f_);
    asplit_kernel<<<(MR * 1024 / 4 + 255) / 256, 256, 0, s1>>>(
        (const float4*)x, (uint2*)xh_, (uint2*)xl_, MR * 1024 / 4);
    cudaEventRecord(evX, s1);

    // other weight transposes overlap h GEMM
    wsplit_kernel<<<dim3(1024/32, 1024/32), wsb, 0, s1>>>(wqr, 1024, 1024, wqrf_);
    wsplit_kernel<<<dim3(2048/32, 512/32),  wsb, 0, s2>>>(wkv, 512,  2048, wkvf_);
    wsplit_kernel<<<dim3(1024/32, 512/32),  wsb, 0, s3>>>(wq,  512,  1024, wqf_);
    wsplit_kernel<<<dim3(64/32,   1024/32), wsb, 0, s3>>>(wkr, 1024, 64,   wkrf_);
    wsplit_kernel<<<dim3(1024/32, 1024/32), wsb, 0, s3>>>(wo,  1024, 1024, wof_);

    // 1) h = x @ w1 + b1 -> split fp16 (main stream)
    cudaStreamWaitEvent(0, evX, 0);
    gemm_f16_2x<128, 1, 0><<<dim3(8, 32), 256, SMG128, 0>>>(
        1024, 1024, xh_, xl_, 1024, w1f_, b1, 1.f, nullptr, hh_, hl_, nullptr);
    cudaEventRecord(evH, 0);

    // 3) qr = rope((h @ wqr + bqr) * scale) -> fp16   (s1)
    cudaStreamWaitEvent(s1, evH, 0);
    gemm_f16_2x<128, 3, 1024><<<dim3(8, 32), 256, SMG128, s1>>>(
        1024, 1024, hh_, hl_, 1024, wqrf_, bqr, scale, nullptr, nullptr, nullptr, qrh_);
    cudaEventRecord(evD1, s1);

    // 4) kv = cKV @ wkv + bkv -> fp16                 (s2)
    cudaStreamWaitEvent(s2, evH, 0);
    gemm_f16_2x<128, 2, 0><<<dim3(16, 32), 256, SMG128, s2>>>(
        2048, 512, hh_, hl_, 1024, wkvf_, bkv, 1.f, nullptr, nullptr, nullptr, kvh_);
    cudaEventRecord(evD2, s2);

    // 5) q = (cq @ wq + bq) * scale -> fp16 ; 2) kr = rope(h @ wkr + bkr) -> fp16   (s3)
    cudaStreamWaitEvent(s3, evH, 0);
    gemm_f16_2x<128, 2, 0><<<dim3(8, 32), 256, SMG128, s3>>>(
        1024, 512, hh_ + 512, hl_ + 512, 1024, wqf_, bq, scale, nullptr, nullptr, nullptr, qh_);
    gemm_f16_2x<64, 3, 64><<<dim3(1, 32), 256, SMG64, s3>>>(
        64, 1024, hh_, hl_, 1024, wkrf_, bkr, 1.f, nullptr, nullptr, nullptr, krh_);
    cudaEventRecord(evD3, s3);

    // join -> attention -> wo (main stream)
    cudaStreamWaitEvent(0, evD1, 0);
    cudaStreamWaitEvent(0, evD2, 0);
    cudaStreamWaitEvent(0, evD3, 0);

    attn_fp16_kernel<<<dim3(16, NH, BB), 256, SMAT, 0>>>();

    gemm_f16_2x<128, 0, 0><<<dim3(8, 32), 256, SMG128, 0>>>(
        1024, 1024, ath_, atl_, 1024, wof_, bo, 1.f, out, nullptr, nullptr, nullptr);
}

// round 13
// speedup vs baseline: 1.9645x; 1.1365x over previous
#include <cuda_runtime.h>
#include <cuda_bf16.h>
#include <cuda_fp16.h>
#include <math.h>
#include <stdint.h>

// Problem constants
#define BB   2
#define TT   2048
#define CC   1024
#define NH   16
#define LAT  512
#define DHR  64
#define MR   (BB*TT)        // 4096 rows

// ---------------------------------------------------------------------------
// Scratch (static device globals)
// ---------------------------------------------------------------------------
__device__ __half g_qh [MR * 1024];
__device__ __half g_qrh[MR * 1024];
__device__ __half g_krh[MR * 64];
__device__ __half g_kvh[MR * 2048];   // k cols 0..1023, v cols 1024..2047

// fp16 hi/lo split pairs (x ~= hi + lo, residual ~2^-22)
__device__ __half g_xh[MR*1024],  g_xl[MR*1024];
__device__ __half g_hh[MR*1024],  g_hl[MR*1024];
__device__ __half g_ath[MR*1024], g_atl[MR*1024];
// transposed weights [N,K], single fp16
__device__ __half g_w1f [1024*1024];
__device__ __half g_wkrf[64*1024];
__device__ __half g_wqrf[1024*1024];
__device__ __half g_wkvf[2048*512];
__device__ __half g_wqf [1024*512];
__device__ __half g_wof [1024*1024];

// ---------------------------------------------------------------------------
// helpers
// ---------------------------------------------------------------------------
__device__ __forceinline__ void mmah(float* c, const uint32_t* a,
                                     uint32_t b0, uint32_t b1) {
    asm volatile(
        "mma.sync.aligned.m16n8k16.row.col.f32.f16.f16.f32 "
        "{%0,%1,%2,%3},{%4,%5,%6,%7},{%8,%9},{%0,%1,%2,%3};"
        : "+f"(c[0]), "+f"(c[1]), "+f"(c[2]), "+f"(c[3])
        : "r"(a[0]), "r"(a[1]), "r"(a[2]), "r"(a[3]), "r"(b0), "r"(b1));
}
__device__ __forceinline__ void mmah4(float* c,
                                      uint32_t a0, uint32_t a1, uint32_t a2, uint32_t a3,
                                      uint32_t b0, uint32_t b1) {
    asm volatile(
        "mma.sync.aligned.m16n8k16.row.col.f32.f16.f16.f32 "
        "{%0,%1,%2,%3},{%4,%5,%6,%7},{%8,%9},{%0,%1,%2,%3};"
        : "+f"(c[0]), "+f"(c[1]), "+f"(c[2]), "+f"(c[3])
        : "r"(a0), "r"(a1), "r"(a2), "r"(a3), "r"(b0), "r"(b1));
}
__device__ __forceinline__ void ldsm4t(uint32_t& r0, uint32_t& r1,
                                       uint32_t& r2, uint32_t& r3, uint32_t addr) {
    asm volatile("ldmatrix.sync.aligned.m8n8.x4.trans.shared.b16 {%0,%1,%2,%3}, [%4];"
                 : "=r"(r0), "=r"(r1), "=r"(r2), "=r"(r3) : "r"(addr));
}
__device__ __forceinline__ uint32_t h2pack(float x, float y) {
    uint32_t u;
    asm("cvt.rn.f16x2.f32 %0, %1, %2;" : "=r"(u) : "f"(y), "f"(x));
    return u;
}
__device__ __forceinline__ void split2h(float x, float y, uint32_t& hi, uint32_t& lo) {
    uint32_t h = h2pack(x, y);
    __half2 hv = *reinterpret_cast<__half2*>(&h);
    float hx = __half2float(hv.x);
    float hy = __half2float(hv.y);
    hi = h;
    lo = h2pack(x - hx, y - hy);
}
__device__ __forceinline__ uint32_t sptr(const void* p) {
    return (uint32_t)__cvta_generic_to_shared(p);
}
__device__ __forceinline__ void cp16(uint32_t dst, const void* src) {
    asm volatile("cp.async.cg.shared.global [%0], [%1], 16;" :: "r"(dst), "l"(src));
}
__device__ __forceinline__ void cp_commit() {
    asm volatile("cp.async.commit_group;");
}
template<int N> __device__ __forceinline__ void cp_wait() {
    asm volatile("cp.async.wait_group %0;" :: "n"(N));
}

// ---------------------------------------------------------------------------
// Weight transpose: W[K,N] fp32 -> Wf[N,K] fp16
// ---------------------------------------------------------------------------
__global__ void wsplit_kernel(const float* __restrict__ W, int K, int N,
                              __half* __restrict__ Wf)
{
    __shared__ float tile[32][33];
    int n0 = blockIdx.x * 32, k0 = blockIdx.y * 32;
    int tx = threadIdx.x, ty = threadIdx.y;
#pragma unroll
    for (int i = 0; i < 32; i += 8)
        tile[ty + i][tx] = W[(size_t)(k0 + ty + i) * N + n0 + tx];
    __syncthreads();
#pragma unroll
    for (int i = 0; i < 32; i += 8) {
        int n = n0 + ty + i, k = k0 + tx;
        Wf[(size_t)n * K + k] = __float2half_rn(tile[tx][ty + i]);
    }
}

// x split: fp32 -> fp16 hi/lo
__global__ void asplit_kernel(const float4* __restrict__ X,
                              uint2* __restrict__ Xh, uint2* __restrict__ Xl, int n4)
{
    int i = blockIdx.x * blockDim.x + threadIdx.x;
    if (i >= n4) return;
    float4 v = X[i];
    uint32_t h0, l0, h1, l1;
    split2h(v.x, v.y, h0, l0);
    split2h(v.z, v.w, h1, l1);
    Xh[i] = make_uint2(h0, h1);
    Xl[i] = make_uint2(l0, l1);
}

// ---------------------------------------------------------------------------
// fp16 mma.sync GEMM, PASSES = 1 or 2:
//   PASSES=2: C = (Ah+Al)[M,K] @ B[N,K]^T + bias  (exact A, rounded B)
//   PASSES=1: C =  Ah    [M,K] @ B[N,K]^T + bias  (both rounded; used where
//             output is stored fp16 anyway -> residual ~ storage rounding)
// OUT: 0 = fp32 C, 1 = split fp16 (Ch/Cl), 2 = packed fp16 (H),
//      3 = packed fp16 with fused RoPE (rotary dim = RD)
// ---------------------------------------------------------------------------
template<int BN, int OUT, int RD, int PASSES>
__global__ __launch_bounds__(256, 2)
void gemm_f16(int N, int K,
              const __half* __restrict__ Agh,
              const __half* __restrict__ Agl, int lda,
              const __half* __restrict__ Bg,
              const float* __restrict__ bias, float oscale,
              float* __restrict__ C,
              __half* __restrict__ Ch,
              __half* __restrict__ Cl,
              __half* __restrict__ H)
{
    constexpr int BM   = 128;
    constexpr int WM   = BM / 4;
    constexpr int WN   = BN / 2;
    constexpr int MT   = WM / 16;
    constexpr int NT   = WN / 8;
    constexpr int STR  = 40;
    constexpr int ASL  = BM * STR;
    constexpr int BSL  = BN * STR;
    constexpr int STG  = PASSES * ASL + BSL;
    constexpr int NAC  = (BM * 4) / 256;
    constexpr int NBC  = (BN * 4) / 256;

    extern __shared__ __half smb[];

    const int tid  = threadIdx.x;
    const int lane = tid & 31;
    const int warp = tid >> 5;
    const int g    = lane >> 2;
    const int t    = lane & 3;
    const int wm   = warp >> 1;
    const int wn   = warp & 1;
    const int bRow = blockIdx.y * BM;
    const int bCol = blockIdx.x * BN;

    float acc[MT][NT][4];
#pragma unroll
    for (int mt = 0; mt < MT; mt++)
#pragma unroll
        for (int nt = 0; nt < NT; nt++)
#pragma unroll
            for (int i = 0; i < 4; i++) acc[mt][nt][i] = 0.f;

    auto issue = [&](int k0, int s) {
        __half* st = smb + s * STG;
#pragma unroll
        for (int i = 0; i < NAC; i++) {
            int idx = tid + i * 256;
            int r = idx >> 2, c = idx & 3;
            uint32_t d = sptr(st + r * STR + c * 8);
            cp16(d, Agh + (size_t)(bRow + r) * lda + k0 + c * 8);
            if (PASSES == 2)
                cp16(d + ASL * 2, Agl + (size_t)(bRow + r) * lda + k0 + c * 8);
        }
#pragma unroll
        for (int i = 0; i < NBC; i++) {
            int idx = tid + i * 256;
            int r = idx >> 2, c = idx & 3;
            cp16(sptr(st + PASSES * ASL + r * STR + c * 8),
                 Bg + (size_t)(bCol + r) * K + k0 + c * 8);
        }
        cp_commit();
    };

    const int iters = K / 32;
    issue(0, 0);

    for (int it = 0; it < iters; it++) {
        const int cur = it & 1;
        if (it + 1 < iters) { issue((it + 1) * 32, cur ^ 1); cp_wait<1>(); }
        else                { cp_wait<0>(); }
        __syncthreads();

        const __half* Ah = smb + cur * STG;
        const __half* Al = Ah + ASL;                  // valid only if PASSES==2
        const __half* Bs = Ah + PASSES * ASL;

#pragma unroll
        for (int s = 0; s < 2; s++) {
            const int kb = 16 * s + 2 * t;
            uint32_t ah[MT][4], al[MT][4];
#pragma unroll
            for (int mt = 0; mt < MT; mt++) {
                int r0 = wm * WM + mt * 16 + g;
                int r1 = r0 + 8;
                ah[mt][0] = *reinterpret_cast<const uint32_t*>(&Ah[r0 * STR + kb]);
                ah[mt][1] = *reinterpret_cast<const uint32_t*>(&Ah[r1 * STR + kb]);
                ah[mt][2] = *reinterpret_cast<const uint32_t*>(&Ah[r0 * STR + kb + 8]);
                ah[mt][3] = *reinterpret_cast<const uint32_t*>(&Ah[r1 * STR + kb + 8]);
                if (PASSES == 2) {
                    al[mt][0] = *reinterpret_cast<const uint32_t*>(&Al[r0 * STR + kb]);
                    al[mt][1] = *reinterpret_cast<const uint32_t*>(&Al[r1 * STR + kb]);
                    al[mt][2] = *reinterpret_cast<const uint32_t*>(&Al[r0 * STR + kb + 8]);
                    al[mt][3] = *reinterpret_cast<const uint32_t*>(&Al[r1 * STR + kb + 8]);
                }
            }
#pragma unroll
            for (int nt = 0; nt < NT; nt++) {
                int nb = wn * WN + nt * 8 + g;
                uint32_t b0 = *reinterpret_cast<const uint32_t*>(&Bs[nb * STR + kb]);
                uint32_t b1 = *reinterpret_cast<const uint32_t*>(&Bs[nb * STR + kb + 8]);
#pragma unroll
                for (int mt = 0; mt < MT; mt++) {
                    mmah(acc[mt][nt], ah[mt], b0, b1);
                    if (PASSES == 2) mmah(acc[mt][nt], al[mt], b0, b1);
                }
            }
        }
        __syncthreads();
    }

#pragma unroll
    for (int mt = 0; mt < MT; mt++) {
        int r0 = bRow + wm * WM + mt * 16 + g;
#pragma unroll
        for (int nt = 0; nt < NT; nt++) {
            int col = bCol + wn * WN + nt * 8 + 2 * t;
            float bx = bias[col], by = bias[col + 1];
            float v00 = (acc[mt][nt][0] + bx) * oscale, v01 = (acc[mt][nt][1] + by) * oscale;
            float v10 = (acc[mt][nt][2] + bx) * oscale, v11 = (acc[mt][nt][3] + by) * oscale;
            if (OUT == 0) {
                float2 a = {v00, v01}, b = {v10, v11};
                *reinterpret_cast<float2*>(C + (size_t)r0 * N + col)       = a;
                *reinterpret_cast<float2*>(C + (size_t)(r0 + 8) * N + col) = b;
            } else if (OUT == 1) {
                uint32_t h0, l0, h1, l1;
                split2h(v00, v01, h0, l0);
                split2h(v10, v11, h1, l1);
                *reinterpret_cast<uint32_t*>(&Ch[(size_t)r0 * N + col])       = h0;
                *reinterpret_cast<uint32_t*>(&Cl[(size_t)r0 * N + col])       = l0;
                *reinterpret_cast<uint32_t*>(&Ch[(size_t)(r0 + 8) * N + col]) = h1;
                *reinterpret_cast<uint32_t*>(&Cl[(size_t)(r0 + 8) * N + col]) = l1;
            } else if (OUT == 2) {
                *reinterpret_cast<uint32_t*>(&H[(size_t)r0 * N + col])       = h2pack(v00, v01);
                *reinterpret_cast<uint32_t*>(&H[(size_t)(r0 + 8) * N + col]) = h2pack(v10, v11);
            } else {
                // fused RoPE (rotary dim RD); (col, col+1) is a rope pair
                float th = expf(-2.0f * (float)(col >> 1) / (float)RD * 9.2103403719761836f);
                int tt0 = r0 & (TT - 1);
                float sn0, cs0, sn1, cs1;
                sincosf((float)(tt0 + 1) * th, &sn0, &cs0);
                sincosf((float)(tt0 + 9) * th, &sn1, &cs1);
                float e0 = v00 * cs0 - v01 * sn0;
                float o0 = v01 * cs0 + v00 * sn0;
                float e1 = v10 * cs1 - v11 * sn1;
                float o1 = v11 * cs1 + v10 * sn1;
                *reinterpret_cast<uint32_t*>(&H[(size_t)r0 * N + col])       = h2pack(e0, o0);
                *reinterpret_cast<uint32_t*>(&H[(size_t)(r0 + 8) * N + col]) = h2pack(e1, o1);
            }
        }
    }
}

// ---------------------------------------------------------------------------
// Causal flash attention, fp16 mma.sync m16n8k16, 2 CTAs/SM. (R12 form)
// ---------------------------------------------------------------------------
#define QSTH 136
#define KSTH 136
#define VSTH 72
#define PSTH 72

#define OFFH_K (128 * QSTH)
#define OFFH_V (OFFH_K + 2 * 64 * KSTH)
#define OFFH_P (OFFH_V + 2 * 64 * VSTH)
#define ATT_HALFS (OFFH_P + 128 * PSTH)     // 53248 halfs = 106496 B

__global__ __launch_bounds__(256, 2)
void attn_fp16_kernel()
{
    extern __shared__ __half smh[];
    __half* Qh = smh;
    __half* Ph = smh + OFFH_P;

    const int tid  = threadIdx.x;
    const int lane = tid & 31;
    const int warp = tid >> 5;
    const int g    = lane >> 2;
    const int t    = lane & 3;
    const int qt   = (gridDim.x - 1) - blockIdx.x;
    const int hh   = blockIdx.y;
    const int b    = blockIdx.z;
    const int rowBase = b * TT + qt * 128;

    auto issueKV = [&](int j, int s) {
        __half* Kt = smh + OFFH_K + s * 64 * KSTH;
        __half* Vt = smh + OFFH_V + s * 64 * VSTH;
        const int kbase = b * TT + j * 64;
#pragma unroll
        for (int i = 0; i < 4; i++) {
            int idx = tid + i * 256;
            int r = idx >> 4, c = idx & 15;
            uint32_t d = sptr(Kt + r * KSTH + c * 8);
            if (c < 8) cp16(d, g_kvh + (size_t)(kbase + r) * 2048 + hh * 64 + c * 8);
            else       cp16(d, g_krh + (size_t)(kbase + r) * 64 + (c - 8) * 8);
        }
#pragma unroll
        for (int i = 0; i < 2; i++) {
            int idx = tid + i * 256;
            int r = idx >> 3, c = idx & 7;
            cp16(sptr(Vt + r * VSTH + c * 8),
                 g_kvh + (size_t)(kbase + r) * 2048 + 1024 + hh * 64 + c * 8);
        }
        cp_commit();
    };

#pragma unroll
    for (int i = 0; i < 8; i++) {
        int idx = tid + i * 256;
        int r = idx >> 4, c = idx & 15;
        uint32_t d = sptr(Qh + r * QSTH + c * 8);
        if (c < 8) cp16(d, g_qh  + (size_t)(rowBase + r) * 1024 + hh * 64 + c * 8);
        else       cp16(d, g_qrh + (size_t)(rowBase + r) * 1024 + hh * 64 + (c - 8) * 8);
    }
    issueKV(0, 0);

    const int vrow = (lane & 7) + ((lane >> 3) & 1) * 8;
    const int vcol = (lane >> 4) * 8;
    const uint32_t vLaneByte = (uint32_t)(vrow * VSTH + vcol) * 2;

    const int rloc0 = warp * 16 + g;
    float m0 = -1e30f, m1 = -1e30f, l0 = 0.f, l1 = 0.f;
    float o[8][4];
#pragma unroll
    for (int nt = 0; nt < 8; nt++)
#pragma unroll
        for (int i = 0; i < 4; i++) o[nt][i] = 0.f;

    const int nkt = 2 * qt + 2;
    for (int j = 0; j < nkt; j++) {
        const int s = j & 1;
        if (j + 1 < nkt) { issueKV(j + 1, s ^ 1); cp_wait<1>(); }
        else             { cp_wait<0>(); }
        __syncthreads();

        const __half* Kt = smh + OFFH_K + s * 64 * KSTH;
        const uint32_t vBuf = sptr(smh + OFFH_V + s * 64 * VSTH);

        float sc[8][4];
#pragma unroll
        for (int nt = 0; nt < 8; nt++)
#pragma unroll
            for (int i = 0; i < 4; i++) sc[nt][i] = 0.f;

#pragma unroll
        for (int ks = 0; ks < 8; ks++) {
            const int kb = ks * 16 + 2 * t;
            uint32_t a0 = *reinterpret_cast<const uint32_t*>(&Qh[(rloc0)     * QSTH + kb]);
            uint32_t a1 = *reinterpret_cast<const uint32_t*>(&Qh[(rloc0 + 8) * QSTH + kb]);
            uint32_t a2 = *reinterpret_cast<const uint32_t*>(&Qh[(rloc0)     * QSTH + kb + 8]);
            uint32_t a3 = *reinterpret_cast<const uint32_t*>(&Qh[(rloc0 + 8) * QSTH + kb + 8]);
#pragma unroll
            for (int nt = 0; nt < 8; nt++) {
                uint32_t b0 = *reinterpret_cast<const uint32_t*>(&Kt[(nt * 8 + g) * KSTH + kb]);
                uint32_t b1 = *reinterpret_cast<const uint32_t*>(&Kt[(nt * 8 + g) * KSTH + kb + 8]);
                mmah4(sc[nt], a0, a1, a2, a3, b0, b1);
            }
        }

        if (j >= 2 * qt) {
            int rg0 = qt * 128 + rloc0;
            int k0 = j * 64;
#pragma unroll
            for (int nt = 0; nt < 8; nt++) {
                int cg = k0 + nt * 8 + 2 * t;
                if (cg     > rg0)     sc[nt][0] = -1e30f;
                if (cg + 1 > rg0)     sc[nt][1] = -1e30f;
                if (cg     > rg0 + 8) sc[nt][2] = -1e30f;
                if (cg + 1 > rg0 + 8) sc[nt][3] = -1e30f;
            }
        }

        float mx0 = -1e30f, mx1 = -1e30f;
#pragma unroll
        for (int nt = 0; nt < 8; nt++) {
            mx0 = fmaxf(mx0, fmaxf(sc[nt][0], sc[nt][1]));
            mx1 = fmaxf(mx1, fmaxf(sc[nt][2], sc[nt][3]));
        }
        mx0 = fmaxf(mx0, __shfl_xor_sync(0xffffffffu, mx0, 1));
        mx0 = fmaxf(mx0, __shfl_xor_sync(0xffffffffu, mx0, 2));
        mx1 = fmaxf(mx1, __shfl_xor_sync(0xffffffffu, mx1, 1));
        mx1 = fmaxf(mx1, __shfl_xor_sync(0xffffffffu, mx1, 2));

        float mn0 = fmaxf(m0, mx0), mn1 = fmaxf(m1, mx1);
        float al0 = __expf(m0 - mn0), al1 = __expf(m1 - mn1);
        m0 = mn0; m1 = mn1;

        float sum0 = 0.f, sum1 = 0.f;
#pragma unroll
        for (int nt = 0; nt < 8; nt++) {
            float p0 = __expf(sc[nt][0] - mn0);
            float p1 = __expf(sc[nt][1] - mn0);
            float p2 = __expf(sc[nt][2] - mn1);
            float p3 = __expf(sc[nt][3] - mn1);
            sum0 += p0 + p1; sum1 += p2 + p3;
            *reinterpret_cast<uint32_t*>(&Ph[(rloc0)     * PSTH + nt * 8 + 2 * t]) = h2pack(p0, p1);
            *reinterpret_cast<uint32_t*>(&Ph[(rloc0 + 8) * PSTH + nt * 8 + 2 * t]) = h2pack(p2, p3);
        }
        sum0 += __shfl_xor_sync(0xffffffffu, sum0, 1);
        sum0 += __shfl_xor_sync(0xffffffffu, sum0, 2);
        sum1 += __shfl_xor_sync(0xffffffffu, sum1, 1);
        sum1 += __shfl_xor_sync(0xffffffffu, sum1, 2);
        l0 = l0 * al0 + sum0;
        l1 = l1 * al1 + sum1;

#pragma unroll
        for (int nt = 0; nt < 8; nt++) {
            o[nt][0] *= al0; o[nt][1] *= al0;
            o[nt][2] *= al1; o[nt][3] *= al1;
        }
        __syncwarp();

#pragma unroll
        for (int ks = 0; ks < 4; ks++) {
            const int kb = ks * 16 + 2 * t;
            uint32_t a0 = *reinterpret_cast<const uint32_t*>(&Ph[(rloc0)     * PSTH + kb]);
            uint32_t a1 = *reinterpret_cast<const uint32_t*>(&Ph[(rloc0 + 8) * PSTH + kb]);
            uint32_t a2 = *reinterpret_cast<const uint32_t*>(&Ph[(rloc0)     * PSTH + kb + 8]);
            uint32_t a3 = *reinterpret_cast<const uint32_t*>(&Ph[(rloc0 + 8) * PSTH + kb + 8]);
#pragma unroll
            for (int ntp = 0; ntp < 4; ntp++) {
                uint32_t b0, b1, b2, b3;
                ldsm4t(b0, b1, b2, b3,
                       vBuf + vLaneByte + (uint32_t)(ks * 16 * VSTH + ntp * 16) * 2);
                mmah4(o[2*ntp],     a0, a1, a2, a3, b0, b1);
                mmah4(o[2*ntp + 1], a0, a1, a2, a3, b2, b3);
            }
        }
        __syncthreads();
    }

    float inv0 = 1.0f / l0, inv1 = 1.0f / l1;
    int rg = rowBase + rloc0;
#pragma unroll
    for (int nt = 0; nt < 8; nt++) {
        int col = hh * 64 + nt * 8 + 2 * t;
        uint32_t h0, l0u, h1, l1u;
        split2h(o[nt][0] * inv0, o[nt][1] * inv0, h0, l0u);
        split2h(o[nt][2] * inv1, o[nt][3] * inv1, h1, l1u);
        *reinterpret_cast<uint32_t*>(&g_ath[(size_t)rg       * 1024 + col]) = h0;
        *reinterpret_cast<uint32_t*>(&g_atl[(size_t)rg       * 1024 + col]) = l0u;
        *reinterpret_cast<uint32_t*>(&g_ath[(size_t)(rg + 8) * 1024 + col]) = h1;
        *reinterpret_cast<uint32_t*>(&g_atl[(size_t)(rg + 8) * 1024 + col]) = l1u;
    }
}

// ---------------------------------------------------------------------------
// Launch — R10/R12 topology (known-good graph shape).
// ---------------------------------------------------------------------------
extern "C" void kernel_launch(void* const* d_in, const int* in_sizes, int n_in,
                              void* d_out, int out_size)
{
    (void)in_sizes; (void)n_in; (void)out_size;
    const float* x   = (const float*)d_in[0];
    const float* w1  = (const float*)d_in[1];
    const float* b1  = (const float*)d_in[2];
    const float* wkr = (const float*)d_in[3];
    const float* bkr = (const float*)d_in[4];
    const float* wqr = (const float*)d_in[5];
    const float* bqr = (const float*)d_in[6];
    const float* wkv = (const float*)d_in[7];
    const float* bkv = (const float*)d_in[8];
    const float* wq  = (const float*)d_in[9];
    const float* bq  = (const float*)d_in[10];
    const float* wo  = (const float*)d_in[11];
    const float* bo  = (const float*)d_in[12];
    float* out = (float*)d_out;
    const float scale = 0.08838834764831845f;   // 128^-0.5

    __half *qh_, *qrh_, *krh_, *kvh_;
    __half *xh_, *xl_, *hh_, *hl_, *ath_, *atl_;
    __half *w1f_, *wkrf_, *wqrf_, *wkvf_, *wqf_, *wof_;
    cudaGetSymbolAddress((void**)&qh_,  g_qh);
    cudaGetSymbolAddress((void**)&qrh_, g_qrh);
    cudaGetSymbolAddress((void**)&krh_, g_krh);
    cudaGetSymbolAddress((void**)&kvh_, g_kvh);
    cudaGetSymbolAddress((void**)&xh_,  g_xh);  cudaGetSymbolAddress((void**)&xl_,  g_xl);
    cudaGetSymbolAddress((void**)&hh_,  g_hh);  cudaGetSymbolAddress((void**)&hl_,  g_hl);
    cudaGetSymbolAddress((void**)&ath_, g_ath); cudaGetSymbolAddress((void**)&atl_, g_atl);
    cudaGetSymbolAddress((void**)&w1f_,  g_w1f);
    cudaGetSymbolAddress((void**)&wkrf_, g_wkrf);
    cudaGetSymbolAddress((void**)&wqrf_, g_wqrf);
    cudaGetSymbolAddress((void**)&wkvf_, g_wkvf);
    cudaGetSymbolAddress((void**)&wqf_,  g_wqf);
    cudaGetSymbolAddress((void**)&wof_,  g_wof);

    const int SMG2_128 = 2 * (2 * 128 * 40 + 128 * 40) * 2;   // 61440 (2-pass)
    const int SMG1_128 = 2 * (128 * 40 + 128 * 40) * 2;       // 40960 (1-pass)
    const int SMG1_64  = 2 * (128 * 40 + 64 * 40) * 2;        // 30720
    const int SMAT     = ATT_HALFS * 2;                        // 106496
    cudaFuncSetAttribute(gemm_f16<128, 0, 0, 2>,    cudaFuncAttributeMaxDynamicSharedMemorySize, SMG2_128);
    cudaFuncSetAttribute(gemm_f16<128, 1, 0, 2>,    cudaFuncAttributeMaxDynamicSharedMemorySize, SMG2_128);
    cudaFuncSetAttribute(gemm_f16<128, 2, 0, 1>,    cudaFuncAttributeMaxDynamicSharedMemorySize, SMG1_128);
    cudaFuncSetAttribute(gemm_f16<128, 3, 1024, 1>, cudaFuncAttributeMaxDynamicSharedMemorySize, SMG1_128);
    cudaFuncSetAttribute(gemm_f16<64,  3, 64, 1>,   cudaFuncAttributeMaxDynamicSharedMemorySize, SMG1_64);
    cudaFuncSetAttribute(attn_fp16_kernel, cudaFuncAttributeMaxDynamicSharedMemorySize, SMAT);

    static cudaStream_t s1 = nullptr, s2 = nullptr, s3 = nullptr;
    static cudaEvent_t evFork, evX, evH, evD1, evD2, evD3;
    if (s1 == nullptr) {
        cudaStreamCreateWithFlags(&s1, cudaStreamNonBlocking);
        cudaStreamCreateWithFlags(&s2, cudaStreamNonBlocking);
        cudaStreamCreateWithFlags(&s3, cudaStreamNonBlocking);
        cudaEventCreateWithFlags(&evFork, cudaEventDisableTiming);
        cudaEventCreateWithFlags(&evX,    cudaEventDisableTiming);
        cudaEventCreateWithFlags(&evH,    cudaEventDisableTiming);
        cudaEventCreateWithFlags(&evD1,   cudaEventDisableTiming);
        cudaEventCreateWithFlags(&evD2,   cudaEventDisableTiming);
        cudaEventCreateWithFlags(&evD3,   cudaEventDisableTiming);
    }

    dim3 wsb(32, 8);

    // fork
    cudaEventRecord(evFork, 0);
    cudaStreamWaitEvent(s1, evFork, 0);
    cudaStreamWaitEvent(s2, evFork, 0);
    cudaStreamWaitEvent(s3, evFork, 0);

    // main: w1 transpose; s1: x split (feeds h GEMM)
    wsplit_kernel<<<dim3(1024/32, 1024/32), wsb, 0, 0>>>(w1, 1024, 1024, w1f_);
    asplit_kernel<<<(MR * 1024 / 4 + 255) / 256, 256, 0, s1>>>(
        (const float4*)x, (uint2*)xh_, (uint2*)xl_, MR * 1024 / 4);
    cudaEventRecord(evX, s1);

    // other weight transposes overlap h GEMM
    wsplit_kernel<<<dim3(1024/32, 1024/32), wsb, 0, s1>>>(wqr, 1024, 1024, wqrf_);
    wsplit_kernel<<<dim3(2048/32, 512/32),  wsb, 0, s2>>>(wkv, 512,  2048, wkvf_);
    wsplit_kernel<<<dim3(1024/32, 512/32),  wsb, 0, s3>>>(wq,  512,  1024, wqf_);
    wsplit_kernel<<<dim3(64/32,   1024/32), wsb, 0, s3>>>(wkr, 1024, 64,   wkrf_);
    wsplit_kernel<<<dim3(1024/32, 1024/32), wsb, 0, s3>>>(wo,  1024, 1024, wof_);

    // 1) h = x @ w1 + b1 -> split fp16 (main stream, 2-pass)
    cudaStreamWaitEvent(0, evX, 0);
    gemm_f16<128, 1, 0, 2><<<dim3(8, 32), 256, SMG2_128, 0>>>(
        1024, 1024, xh_, xl_, 1024, w1f_, b1, 1.f, nullptr, hh_, hl_, nullptr);
    cudaEventRecord(evH, 0);

    // 3) qr = rope((h @ wqr + bqr) * scale) -> fp16   (s1, 1-pass)
    cudaStreamWaitEvent(s1, evH, 0);
    gemm_f16<128, 3, 1024, 1><<<dim3(8, 32), 256, SMG1_128, s1>>>(
        1024, 1024, hh_, hh_, 1024, wqrf_, bqr, scale, nullptr, nullptr, nullptr, qrh_);
    cudaEventRecord(evD1, s1);

    // 4) kv = cKV @ wkv + bkv -> fp16                 (s2, 1-pass)
    cudaStreamWaitEvent(s2, evH, 0);
    gemm_f16<128, 2, 0, 1><<<dim3(16, 32), 256, SMG1_128, s2>>>(
        2048, 512, hh_, hh_, 1024, wkvf_, bkv, 1.f, nullptr, nullptr, nullptr, kvh_);
    cudaEventRecord(evD2, s2);

    // 5) q = (cq @ wq + bq) * scale -> fp16 ; 2) kr = rope(h @ wkr + bkr) -> fp16   (s3, 1-pass)
    cudaStreamWaitEvent(s3, evH, 0);
    gemm_f16<128, 2, 0, 1><<<dim3(8, 32), 256, SMG1_128, s3>>>(
        1024, 512, hh_ + 512, hh_ + 512, 1024, wqf_, bq, scale, nullptr, nullptr, nullptr, qh_);
    gemm_f16<64, 3, 64, 1><<<dim3(1, 32), 256, SMG1_64, s3>>>(
        64, 1024, hh_, hh_, 1024, wkrf_, bkr, 1.f, nullptr, nullptr, nullptr, krh_);
    cudaEventRecord(evD3, s3);

    // join -> attention -> wo (main stream)
    cudaStreamWaitEvent(0, evD1, 0);
    cudaStreamWaitEvent(0, evD2, 0);
    cudaStreamWaitEvent(0, evD3, 0);

    attn_fp16_kernel<<<dim3(16, NH, BB), 256, SMAT, 0>>>();

    gemm_f16<128, 0, 0, 2><<<dim3(8, 32), 256, SMG2_128, 0>>>(
        1024, 1024, ath_, atl_, 1024, wof_, bo, 1.f, out, nullptr, nullptr, nullptr);
}

// round 14
// speedup vs baseline: 2.1976x; 1.1186x over previous
#include <cuda_runtime.h>
#include <cuda_bf16.h>
#include <cuda_fp16.h>
#include <math.h>
#include <stdint.h>

// Problem constants
#define BB   2
#define TT   2048
#define CC   1024
#define NH   16
#define LAT  512
#define DHR  64
#define MR   (BB*TT)        // 4096 rows

// ---------------------------------------------------------------------------
// Scratch (static device globals)
// ---------------------------------------------------------------------------
__device__ __half g_qh [MR * 1024];
__device__ __half g_qrh[MR * 1024];
__device__ __half g_krh[MR * 64];
__device__ __half g_kvh[MR * 2048];   // k cols 0..1023, v cols 1024..2047
__device__ __half g_ath[MR * 1024];   // attention out (fp16)

// fp16 hi/lo split pairs (x ~= hi + lo, residual ~2^-22)
__device__ __half g_xh[MR*1024],  g_xl[MR*1024];
__device__ __half g_hh[MR*1024],  g_hl[MR*1024];
// transposed weights [N,K], single fp16
__device__ __half g_w1f [1024*1024];
__device__ __half g_wkrf[64*1024];
__device__ __half g_wqrf[1024*1024];
__device__ __half g_wkvf[2048*512];
__device__ __half g_wqf [1024*512];
__device__ __half g_wof [1024*1024];

// ---------------------------------------------------------------------------
// helpers
// ---------------------------------------------------------------------------
__device__ __forceinline__ void mmah(float* c, const uint32_t* a,
                                     uint32_t b0, uint32_t b1) {
    asm volatile(
        "mma.sync.aligned.m16n8k16.row.col.f32.f16.f16.f32 "
        "{%0,%1,%2,%3},{%4,%5,%6,%7},{%8,%9},{%0,%1,%2,%3};"
        : "+f"(c[0]), "+f"(c[1]), "+f"(c[2]), "+f"(c[3])
        : "r"(a[0]), "r"(a[1]), "r"(a[2]), "r"(a[3]), "r"(b0), "r"(b1));
}
__device__ __forceinline__ void mmah4(float* c,
                                      uint32_t a0, uint32_t a1, uint32_t a2, uint32_t a3,
                                      uint32_t b0, uint32_t b1) {
    asm volatile(
        "mma.sync.aligned.m16n8k16.row.col.f32.f16.f16.f32 "
        "{%0,%1,%2,%3},{%4,%5,%6,%7},{%8,%9},{%0,%1,%2,%3};"
        : "+f"(c[0]), "+f"(c[1]), "+f"(c[2]), "+f"(c[3])
        : "r"(a0), "r"(a1), "r"(a2), "r"(a3), "r"(b0), "r"(b1));
}
__device__ __forceinline__ void ldsm4t(uint32_t& r0, uint32_t& r1,
                                       uint32_t& r2, uint32_t& r3, uint32_t addr) {
    asm volatile("ldmatrix.sync.aligned.m8n8.x4.trans.shared.b16 {%0,%1,%2,%3}, [%4];"
                 : "=r"(r0), "=r"(r1), "=r"(r2), "=r"(r3) : "r"(addr));
}
__device__ __forceinline__ uint32_t h2pack(float x, float y) {
    uint32_t u;
    asm("cvt.rn.f16x2.f32 %0, %1, %2;" : "=r"(u) : "f"(y), "f"(x));
    return u;
}
__device__ __forceinline__ void split2h(float x, float y, uint32_t& hi, uint32_t& lo) {
    uint32_t h = h2pack(x, y);
    __half2 hv = *reinterpret_cast<__half2*>(&h);
    float hx = __half2float(hv.x);
    float hy = __half2float(hv.y);
    hi = h;
    lo = h2pack(x - hx, y - hy);
}
__device__ __forceinline__ uint32_t sptr(const void* p) {
    return (uint32_t)__cvta_generic_to_shared(p);
}
__device__ __forceinline__ void cp16(uint32_t dst, const void* src) {
    asm volatile("cp.async.cg.shared.global [%0], [%1], 16;" :: "r"(dst), "l"(src));
}
__device__ __forceinline__ void cp_commit() {
    asm volatile("cp.async.commit_group;");
}
template<int N> __device__ __forceinline__ void cp_wait() {
    asm volatile("cp.async.wait_group %0;" :: "n"(N));
}

// ---------------------------------------------------------------------------
// Weight transpose: W[K,N] fp32 -> Wf[N,K] fp16
// ---------------------------------------------------------------------------
__global__ void wsplit_kernel(const float* __restrict__ W, int K, int N,
                              __half* __restrict__ Wf)
{
    __shared__ float tile[32][33];
    int n0 = blockIdx.x * 32, k0 = blockIdx.y * 32;
    int tx = threadIdx.x, ty = threadIdx.y;
#pragma unroll
    for (int i = 0; i < 32; i += 8)
        tile[ty + i][tx] = W[(size_t)(k0 + ty + i) * N + n0 + tx];
    __syncthreads();
#pragma unroll
    for (int i = 0; i < 32; i += 8) {
        int n = n0 + ty + i, k = k0 + tx;
        Wf[(size_t)n * K + k] = __float2half_rn(tile[tx][ty + i]);
    }
}

__global__ void asplit_kernel(const float4* __restrict__ X,
                              uint2* __restrict__ Xh, uint2* __restrict__ Xl, int n4)
{
    int i = blockIdx.x * blockDim.x + threadIdx.x;
    if (i >= n4) return;
    float4 v = X[i];
    uint32_t h0, l0, h1, l1;
    split2h(v.x, v.y, h0, l0);
    split2h(v.z, v.w, h1, l1);
    Xh[i] = make_uint2(h0, h1);
    Xl[i] = make_uint2(l0, l1);
}

// ---------------------------------------------------------------------------
// fp16 mma.sync GEMM, PASSES = 1 or 2. (R13 form)
// OUT: 0 = fp32 C, 1 = split fp16 (Ch/Cl), 2 = packed fp16 (H),
//      3 = packed fp16 with fused RoPE (rotary dim = RD)
// ---------------------------------------------------------------------------
template<int BN, int OUT, int RD, int PASSES>
__global__ __launch_bounds__(256, 2)
void gemm_f16(int N, int K,
              const __half* __restrict__ Agh,
              const __half* __restrict__ Agl, int lda,
              const __half* __restrict__ Bg,
              const float* __restrict__ bias, float oscale,
              float* __restrict__ C,
              __half* __restrict__ Ch,
              __half* __restrict__ Cl,
              __half* __restrict__ H)
{
    constexpr int BM   = 128;
    constexpr int WM   = BM / 4;
    constexpr int WN   = BN / 2;
    constexpr int MT   = WM / 16;
    constexpr int NT   = WN / 8;
    constexpr int STR  = 40;
    constexpr int ASL  = BM * STR;
    constexpr int BSL  = BN * STR;
    constexpr int STG  = PASSES * ASL + BSL;
    constexpr int NAC  = (BM * 4) / 256;
    constexpr int NBC  = (BN * 4) / 256;

    extern __shared__ __half smb[];

    const int tid  = threadIdx.x;
    const int lane = tid & 31;
    const int warp = tid >> 5;
    const int g    = lane >> 2;
    const int t    = lane & 3;
    const int wm   = warp >> 1;
    const int wn   = warp & 1;
    const int bRow = blockIdx.y * BM;
    const int bCol = blockIdx.x * BN;

    float acc[MT][NT][4];
#pragma unroll
    for (int mt = 0; mt < MT; mt++)
#pragma unroll
        for (int nt = 0; nt < NT; nt++)
#pragma unroll
            for (int i = 0; i < 4; i++) acc[mt][nt][i] = 0.f;

    auto issue = [&](int k0, int s) {
        __half* st = smb + s * STG;
#pragma unroll
        for (int i = 0; i < NAC; i++) {
            int idx = tid + i * 256;
            int r = idx >> 2, c = idx & 3;
            uint32_t d = sptr(st + r * STR + c * 8);
            cp16(d, Agh + (size_t)(bRow + r) * lda + k0 + c * 8);
            if (PASSES == 2)
                cp16(d + ASL * 2, Agl + (size_t)(bRow + r) * lda + k0 + c * 8);
        }
#pragma unroll
        for (int i = 0; i < NBC; i++) {
            int idx = tid + i * 256;
            int r = idx >> 2, c = idx & 3;
            cp16(sptr(st + PASSES * ASL + r * STR + c * 8),
                 Bg + (size_t)(bCol + r) * K + k0 + c * 8);
        }
        cp_commit();
    };

    const int iters = K / 32;
    issue(0, 0);

    for (int it = 0; it < iters; it++) {
        const int cur = it & 1;
        if (it + 1 < iters) { issue((it + 1) * 32, cur ^ 1); cp_wait<1>(); }
        else                { cp_wait<0>(); }
        __syncthreads();

        const __half* Ah = smb + cur * STG;
        const __half* Al = Ah + ASL;
        const __half* Bs = Ah + PASSES * ASL;

#pragma unroll
        for (int s = 0; s < 2; s++) {
            const int kb = 16 * s + 2 * t;
            uint32_t ah[MT][4], al[MT][4];
#pragma unroll
            for (int mt = 0; mt < MT; mt++) {
                int r0 = wm * WM + mt * 16 + g;
                int r1 = r0 + 8;
                ah[mt][0] = *reinterpret_cast<const uint32_t*>(&Ah[r0 * STR + kb]);
                ah[mt][1] = *reinterpret_cast<const uint32_t*>(&Ah[r1 * STR + kb]);
                ah[mt][2] = *reinterpret_cast<const uint32_t*>(&Ah[r0 * STR + kb + 8]);
                ah[mt][3] = *reinterpret_cast<const uint32_t*>(&Ah[r1 * STR + kb + 8]);
                if (PASSES == 2) {
                    al[mt][0] = *reinterpret_cast<const uint32_t*>(&Al[r0 * STR + kb]);
                    al[mt][1] = *reinterpret_cast<const uint32_t*>(&Al[r1 * STR + kb]);
                    al[mt][2] = *reinterpret_cast<const uint32_t*>(&Al[r0 * STR + kb + 8]);
                    al[mt][3] = *reinterpret_cast<const uint32_t*>(&Al[r1 * STR + kb + 8]);
                }
            }
#pragma unroll
            for (int nt = 0; nt < NT; nt++) {
                int nb = wn * WN + nt * 8 + g;
                uint32_t b0 = *reinterpret_cast<const uint32_t*>(&Bs[nb * STR + kb]);
                uint32_t b1 = *reinterpret_cast<const uint32_t*>(&Bs[nb * STR + kb + 8]);
#pragma unroll
                for (int mt = 0; mt < MT; mt++) {
                    mmah(acc[mt][nt], ah[mt], b0, b1);
                    if (PASSES == 2) mmah(acc[mt][nt], al[mt], b0, b1);
                }
            }
        }
        __syncthreads();
    }

#pragma unroll
    for (int mt = 0; mt < MT; mt++) {
        int r0 = bRow + wm * WM + mt * 16 + g;
#pragma unroll
        for (int nt = 0; nt < NT; nt++) {
            int col = bCol + wn * WN + nt * 8 + 2 * t;
            float bx = bias[col], by = bias[col + 1];
            float v00 = (acc[mt][nt][0] + bx) * oscale, v01 = (acc[mt][nt][1] + by) * oscale;
            float v10 = (acc[mt][nt][2] + bx) * oscale, v11 = (acc[mt][nt][3] + by) * oscale;
            if (OUT == 0) {
                float2 a = {v00, v01}, b = {v10, v11};
                *reinterpret_cast<float2*>(C + (size_t)r0 * N + col)       = a;
                *reinterpret_cast<float2*>(C + (size_t)(r0 + 8) * N + col) = b;
            } else if (OUT == 1) {
                uint32_t h0, l0, h1, l1;
                split2h(v00, v01, h0, l0);
                split2h(v10, v11, h1, l1);
                *reinterpret_cast<uint32_t*>(&Ch[(size_t)r0 * N + col])       = h0;
                *reinterpret_cast<uint32_t*>(&Cl[(size_t)r0 * N + col])       = l0;
                *reinterpret_cast<uint32_t*>(&Ch[(size_t)(r0 + 8) * N + col]) = h1;
                *reinterpret_cast<uint32_t*>(&Cl[(size_t)(r0 + 8) * N + col]) = l1;
            } else if (OUT == 2) {
                *reinterpret_cast<uint32_t*>(&H[(size_t)r0 * N + col])       = h2pack(v00, v01);
                *reinterpret_cast<uint32_t*>(&H[(size_t)(r0 + 8) * N + col]) = h2pack(v10, v11);
            } else {
                float th = expf(-2.0f * (float)(col >> 1) / (float)RD * 9.2103403719761836f);
                int tt0 = r0 & (TT - 1);
                float sn0, cs0, sn1, cs1;
                sincosf((float)(tt0 + 1) * th, &sn0, &cs0);
                sincosf((float)(tt0 + 9) * th, &sn1, &cs1);
                float e0 = v00 * cs0 - v01 * sn0;
                float o0 = v01 * cs0 + v00 * sn0;
                float e1 = v10 * cs1 - v11 * sn1;
                float o1 = v11 * cs1 + v10 * sn1;
                *reinterpret_cast<uint32_t*>(&H[(size_t)r0 * N + col])       = h2pack(e0, o0);
                *reinterpret_cast<uint32_t*>(&H[(size_t)(r0 + 8) * N + col]) = h2pack(e1, o1);
            }
        }
    }
}

// ---------------------------------------------------------------------------
// Causal flash attention, fp16 mma.sync m16n8k16.
// P kept in registers (QK C-fragment == PV A-fragment layout) — no smem P.
// ---------------------------------------------------------------------------
#define QSTH 136
#define KSTH 136
#define VSTH 72

#define OFFH_K (128 * QSTH)
#define OFFH_V (OFFH_K + 2 * 64 * KSTH)
#define ATT_HALFS (OFFH_V + 2 * 64 * VSTH)   // 44032 halfs = 88064 B

__global__ __launch_bounds__(256, 2)
void attn_fp16_kernel()
{
    extern __shared__ __half smh[];
    __half* Qh = smh;

    const int tid  = threadIdx.x;
    const int lane = tid & 31;
    const int warp = tid >> 5;
    const int g    = lane >> 2;
    const int t    = lane & 3;
    const int qt   = (gridDim.x - 1) - blockIdx.x;
    const int hh   = blockIdx.y;
    const int b    = blockIdx.z;
    const int rowBase = b * TT + qt * 128;

    auto issueKV = [&](int j, int s) {
        __half* Kt = smh + OFFH_K + s * 64 * KSTH;
        __half* Vt = smh + OFFH_V + s * 64 * VSTH;
        const int kbase = b * TT + j * 64;
#pragma unroll
        for (int i = 0; i < 4; i++) {
            int idx = tid + i * 256;
            int r = idx >> 4, c = idx & 15;
            uint32_t d = sptr(Kt + r * KSTH + c * 8);
            if (c < 8) cp16(d, g_kvh + (size_t)(kbase + r) * 2048 + hh * 64 + c * 8);
            else       cp16(d, g_krh + (size_t)(kbase + r) * 64 + (c - 8) * 8);
        }
#pragma unroll
        for (int i = 0; i < 2; i++) {
            int idx = tid + i * 256;
            int r = idx >> 3, c = idx & 7;
            cp16(sptr(Vt + r * VSTH + c * 8),
                 g_kvh + (size_t)(kbase + r) * 2048 + 1024 + hh * 64 + c * 8);
        }
        cp_commit();
    };

#pragma unroll
    for (int i = 0; i < 8; i++) {
        int idx = tid + i * 256;
        int r = idx >> 4, c = idx & 15;
        uint32_t d = sptr(Qh + r * QSTH + c * 8);
        if (c < 8) cp16(d, g_qh  + (size_t)(rowBase + r) * 1024 + hh * 64 + c * 8);
        else       cp16(d, g_qrh + (size_t)(rowBase + r) * 1024 + hh * 64 + (c - 8) * 8);
    }
    issueKV(0, 0);

    const int vrow = (lane & 7) + ((lane >> 3) & 1) * 8;
    const int vcol = (lane >> 4) * 8;
    const uint32_t vLaneByte = (uint32_t)(vrow * VSTH + vcol) * 2;

    const int rloc0 = warp * 16 + g;
    float m0 = -1e30f, m1 = -1e30f, l0 = 0.f, l1 = 0.f;
    float o[8][4];
#pragma unroll
    for (int nt = 0; nt < 8; nt++)
#pragma unroll
        for (int i = 0; i < 4; i++) o[nt][i] = 0.f;

    const int nkt = 2 * qt + 2;
    for (int j = 0; j < nkt; j++) {
        const int s = j & 1;
        if (j + 1 < nkt) { issueKV(j + 1, s ^ 1); cp_wait<1>(); }
        else             { cp_wait<0>(); }
        __syncthreads();

        const __half* Kt = smh + OFFH_K + s * 64 * KSTH;
        const uint32_t vBuf = sptr(smh + OFFH_V + s * 64 * VSTH);

        // --- S = Q @ K^T ------------------------------------------------------
        float sc[8][4];
#pragma unroll
        for (int nt = 0; nt < 8; nt++)
#pragma unroll
            for (int i = 0; i < 4; i++) sc[nt][i] = 0.f;

#pragma unroll
        for (int ks = 0; ks < 8; ks++) {
            const int kb = ks * 16 + 2 * t;
            uint32_t a0 = *reinterpret_cast<const uint32_t*>(&Qh[(rloc0)     * QSTH + kb]);
            uint32_t a1 = *reinterpret_cast<const uint32_t*>(&Qh[(rloc0 + 8) * QSTH + kb]);
            uint32_t a2 = *reinterpret_cast<const uint32_t*>(&Qh[(rloc0)     * QSTH + kb + 8]);
            uint32_t a3 = *reinterpret_cast<const uint32_t*>(&Qh[(rloc0 + 8) * QSTH + kb + 8]);
#pragma unroll
            for (int nt = 0; nt < 8; nt++) {
                uint32_t b0 = *reinterpret_cast<const uint32_t*>(&Kt[(nt * 8 + g) * KSTH + kb]);
                uint32_t b1 = *reinterpret_cast<const uint32_t*>(&Kt[(nt * 8 + g) * KSTH + kb + 8]);
                mmah4(sc[nt], a0, a1, a2, a3, b0, b1);
            }
        }

        // --- causal mask -------------------------------------------------------
        if (j >= 2 * qt) {
            int rg0 = qt * 128 + rloc0;
            int k0 = j * 64;
#pragma unroll
            for (int nt = 0; nt < 8; nt++) {
                int cg = k0 + nt * 8 + 2 * t;
                if (cg     > rg0)     sc[nt][0] = -1e30f;
                if (cg + 1 > rg0)     sc[nt][1] = -1e30f;
                if (cg     > rg0 + 8) sc[nt][2] = -1e30f;
                if (cg + 1 > rg0 + 8) sc[nt][3] = -1e30f;
            }
        }

        // --- online softmax, P packed directly into PV A-fragments ------------
        float mx0 = -1e30f, mx1 = -1e30f;
#pragma unroll
        for (int nt = 0; nt < 8; nt++) {
            mx0 = fmaxf(mx0, fmaxf(sc[nt][0], sc[nt][1]));
            mx1 = fmaxf(mx1, fmaxf(sc[nt][2], sc[nt][3]));
        }
        mx0 = fmaxf(mx0, __shfl_xor_sync(0xffffffffu, mx0, 1));
        mx0 = fmaxf(mx0, __shfl_xor_sync(0xffffffffu, mx0, 2));
        mx1 = fmaxf(mx1, __shfl_xor_sync(0xffffffffu, mx1, 1));
        mx1 = fmaxf(mx1, __shfl_xor_sync(0xffffffffu, mx1, 2));

        float mn0 = fmaxf(m0, mx0), mn1 = fmaxf(m1, mx1);
        float al0 = __expf(m0 - mn0), al1 = __expf(m1 - mn1);
        m0 = mn0; m1 = mn1;

        uint32_t pa[8], pb[8];
        float sum0 = 0.f, sum1 = 0.f;
#pragma unroll
        for (int nt = 0; nt < 8; nt++) {
            float p0 = __expf(sc[nt][0] - mn0);
            float p1 = __expf(sc[nt][1] - mn0);
            float p2 = __expf(sc[nt][2] - mn1);
            float p3 = __expf(sc[nt][3] - mn1);
            sum0 += p0 + p1; sum1 += p2 + p3;
            pa[nt] = h2pack(p0, p1);     // row rloc0,   keys nt*8+2t, +1
            pb[nt] = h2pack(p2, p3);     // row rloc0+8, same keys
        }
        sum0 += __shfl_xor_sync(0xffffffffu, sum0, 1);
        sum0 += __shfl_xor_sync(0xffffffffu, sum0, 2);
        sum1 += __shfl_xor_sync(0xffffffffu, sum1, 1);
        sum1 += __shfl_xor_sync(0xffffffffu, sum1, 2);
        l0 = l0 * al0 + sum0;
        l1 = l1 * al1 + sum1;

#pragma unroll
        for (int nt = 0; nt < 8; nt++) {
            o[nt][0] *= al0; o[nt][1] *= al0;
            o[nt][2] *= al1; o[nt][3] *= al1;
        }

        // --- O += P @ V (P from registers; V via ldmatrix.trans) ---------------
#pragma unroll
        for (int ks = 0; ks < 4; ks++) {
            uint32_t a0 = pa[2 * ks];
            uint32_t a1 = pb[2 * ks];
            uint32_t a2 = pa[2 * ks + 1];
            uint32_t a3 = pb[2 * ks + 1];
#pragma unroll
            for (int ntp = 0; ntp < 4; ntp++) {
                uint32_t b0, b1, b2, b3;
                ldsm4t(b0, b1, b2, b3,
                       vBuf + vLaneByte + (uint32_t)(ks * 16 * VSTH + ntp * 16) * 2);
                mmah4(o[2*ntp],     a0, a1, a2, a3, b0, b1);
                mmah4(o[2*ntp + 1], a0, a1, a2, a3, b2, b3);
            }
        }
        __syncthreads();
    }

    // finalize + store fp16 (wo GEMM is 1-pass)
    float inv0 = 1.0f / l0, inv1 = 1.0f / l1;
    int rg = rowBase + rloc0;
#pragma unroll
    for (int nt = 0; nt < 8; nt++) {
        int col = hh * 64 + nt * 8 + 2 * t;
        *reinterpret_cast<uint32_t*>(&g_ath[(size_t)rg       * 1024 + col]) =
            h2pack(o[nt][0] * inv0, o[nt][1] * inv0);
        *reinterpret_cast<uint32_t*>(&g_ath[(size_t)(rg + 8) * 1024 + col]) =
            h2pack(o[nt][2] * inv1, o[nt][3] * inv1);
    }
}

// ---------------------------------------------------------------------------
// Launch — R10/R12 topology (known-good graph shape).
// ---------------------------------------------------------------------------
extern "C" void kernel_launch(void* const* d_in, const int* in_sizes, int n_in,
                              void* d_out, int out_size)
{
    (void)in_sizes; (void)n_in; (void)out_size;
    const float* x   = (const float*)d_in[0];
    const float* w1  = (const float*)d_in[1];
    const float* b1  = (const float*)d_in[2];
    const float* wkr = (const float*)d_in[3];
    const float* bkr = (const float*)d_in[4];
    const float* wqr = (const float*)d_in[5];
    const float* bqr = (const float*)d_in[6];
    const float* wkv = (const float*)d_in[7];
    const float* bkv = (const float*)d_in[8];
    const float* wq  = (const float*)d_in[9];
    const float* bq  = (const float*)d_in[10];
    const float* wo  = (const float*)d_in[11];
    const float* bo  = (const float*)d_in[12];
    float* out = (float*)d_out;
    const float scale = 0.08838834764831845f;   // 128^-0.5

    __half *qh_, *qrh_, *krh_, *kvh_, *ath_;
    __half *xh_, *xl_, *hh_, *hl_;
    __half *w1f_, *wkrf_, *wqrf_, *wkvf_, *wqf_, *wof_;
    cudaGetSymbolAddress((void**)&qh_,  g_qh);
    cudaGetSymbolAddress((void**)&qrh_, g_qrh);
    cudaGetSymbolAddress((void**)&krh_, g_krh);
    cudaGetSymbolAddress((void**)&kvh_, g_kvh);
    cudaGetSymbolAddress((void**)&ath_, g_ath);
    cudaGetSymbolAddress((void**)&xh_,  g_xh);  cudaGetSymbolAddress((void**)&xl_,  g_xl);
    cudaGetSymbolAddress((void**)&hh_,  g_hh);  cudaGetSymbolAddress((void**)&hl_,  g_hl);
    cudaGetSymbolAddress((void**)&w1f_,  g_w1f);
    cudaGetSymbolAddress((void**)&wkrf_, g_wkrf);
    cudaGetSymbolAddress((void**)&wqrf_, g_wqrf);
    cudaGetSymbolAddress((void**)&wkvf_, g_wkvf);
    cudaGetSymbolAddress((void**)&wqf_,  g_wqf);
    cudaGetSymbolAddress((void**)&wof_,  g_wof);

    const int SMG2_128 = 2 * (2 * 128 * 40 + 128 * 40) * 2;   // 61440 (2-pass)
    const int SMG1_128 = 2 * (128 * 40 + 128 * 40) * 2;       // 40960 (1-pass)
    const int SMG1_64  = 2 * (128 * 40 + 64 * 40) * 2;        // 30720
    const int SMAT     = ATT_HALFS * 2;                        // 88064
    cudaFuncSetAttribute(gemm_f16<128, 1, 0, 2>,    cudaFuncAttributeMaxDynamicSharedMemorySize, SMG2_128);
    cudaFuncSetAttribute(gemm_f16<128, 0, 0, 1>,    cudaFuncAttributeMaxDynamicSharedMemorySize, SMG1_128);
    cudaFuncSetAttribute(gemm_f16<128, 2, 0, 1>,    cudaFuncAttributeMaxDynamicSharedMemorySize, SMG1_128);
    cudaFuncSetAttribute(gemm_f16<128, 3, 1024, 1>, cudaFuncAttributeMaxDynamicSharedMemorySize, SMG1_128);
    cudaFuncSetAttribute(gemm_f16<64,  3, 64, 1>,   cudaFuncAttributeMaxDynamicSharedMemorySize, SMG1_64);
    cudaFuncSetAttribute(attn_fp16_kernel, cudaFuncAttributeMaxDynamicSharedMemorySize, SMAT);

    static cudaStream_t s1 = nullptr, s2 = nullptr, s3 = nullptr;
    static cudaEvent_t evFork, evX, evH, evD1, evD2, evD3;
    if (s1 == nullptr) {
        cudaStreamCreateWithFlags(&s1, cudaStreamNonBlocking);
        cudaStreamCreateWithFlags(&s2, cudaStreamNonBlocking);
        cudaStreamCreateWithFlags(&s3, cudaStreamNonBlocking);
        cudaEventCreateWithFlags(&evFork, cudaEventDisableTiming);
        cudaEventCreateWithFlags(&evX,    cudaEventDisableTiming);
        cudaEventCreateWithFlags(&evH,    cudaEventDisableTiming);
        cudaEventCreateWithFlags(&evD1,   cudaEventDisableTiming);
        cudaEventCreateWithFlags(&evD2,   cudaEventDisableTiming);
        cudaEventCreateWithFlags(&evD3,   cudaEventDisableTiming);
    }

    dim3 wsb(32, 8);

    // fork
    cudaEventRecord(evFork, 0);
    cudaStreamWaitEvent(s1, evFork, 0);
    cudaStreamWaitEvent(s2, evFork, 0);
    cudaStreamWaitEvent(s3, evFork, 0);

    // main: w1 transpose; s1: x split (feeds h GEMM)
    wsplit_kernel<<<dim3(1024/32, 1024/32), wsb, 0, 0>>>(w1, 1024, 1024, w1f_);
    asplit_kernel<<<(MR * 1024 / 4 + 255) / 256, 256, 0, s1>>>(
        (const float4*)x, (uint2*)xh_, (uint2*)xl_, MR * 1024 / 4);
    cudaEventRecord(evX, s1);

    // other weight transposes overlap h GEMM
    wsplit_kernel<<<dim3(1024/32, 1024/32), wsb, 0, s1>>>(wqr, 1024, 1024, wqrf_);
    wsplit_kernel<<<dim3(2048/32, 512/32),  wsb, 0, s2>>>(wkv, 512,  2048, wkvf_);
    wsplit_kernel<<<dim3(1024/32, 512/32),  wsb, 0, s3>>>(wq,  512,  1024, wqf_);
    wsplit_kernel<<<dim3(64/32,   1024/32), wsb, 0, s3>>>(wkr, 1024, 64,   wkrf_);
    wsplit_kernel<<<dim3(1024/32, 1024/32), wsb, 0, s3>>>(wo,  1024, 1024, wof_);

    // 1) h = x @ w1 + b1 -> split fp16 (main stream, 2-pass)
    cudaStreamWaitEvent(0, evX, 0);
    gemm_f16<128, 1, 0, 2><<<dim3(8, 32), 256, SMG2_128, 0>>>(
        1024, 1024, xh_, xl_, 1024, w1f_, b1, 1.f, nullptr, hh_, hl_, nullptr);
    cudaEventRecord(evH, 0);

    // 3) qr = rope((h @ wqr + bqr) * scale) -> fp16   (s1, 1-pass)
    cudaStreamWaitEvent(s1, evH, 0);
    gemm_f16<128, 3, 1024, 1><<<dim3(8, 32), 256, SMG1_128, s1>>>(
        1024, 1024, hh_, hh_, 1024, wqrf_, bqr, scale, nullptr, nullptr, nullptr, qrh_);
    cudaEventRecord(evD1, s1);

    // 4) kv = cKV @ wkv + bkv -> fp16                 (s2, 1-pass)
    cudaStreamWaitEvent(s2, evH, 0);
    gemm_f16<128, 2, 0, 1><<<dim3(16, 32), 256, SMG1_128, s2>>>(
        2048, 512, hh_, hh_, 1024, wkvf_, bkv, 1.f, nullptr, nullptr, nullptr, kvh_);
    cudaEventRecord(evD2, s2);

    // 5) q = (cq @ wq + bq) * scale -> fp16 ; 2) kr = rope(h @ wkr + bkr) -> fp16   (s3, 1-pass)
    cudaStreamWaitEvent(s3, evH, 0);
    gemm_f16<128, 2, 0, 1><<<dim3(8, 32), 256, SMG1_128, s3>>>(
        1024, 512, hh_ + 512, hh_ + 512, 1024, wqf_, bq, scale, nullptr, nullptr, nullptr, qh_);
    gemm_f16<64, 3, 64, 1><<<dim3(1, 32), 256, SMG1_64, s3>>>(
        64, 1024, hh_, hh_, 1024, wkrf_, bkr, 1.f, nullptr, nullptr, nullptr, krh_);
    cudaEventRecord(evD3, s3);

    // join -> attention -> wo (main stream)
    cudaStreamWaitEvent(0, evD1, 0);
    cudaStreamWaitEvent(0, evD2, 0);
    cudaStreamWaitEvent(0, evD3, 0);

    attn_fp16_kernel<<<dim3(16, NH, BB), 256, SMAT, 0>>>();

    // 7) out = att @ wo + bo  (1-pass; att fp16 storage is the only new error)
    gemm_f16<128, 0, 0, 1><<<dim3(8, 32), 256, SMG1_128, 0>>>(
        1024, 1024, ath_, ath_, 1024, wof_, bo, 1.f, out, nullptr, nullptr, nullptr);
}

// round 15
// speedup vs baseline: 2.3625x; 1.0750x over previous
#include <cuda_runtime.h>
#include <cuda_bf16.h>
#include <cuda_fp16.h>
#include <math.h>
#include <stdint.h>

// Problem constants
#define BB   2
#define TT   2048
#define CC   1024
#define NH   16
#define LAT  512
#define DHR  64
#define MR   (BB*TT)        // 4096 rows

// ---------------------------------------------------------------------------
// Scratch (static device globals)
// ---------------------------------------------------------------------------
__device__ __half g_qh [MR * 1024];
__device__ __half g_qrh[MR * 1024];
__device__ __half g_krh[MR * 64];
__device__ __half g_kvh[MR * 2048];   // k cols 0..1023, v cols 1024..2047
__device__ __half g_ath[MR * 1024];   // attention out (fp16)

__device__ __half g_xh[MR*1024];      // x (fp16)
__device__ __half g_hh[MR*1024];      // h (fp16)
// transposed weights [N,K], single fp16
__device__ __half g_w1f [1024*1024];
__device__ __half g_wkrf[64*1024];
__device__ __half g_wqrf[1024*1024];
__device__ __half g_wkvf[2048*512];
__device__ __half g_wqf [1024*512];
__device__ __half g_wof [1024*1024];

// ---------------------------------------------------------------------------
// helpers
// ---------------------------------------------------------------------------
__device__ __forceinline__ void mmah(float* c, const uint32_t* a,
                                     uint32_t b0, uint32_t b1) {
    asm volatile(
        "mma.sync.aligned.m16n8k16.row.col.f32.f16.f16.f32 "
        "{%0,%1,%2,%3},{%4,%5,%6,%7},{%8,%9},{%0,%1,%2,%3};"
        : "+f"(c[0]), "+f"(c[1]), "+f"(c[2]), "+f"(c[3])
        : "r"(a[0]), "r"(a[1]), "r"(a[2]), "r"(a[3]), "r"(b0), "r"(b1));
}
__device__ __forceinline__ void mmah4(float* c,
                                      uint32_t a0, uint32_t a1, uint32_t a2, uint32_t a3,
                                      uint32_t b0, uint32_t b1) {
    asm volatile(
        "mma.sync.aligned.m16n8k16.row.col.f32.f16.f16.f32 "
        "{%0,%1,%2,%3},{%4,%5,%6,%7},{%8,%9},{%0,%1,%2,%3};"
        : "+f"(c[0]), "+f"(c[1]), "+f"(c[2]), "+f"(c[3])
        : "r"(a0), "r"(a1), "r"(a2), "r"(a3), "r"(b0), "r"(b1));
}
__device__ __forceinline__ void ldsm4t(uint32_t& r0, uint32_t& r1,
                                       uint32_t& r2, uint32_t& r3, uint32_t addr) {
    asm volatile("ldmatrix.sync.aligned.m8n8.x4.trans.shared.b16 {%0,%1,%2,%3}, [%4];"
                 : "=r"(r0), "=r"(r1), "=r"(r2), "=r"(r3) : "r"(addr));
}
__device__ __forceinline__ uint32_t h2pack(float x, float y) {
    uint32_t u;
    asm("cvt.rn.f16x2.f32 %0, %1, %2;" : "=r"(u) : "f"(y), "f"(x));
    return u;
}
__device__ __forceinline__ uint32_t sptr(const void* p) {
    return (uint32_t)__cvta_generic_to_shared(p);
}
__device__ __forceinline__ void cp16(uint32_t dst, const void* src) {
    asm volatile("cp.async.cg.shared.global [%0], [%1], 16;" :: "r"(dst), "l"(src));
}
__device__ __forceinline__ void cp_commit() {
    asm volatile("cp.async.commit_group;");
}
template<int N> __device__ __forceinline__ void cp_wait() {
    asm volatile("cp.async.wait_group %0;" :: "n"(N));
}

// ---------------------------------------------------------------------------
// Weight transpose: W[K,N] fp32 -> Wf[N,K] fp16
// ---------------------------------------------------------------------------
__global__ void wsplit_kernel(const float* __restrict__ W, int K, int N,
                              __half* __restrict__ Wf)
{
    __shared__ float tile[32][33];
    int n0 = blockIdx.x * 32, k0 = blockIdx.y * 32;
    int tx = threadIdx.x, ty = threadIdx.y;
#pragma unroll
    for (int i = 0; i < 32; i += 8)
        tile[ty + i][tx] = W[(size_t)(k0 + ty + i) * N + n0 + tx];
    __syncthreads();
#pragma unroll
    for (int i = 0; i < 32; i += 8) {
        int n = n0 + ty + i, k = k0 + tx;
        Wf[(size_t)n * K + k] = __float2half_rn(tile[tx][ty + i]);
    }
}

// x convert: fp32 -> fp16
__global__ void aconv_kernel(const float4* __restrict__ X,
                             uint2* __restrict__ Xh, int n4)
{
    int i = blockIdx.x * blockDim.x + threadIdx.x;
    if (i >= n4) return;
    float4 v = X[i];
    Xh[i] = make_uint2(h2pack(v.x, v.y), h2pack(v.z, v.w));
}

// ---------------------------------------------------------------------------
// 1-pass fp16 mma.sync GEMM: C = A[M,K] @ B[N,K]^T + bias
// OUT: 0 = fp32 C, 2 = packed fp16 (H),
//      3 = packed fp16 with fused RoPE (rotary dim = RD)
// ---------------------------------------------------------------------------
template<int BN, int OUT, int RD>
__global__ __launch_bounds__(256, 2)
void gemm_f16(int N, int K,
              const __half* __restrict__ Ag, int lda,
              const __half* __restrict__ Bg,
              const float* __restrict__ bias, float oscale,
              float* __restrict__ C,
              __half* __restrict__ H)
{
    constexpr int BM   = 128;
    constexpr int WM   = BM / 4;
    constexpr int WN   = BN / 2;
    constexpr int MT   = WM / 16;
    constexpr int NT   = WN / 8;
    constexpr int STR  = 40;
    constexpr int ASL  = BM * STR;
    constexpr int BSL  = BN * STR;
    constexpr int STG  = ASL + BSL;
    constexpr int NAC  = (BM * 4) / 256;
    constexpr int NBC  = (BN * 4) / 256;

    extern __shared__ __half smb[];

    const int tid  = threadIdx.x;
    const int lane = tid & 31;
    const int warp = tid >> 5;
    const int g    = lane >> 2;
    const int t    = lane & 3;
    const int wm   = warp >> 1;
    const int wn   = warp & 1;
    const int bRow = blockIdx.y * BM;
    const int bCol = blockIdx.x * BN;

    float acc[MT][NT][4];
#pragma unroll
    for (int mt = 0; mt < MT; mt++)
#pragma unroll
        for (int nt = 0; nt < NT; nt++)
#pragma unroll
            for (int i = 0; i < 4; i++) acc[mt][nt][i] = 0.f;

    auto issue = [&](int k0, int s) {
        __half* st = smb + s * STG;
#pragma unroll
        for (int i = 0; i < NAC; i++) {
            int idx = tid + i * 256;
            int r = idx >> 2, c = idx & 3;
            cp16(sptr(st + r * STR + c * 8),
                 Ag + (size_t)(bRow + r) * lda + k0 + c * 8);
        }
#pragma unroll
        for (int i = 0; i < NBC; i++) {
            int idx = tid + i * 256;
            int r = idx >> 2, c = idx & 3;
            cp16(sptr(st + ASL + r * STR + c * 8),
                 Bg + (size_t)(bCol + r) * K + k0 + c * 8);
        }
        cp_commit();
    };

    const int iters = K / 32;
    issue(0, 0);

    for (int it = 0; it < iters; it++) {
        const int cur = it & 1;
        if (it + 1 < iters) { issue((it + 1) * 32, cur ^ 1); cp_wait<1>(); }
        else                { cp_wait<0>(); }
        __syncthreads();

        const __half* As = smb + cur * STG;
        const __half* Bs = As + ASL;

#pragma unroll
        for (int s = 0; s < 2; s++) {
            const int kb = 16 * s + 2 * t;
            uint32_t ah[MT][4];
#pragma unroll
            for (int mt = 0; mt < MT; mt++) {
                int r0 = wm * WM + mt * 16 + g;
                int r1 = r0 + 8;
                ah[mt][0] = *reinterpret_cast<const uint32_t*>(&As[r0 * STR + kb]);
                ah[mt][1] = *reinterpret_cast<const uint32_t*>(&As[r1 * STR + kb]);
                ah[mt][2] = *reinterpret_cast<const uint32_t*>(&As[r0 * STR + kb + 8]);
                ah[mt][3] = *reinterpret_cast<const uint32_t*>(&As[r1 * STR + kb + 8]);
            }
#pragma unroll
            for (int nt = 0; nt < NT; nt++) {
                int nb = wn * WN + nt * 8 + g;
                uint32_t b0 = *reinterpret_cast<const uint32_t*>(&Bs[nb * STR + kb]);
                uint32_t b1 = *reinterpret_cast<const uint32_t*>(&Bs[nb * STR + kb + 8]);
#pragma unroll
                for (int mt = 0; mt < MT; mt++)
                    mmah(acc[mt][nt], ah[mt], b0, b1);
            }
        }
        __syncthreads();
    }

#pragma unroll
    for (int mt = 0; mt < MT; mt++) {
        int r0 = bRow + wm * WM + mt * 16 + g;
#pragma unroll
        for (int nt = 0; nt < NT; nt++) {
            int col = bCol + wn * WN + nt * 8 + 2 * t;
            float bx = bias[col], by = bias[col + 1];
            float v00 = (acc[mt][nt][0] + bx) * oscale, v01 = (acc[mt][nt][1] + by) * oscale;
            float v10 = (acc[mt][nt][2] + bx) * oscale, v11 = (acc[mt][nt][3] + by) * oscale;
            if (OUT == 0) {
                float2 a = {v00, v01}, b = {v10, v11};
                *reinterpret_cast<float2*>(C + (size_t)r0 * N + col)       = a;
                *reinterpret_cast<float2*>(C + (size_t)(r0 + 8) * N + col) = b;
            } else if (OUT == 2) {
                *reinterpret_cast<uint32_t*>(&H[(size_t)r0 * N + col])       = h2pack(v00, v01);
                *reinterpret_cast<uint32_t*>(&H[(size_t)(r0 + 8) * N + col]) = h2pack(v10, v11);
            } else {
                float th = expf(-2.0f * (float)(col >> 1) / (float)RD * 9.2103403719761836f);
                int tt0 = r0 & (TT - 1);
                float sn0, cs0, sn1, cs1;
                sincosf((float)(tt0 + 1) * th, &sn0, &cs0);
                sincosf((float)(tt0 + 9) * th, &sn1, &cs1);
                float e0 = v00 * cs0 - v01 * sn0;
                float o0 = v01 * cs0 + v00 * sn0;
                float e1 = v10 * cs1 - v11 * sn1;
                float o1 = v11 * cs1 + v10 * sn1;
                *reinterpret_cast<uint32_t*>(&H[(size_t)r0 * N + col])       = h2pack(e0, o0);
                *reinterpret_cast<uint32_t*>(&H[(size_t)(r0 + 8) * N + col]) = h2pack(e1, o1);
            }
        }
    }
}

// ---------------------------------------------------------------------------
// Causal flash attention, fp16 mma.sync m16n8k16. (R14 form — P in registers)
// ---------------------------------------------------------------------------
#define QSTH 136
#define KSTH 136
#define VSTH 72

#define OFFH_K (128 * QSTH)
#define OFFH_V (OFFH_K + 2 * 64 * KSTH)
#define ATT_HALFS (OFFH_V + 2 * 64 * VSTH)   // 44032 halfs = 88064 B

__global__ __launch_bounds__(256, 2)
void attn_fp16_kernel()
{
    extern __shared__ __half smh[];
    __half* Qh = smh;

    const int tid  = threadIdx.x;
    const int lane = tid & 31;
    const int warp = tid >> 5;
    const int g    = lane >> 2;
    const int t    = lane & 3;
    const int qt   = (gridDim.x - 1) - blockIdx.x;
    const int hh   = blockIdx.y;
    const int b    = blockIdx.z;
    const int rowBase = b * TT + qt * 128;

    auto issueKV = [&](int j, int s) {
        __half* Kt = smh + OFFH_K + s * 64 * KSTH;
        __half* Vt = smh + OFFH_V + s * 64 * VSTH;
        const int kbase = b * TT + j * 64;
#pragma unroll
        for (int i = 0; i < 4; i++) {
            int idx = tid + i * 256;
            int r = idx >> 4, c = idx & 15;
            uint32_t d = sptr(Kt + r * KSTH + c * 8);
            if (c < 8) cp16(d, g_kvh + (size_t)(kbase + r) * 2048 + hh * 64 + c * 8);
            else       cp16(d, g_krh + (size_t)(kbase + r) * 64 + (c - 8) * 8);
        }
#pragma unroll
        for (int i = 0; i < 2; i++) {
            int idx = tid + i * 256;
            int r = idx >> 3, c = idx & 7;
            cp16(sptr(Vt + r * VSTH + c * 8),
                 g_kvh + (size_t)(kbase + r) * 2048 + 1024 + hh * 64 + c * 8);
        }
        cp_commit();
    };

#pragma unroll
    for (int i = 0; i < 8; i++) {
        int idx = tid + i * 256;
        int r = idx >> 4, c = idx & 15;
        uint32_t d = sptr(Qh + r * QSTH + c * 8);
        if (c < 8) cp16(d, g_qh  + (size_t)(rowBase + r) * 1024 + hh * 64 + c * 8);
        else       cp16(d, g_qrh + (size_t)(rowBase + r) * 1024 + hh * 64 + (c - 8) * 8);
    }
    issueKV(0, 0);

    const int vrow = (lane & 7) + ((lane >> 3) & 1) * 8;
    const int vcol = (lane >> 4) * 8;
    const uint32_t vLaneByte = (uint32_t)(vrow * VSTH + vcol) * 2;

    const int rloc0 = warp * 16 + g;
    float m0 = -1e30f, m1 = -1e30f, l0 = 0.f, l1 = 0.f;
    float o[8][4];
#pragma unroll
    for (int nt = 0; nt < 8; nt++)
#pragma unroll
        for (int i = 0; i < 4; i++) o[nt][i] = 0.f;

    const int nkt = 2 * qt + 2;
    for (int j = 0; j < nkt; j++) {
        const int s = j & 1;
        if (j + 1 < nkt) { issueKV(j + 1, s ^ 1); cp_wait<1>(); }
        else             { cp_wait<0>(); }
        __syncthreads();

        const __half* Kt = smh + OFFH_K + s * 64 * KSTH;
        const uint32_t vBuf = sptr(smh + OFFH_V + s * 64 * VSTH);

        // --- S = Q @ K^T ------------------------------------------------------
        float sc[8][4];
#pragma unroll
        for (int nt = 0; nt < 8; nt++)
#pragma unroll
            for (int i = 0; i < 4; i++) sc[nt][i] = 0.f;

#pragma unroll
        for (int ks = 0; ks < 8; ks++) {
            const int kb = ks * 16 + 2 * t;
            uint32_t a0 = *reinterpret_cast<const uint32_t*>(&Qh[(rloc0)     * QSTH + kb]);
            uint32_t a1 = *reinterpret_cast<const uint32_t*>(&Qh[(rloc0 + 8) * QSTH + kb]);
            uint32_t a2 = *reinterpret_cast<const uint32_t*>(&Qh[(rloc0)     * QSTH + kb + 8]);
            uint32_t a3 = *reinterpret_cast<const uint32_t*>(&Qh[(rloc0 + 8) * QSTH + kb + 8]);
#pragma unroll
            for (int nt = 0; nt < 8; nt++) {
                uint32_t b0 = *reinterpret_cast<const uint32_t*>(&Kt[(nt * 8 + g) * KSTH + kb]);
                uint32_t b1 = *reinterpret_cast<const uint32_t*>(&Kt[(nt * 8 + g) * KSTH + kb + 8]);
                mmah4(sc[nt], a0, a1, a2, a3, b0, b1);
            }
        }

        // --- causal mask -------------------------------------------------------
        if (j >= 2 * qt) {
            int rg0 = qt * 128 + rloc0;
            int k0 = j * 64;
#pragma unroll
            for (int nt = 0; nt < 8; nt++) {
                int cg = k0 + nt * 8 + 2 * t;
                if (cg     > rg0)     sc[nt][0] = -1e30f;
                if (cg + 1 > rg0)     sc[nt][1] = -1e30f;
                if (cg     > rg0 + 8) sc[nt][2] = -1e30f;
                if (cg + 1 > rg0 + 8) sc[nt][3] = -1e30f;
            }
        }

        // --- online softmax, P packed directly into PV A-fragments ------------
        float mx0 = -1e30f, mx1 = -1e30f;
#pragma unroll
        for (int nt = 0; nt < 8; nt++) {
            mx0 = fmaxf(mx0, fmaxf(sc[nt][0], sc[nt][1]));
            mx1 = fmaxf(mx1, fmaxf(sc[nt][2], sc[nt][3]));
        }
        mx0 = fmaxf(mx0, __shfl_xor_sync(0xffffffffu, mx0, 1));
        mx0 = fmaxf(mx0, __shfl_xor_sync(0xffffffffu, mx0, 2));
        mx1 = fmaxf(mx1, __shfl_xor_sync(0xffffffffu, mx1, 1));
        mx1 = fmaxf(mx1, __shfl_xor_sync(0xffffffffu, mx1, 2));

        float mn0 = fmaxf(m0, mx0), mn1 = fmaxf(m1, mx1);
        float al0 = __expf(m0 - mn0), al1 = __expf(m1 - mn1);
        m0 = mn0; m1 = mn1;

        uint32_t pa[8], pb[8];
        float sum0 = 0.f, sum1 = 0.f;
#pragma unroll
        for (int nt = 0; nt < 8; nt++) {
            float p0 = __expf(sc[nt][0] - mn0);
            float p1 = __expf(sc[nt][1] - mn0);
            float p2 = __expf(sc[nt][2] - mn1);
            float p3 = __expf(sc[nt][3] - mn1);
            sum0 += p0 + p1; sum1 += p2 + p3;
            pa[nt] = h2pack(p0, p1);
            pb[nt] = h2pack(p2, p3);
        }
        sum0 += __shfl_xor_sync(0xffffffffu, sum0, 1);
        sum0 += __shfl_xor_sync(0xffffffffu, sum0, 2);
        sum1 += __shfl_xor_sync(0xffffffffu, sum1, 1);
        sum1 += __shfl_xor_sync(0xffffffffu, sum1, 2);
        l0 = l0 * al0 + sum0;
        l1 = l1 * al1 + sum1;

#pragma unroll
        for (int nt = 0; nt < 8; nt++) {
            o[nt][0] *= al0; o[nt][1] *= al0;
            o[nt][2] *= al1; o[nt][3] *= al1;
        }

        // --- O += P @ V (P from registers; V via ldmatrix.trans) ---------------
#pragma unroll
        for (int ks = 0; ks < 4; ks++) {
            uint32_t a0 = pa[2 * ks];
            uint32_t a1 = pb[2 * ks];
            uint32_t a2 = pa[2 * ks + 1];
            uint32_t a3 = pb[2 * ks + 1];
#pragma unroll
            for (int ntp = 0; ntp < 4; ntp++) {
                uint32_t b0, b1, b2, b3;
                ldsm4t(b0, b1, b2, b3,
                       vBuf + vLaneByte + (uint32_t)(ks * 16 * VSTH + ntp * 16) * 2);
                mmah4(o[2*ntp],     a0, a1, a2, a3, b0, b1);
                mmah4(o[2*ntp + 1], a0, a1, a2, a3, b2, b3);
            }
        }
        __syncthreads();
    }

    float inv0 = 1.0f / l0, inv1 = 1.0f / l1;
    int rg = rowBase + rloc0;
#pragma unroll
    for (int nt = 0; nt < 8; nt++) {
        int col = hh * 64 + nt * 8 + 2 * t;
        *reinterpret_cast<uint32_t*>(&g_ath[(size_t)rg       * 1024 + col]) =
            h2pack(o[nt][0] * inv0, o[nt][1] * inv0);
        *reinterpret_cast<uint32_t*>(&g_ath[(size_t)(rg + 8) * 1024 + col]) =
            h2pack(o[nt][2] * inv1, o[nt][3] * inv1);
    }
}

// ---------------------------------------------------------------------------
// Launch — R10/R12 topology (known-good graph shape).
// ---------------------------------------------------------------------------
extern "C" void kernel_launch(void* const* d_in, const int* in_sizes, int n_in,
                              void* d_out, int out_size)
{
    (void)in_sizes; (void)n_in; (void)out_size;
    const float* x   = (const float*)d_in[0];
    const float* w1  = (const float*)d_in[1];
    const float* b1  = (const float*)d_in[2];
    const float* wkr = (const float*)d_in[3];
    const float* bkr = (const float*)d_in[4];
    const float* wqr = (const float*)d_in[5];
    const float* bqr = (const float*)d_in[6];
    const float* wkv = (const float*)d_in[7];
    const float* bkv = (const float*)d_in[8];
    const float* wq  = (const float*)d_in[9];
    const float* bq  = (const float*)d_in[10];
    const float* wo  = (const float*)d_in[11];
    const float* bo  = (const float*)d_in[12];
    float* out = (float*)d_out;
    const float scale = 0.08838834764831845f;   // 128^-0.5

    __half *qh_, *qrh_, *krh_, *kvh_, *ath_, *xh_, *hh_;
    __half *w1f_, *wkrf_, *wqrf_, *wkvf_, *wqf_, *wof_;
    cudaGetSymbolAddress((void**)&qh_,  g_qh);
    cudaGetSymbolAddress((void**)&qrh_, g_qrh);
    cudaGetSymbolAddress((void**)&krh_, g_krh);
    cudaGetSymbolAddress((void**)&kvh_, g_kvh);
    cudaGetSymbolAddress((void**)&ath_, g_ath);
    cudaGetSymbolAddress((void**)&xh_,  g_xh);
    cudaGetSymbolAddress((void**)&hh_,  g_hh);
    cudaGetSymbolAddress((void**)&w1f_,  g_w1f);
    cudaGetSymbolAddress((void**)&wkrf_, g_wkrf);
    cudaGetSymbolAddress((void**)&wqrf_, g_wqrf);
    cudaGetSymbolAddress((void**)&wkvf_, g_wkvf);
    cudaGetSymbolAddress((void**)&wqf_,  g_wqf);
    cudaGetSymbolAddress((void**)&wof_,  g_wof);

    const int SMG_128 = 2 * (128 * 40 + 128 * 40) * 2;   // 40960
    const int SMG_64  = 2 * (128 * 40 + 64 * 40) * 2;    // 30720
    const int SMAT    = ATT_HALFS * 2;                    // 88064
    cudaFuncSetAttribute(gemm_f16<128, 0, 0>,    cudaFuncAttributeMaxDynamicSharedMemorySize, SMG_128);
    cudaFuncSetAttribute(gemm_f16<128, 2, 0>,    cudaFuncAttributeMaxDynamicSharedMemorySize, SMG_128);
    cudaFuncSetAttribute(gemm_f16<128, 3, 1024>, cudaFuncAttributeMaxDynamicSharedMemorySize, SMG_128);
    cudaFuncSetAttribute(gemm_f16<64,  3, 64>,   cudaFuncAttributeMaxDynamicSharedMemorySize, SMG_64);
    cudaFuncSetAttribute(attn_fp16_kernel, cudaFuncAttributeMaxDynamicSharedMemorySize, SMAT);

    static cudaStream_t s1 = nullptr, s2 = nullptr, s3 = nullptr;
    static cudaEvent_t evFork, evX, evH, evD1, evD2, evD3;
    if (s1 == nullptr) {
        cudaStreamCreateWithFlags(&s1, cudaStreamNonBlocking);
        cudaStreamCreateWithFlags(&s2, cudaStreamNonBlocking);
        cudaStreamCreateWithFlags(&s3, cudaStreamNonBlocking);
        cudaEventCreateWithFlags(&evFork, cudaEventDisableTiming);
        cudaEventCreateWithFlags(&evX,    cudaEventDisableTiming);
        cudaEventCreateWithFlags(&evH,    cudaEventDisableTiming);
        cudaEventCreateWithFlags(&evD1,   cudaEventDisableTiming);
        cudaEventCreateWithFlags(&evD2,   cudaEventDisableTiming);
        cudaEventCreateWithFlags(&evD3,   cudaEventDisableTiming);
    }

    dim3 wsb(32, 8);

    // fork
    cudaEventRecord(evFork, 0);
    cudaStreamWaitEvent(s1, evFork, 0);
    cudaStreamWaitEvent(s2, evFork, 0);
    cudaStreamWaitEvent(s3, evFork, 0);

    // main: w1 transpose; s1: x convert (feeds h GEMM)
    wsplit_kernel<<<dim3(1024/32, 1024/32), wsb, 0, 0>>>(w1, 1024, 1024, w1f_);
    aconv_kernel<<<(MR * 1024 / 4 + 255) / 256, 256, 0, s1>>>(
        (const float4*)x, (uint2*)xh_, MR * 1024 / 4);
    cudaEventRecord(evX, s1);

    // other weight transposes overlap h GEMM
    wsplit_kernel<<<dim3(1024/32, 1024/32), wsb, 0, s1>>>(wqr, 1024, 1024, wqrf_);
    wsplit_kernel<<<dim3(2048/32, 512/32),  wsb, 0, s2>>>(wkv, 512,  2048, wkvf_);
    wsplit_kernel<<<dim3(1024/32, 512/32),  wsb, 0, s3>>>(wq,  512,  1024, wqf_);
    wsplit_kernel<<<dim3(64/32,   1024/32), wsb, 0, s3>>>(wkr, 1024, 64,   wkrf_);
    wsplit_kernel<<<dim3(1024/32, 1024/32), wsb, 0, s3>>>(wo,  1024, 1024, wof_);

    // 1) h = x @ w1 + b1 -> fp16 (main stream, 1-pass)
    cudaStreamWaitEvent(0, evX, 0);
    gemm_f16<128, 2, 0><<<dim3(8, 32), 256, SMG_128, 0>>>(
        1024, 1024, xh_, 1024, w1f_, b1, 1.f, nullptr, hh_);
    cudaEventRecord(evH, 0);

    // 3) qr = rope((h @ wqr + bqr) * scale) -> fp16   (s1)
    cudaStreamWaitEvent(s1, evH, 0);
    gemm_f16<128, 3, 1024><<<dim3(8, 32), 256, SMG_128, s1>>>(
        1024, 1024, hh_, 1024, wqrf_, bqr, scale, nullptr, qrh_);
    cudaEventRecord(evD1, s1);

    // 4) kv = cKV @ wkv + bkv -> fp16                 (s2)
    cudaStreamWaitEvent(s2, evH, 0);
    gemm_f16<128, 2, 0><<<dim3(16, 32), 256, SMG_128, s2>>>(
        2048, 512, hh_, 1024, wkvf_, bkv, 1.f, nullptr, kvh_);
    cudaEventRecord(evD2, s2);

    // 5) q = (cq @ wq + bq) * scale -> fp16 ; 2) kr = rope(h @ wkr + bkr) -> fp16   (s3)
    cudaStreamWaitEvent(s3, evH, 0);
    gemm_f16<128, 2, 0><<<dim3(8, 32), 256, SMG_128, s3>>>(
        1024, 512, hh_ + 512, 1024, wqf_, bq, scale, nullptr, qh_);
    gemm_f16<64, 3, 64><<<dim3(1, 32), 256, SMG_64, s3>>>(
        64, 1024, hh_, 1024, wkrf_, bkr, 1.f, nullptr, krh_);
    cudaEventRecord(evD3, s3);

    // join -> attention -> wo (main stream)
    cudaStreamWaitEvent(0, evD1, 0);
    cudaStreamWaitEvent(0, evD2, 0);
    cudaStreamWaitEvent(0, evD3, 0);

    attn_fp16_kernel<<<dim3(16, NH, BB), 256, SMAT, 0>>>();

    // 7) out = att @ wo + bo
    gemm_f16<128, 0, 0><<<dim3(8, 32), 256, SMG_128, 0>>>(
        1024, 1024, ath_, 1024, wof_, bo, 1.f, out, nullptr);
}

// round 16
// speedup vs baseline: 2.4455x; 1.0351x over previous
#include <cuda_runtime.h>
#include <cuda_bf16.h>
#include <cuda_fp16.h>
#include <math.h>
#include <stdint.h>

// Problem constants
#define BB   2
#define TT   2048
#define CC   1024
#define NH   16
#define LAT  512
#define DHR  64
#define MR   (BB*TT)        // 4096 rows

// ---------------------------------------------------------------------------
// Scratch (static device globals)
// ---------------------------------------------------------------------------
__device__ __half g_qh [MR * 1024];
__device__ __half g_qrh[MR * 1024];
__device__ __half g_krh[MR * 64];
__device__ __half g_kvh[MR * 2048];   // k cols 0..1023, v cols 1024..2047
__device__ __half g_ath[MR * 1024];   // attention out (fp16)

__device__ __half g_xh[MR*1024];      // x (fp16)
__device__ __half g_hh[MR*1024];      // h (fp16)
// transposed weights [N,K], single fp16
__device__ __half g_w1f [1024*1024];
__device__ __half g_wkrf[64*1024];
__device__ __half g_wqrf[1024*1024];
__device__ __half g_wkvf[2048*512];
__device__ __half g_wqf [1024*512];
__device__ __half g_wof [1024*1024];

// ---------------------------------------------------------------------------
// helpers
// ---------------------------------------------------------------------------
__device__ __forceinline__ void mmah(float* c, const uint32_t* a,
                                     uint32_t b0, uint32_t b1) {
    asm volatile(
        "mma.sync.aligned.m16n8k16.row.col.f32.f16.f16.f32 "
        "{%0,%1,%2,%3},{%4,%5,%6,%7},{%8,%9},{%0,%1,%2,%3};"
        : "+f"(c[0]), "+f"(c[1]), "+f"(c[2]), "+f"(c[3])
        : "r"(a[0]), "r"(a[1]), "r"(a[2]), "r"(a[3]), "r"(b0), "r"(b1));
}
__device__ __forceinline__ void mmah4(float* c,
                                      uint32_t a0, uint32_t a1, uint32_t a2, uint32_t a3,
                                      uint32_t b0, uint32_t b1) {
    asm volatile(
        "mma.sync.aligned.m16n8k16.row.col.f32.f16.f16.f32 "
        "{%0,%1,%2,%3},{%4,%5,%6,%7},{%8,%9},{%0,%1,%2,%3};"
        : "+f"(c[0]), "+f"(c[1]), "+f"(c[2]), "+f"(c[3])
        : "r"(a0), "r"(a1), "r"(a2), "r"(a3), "r"(b0), "r"(b1));
}
__device__ __forceinline__ void ldsm4t(uint32_t& r0, uint32_t& r1,
                                       uint32_t& r2, uint32_t& r3, uint32_t addr) {
    asm volatile("ldmatrix.sync.aligned.m8n8.x4.trans.shared.b16 {%0,%1,%2,%3}, [%4];"
                 : "=r"(r0), "=r"(r1), "=r"(r2), "=r"(r3) : "r"(addr));
}
__device__ __forceinline__ uint32_t h2pack(float x, float y) {
    uint32_t u;
    asm("cvt.rn.f16x2.f32 %0, %1, %2;" : "=r"(u) : "f"(y), "f"(x));
    return u;
}
__device__ __forceinline__ uint32_t sptr(const void* p) {
    return (uint32_t)__cvta_generic_to_shared(p);
}
__device__ __forceinline__ void cp16(uint32_t dst, const void* src) {
    asm volatile("cp.async.cg.shared.global [%0], [%1], 16;" :: "r"(dst), "l"(src));
}
__device__ __forceinline__ void cp_commit() {
    asm volatile("cp.async.commit_group;");
}
template<int N> __device__ __forceinline__ void cp_wait() {
    asm volatile("cp.async.wait_group %0;" :: "n"(N));
}

// ---------------------------------------------------------------------------
// Weight transpose: W[K,N] fp32 -> Wf[N,K] fp16
// ---------------------------------------------------------------------------
__global__ void wsplit_kernel(const float* __restrict__ W, int K, int N,
                              __half* __restrict__ Wf)
{
    __shared__ float tile[32][33];
    int n0 = blockIdx.x * 32, k0 = blockIdx.y * 32;
    int tx = threadIdx.x, ty = threadIdx.y;
#pragma unroll
    for (int i = 0; i < 32; i += 8)
        tile[ty + i][tx] = W[(size_t)(k0 + ty + i) * N + n0 + tx];
    __syncthreads();
#pragma unroll
    for (int i = 0; i < 32; i += 8) {
        int n = n0 + ty + i, k = k0 + tx;
        Wf[(size_t)n * K + k] = __float2half_rn(tile[tx][ty + i]);
    }
}

// x convert: fp32 -> fp16
__global__ void aconv_kernel(const float4* __restrict__ X,
                             uint2* __restrict__ Xh, int n4)
{
    int i = blockIdx.x * blockDim.x + threadIdx.x;
    if (i >= n4) return;
    float4 v = X[i];
    Xh[i] = make_uint2(h2pack(v.x, v.y), h2pack(v.z, v.w));
}

// ---------------------------------------------------------------------------
// 1-pass fp16 mma.sync GEMM, 3-stage cp.async pipeline, ONE sync per k-iter.
// C = A[M,K] @ B[N,K]^T + bias
// OUT: 0 = fp32 C, 2 = packed fp16 (H),
//      3 = packed fp16 with fused RoPE (rotary dim = RD)
// ---------------------------------------------------------------------------
template<int BN, int OUT, int RD>
__global__ __launch_bounds__(256, 2)
void gemm_f16(int N, int K, int rowOff,
              const __half* __restrict__ Ag, int lda,
              const __half* __restrict__ Bg,
              const float* __restrict__ bias, float oscale,
              float* __restrict__ C,
              __half* __restrict__ H)
{
    constexpr int BM   = 128;
    constexpr int WM   = BM / 4;
    constexpr int WN   = BN / 2;
    constexpr int MT   = WM / 16;
    constexpr int NT   = WN / 8;
    constexpr int STR  = 40;
    constexpr int ASL  = BM * STR;
    constexpr int BSL  = BN * STR;
    constexpr int STG  = ASL + BSL;
    constexpr int NAC  = (BM * 4) / 256;
    constexpr int NBC  = (BN * 4) / 256;

    extern __shared__ __half smb[];

    const int tid  = threadIdx.x;
    const int lane = tid & 31;
    const int warp = tid >> 5;
    const int g    = lane >> 2;
    const int t    = lane & 3;
    const int wm   = warp >> 1;
    const int wn   = warp & 1;
    const int bRow = blockIdx.y * BM + rowOff;
    const int bCol = blockIdx.x * BN;

    float acc[MT][NT][4];
#pragma unroll
    for (int mt = 0; mt < MT; mt++)
#pragma unroll
        for (int nt = 0; nt < NT; nt++)
#pragma unroll
            for (int i = 0; i < 4; i++) acc[mt][nt][i] = 0.f;

    auto issue = [&](int k0, int s) {
        __half* st = smb + s * STG;
#pragma unroll
        for (int i = 0; i < NAC; i++) {
            int idx = tid + i * 256;
            int r = idx >> 2, c = idx & 3;
            cp16(sptr(st + r * STR + c * 8),
                 Ag + (size_t)(bRow + r) * lda + k0 + c * 8);
        }
#pragma unroll
        for (int i = 0; i < NBC; i++) {
            int idx = tid + i * 256;
            int r = idx >> 2, c = idx & 3;
            cp16(sptr(st + ASL + r * STR + c * 8),
                 Bg + (size_t)(bCol + r) * K + k0 + c * 8);
        }
        cp_commit();
    };

    const int iters = K / 32;
    issue(0, 0);
    issue(32, 1);       // iters >= 16 at all call sites

    for (int it = 0; it < iters; it++) {
        const int cur = it % 3;
        if (it + 1 < iters) cp_wait<1>();
        else                cp_wait<0>();
        __syncthreads();   // stage `cur` ready; all warps done with stage it-1
        if (it + 2 < iters) issue((it + 2) * 32, (it + 2) % 3);

        const __half* As = smb + cur * STG;
        const __half* Bs = As + ASL;

#pragma unroll
        for (int s = 0; s < 2; s++) {
            const int kb = 16 * s + 2 * t;
            uint32_t ah[MT][4];
#pragma unroll
            for (int mt = 0; mt < MT; mt++) {
                int r0 = wm * WM + mt * 16 + g;
                int r1 = r0 + 8;
                ah[mt][0] = *reinterpret_cast<const uint32_t*>(&As[r0 * STR + kb]);
                ah[mt][1] = *reinterpret_cast<const uint32_t*>(&As[r1 * STR + kb]);
                ah[mt][2] = *reinterpret_cast<const uint32_t*>(&As[r0 * STR + kb + 8]);
                ah[mt][3] = *reinterpret_cast<const uint32_t*>(&As[r1 * STR + kb + 8]);
            }
#pragma unroll
            for (int nt = 0; nt < NT; nt++) {
                int nb = wn * WN + nt * 8 + g;
                uint32_t b0 = *reinterpret_cast<const uint32_t*>(&Bs[nb * STR + kb]);
                uint32_t b1 = *reinterpret_cast<const uint32_t*>(&Bs[nb * STR + kb + 8]);
#pragma unroll
                for (int mt = 0; mt < MT; mt++)
                    mmah(acc[mt][nt], ah[mt], b0, b1);
            }
        }
    }

#pragma unroll
    for (int mt = 0; mt < MT; mt++) {
        int r0 = bRow + wm * WM + mt * 16 + g;
#pragma unroll
        for (int nt = 0; nt < NT; nt++) {
            int col = bCol + wn * WN + nt * 8 + 2 * t;
            float bx = bias[col], by = bias[col + 1];
            float v00 = (acc[mt][nt][0] + bx) * oscale, v01 = (acc[mt][nt][1] + by) * oscale;
            float v10 = (acc[mt][nt][2] + bx) * oscale, v11 = (acc[mt][nt][3] + by) * oscale;
            if (OUT == 0) {
                float2 a = {v00, v01}, b = {v10, v11};
                *reinterpret_cast<float2*>(C + (size_t)r0 * N + col)       = a;
                *reinterpret_cast<float2*>(C + (size_t)(r0 + 8) * N + col) = b;
            } else if (OUT == 2) {
                *reinterpret_cast<uint32_t*>(&H[(size_t)r0 * N + col])       = h2pack(v00, v01);
                *reinterpret_cast<uint32_t*>(&H[(size_t)(r0 + 8) * N + col]) = h2pack(v10, v11);
            } else {
                float th = expf(-2.0f * (float)(col >> 1) / (float)RD * 9.2103403719761836f);
                int tt0 = r0 & (TT - 1);
                float sn0, cs0, sn1, cs1;
                sincosf((float)(tt0 + 1) * th, &sn0, &cs0);
                sincosf((float)(tt0 + 9) * th, &sn1, &cs1);
                float e0 = v00 * cs0 - v01 * sn0;
                float o0 = v01 * cs0 + v00 * sn0;
                float e1 = v10 * cs1 - v11 * sn1;
                float o1 = v11 * cs1 + v10 * sn1;
                *reinterpret_cast<uint32_t*>(&H[(size_t)r0 * N + col])       = h2pack(e0, o0);
                *reinterpret_cast<uint32_t*>(&H[(size_t)(r0 + 8) * N + col]) = h2pack(e1, o1);
            }
        }
    }
}

// ---------------------------------------------------------------------------
// Causal flash attention, fp16 mma.sync m16n8k16, per-batch launch.
// P in registers (QK C-fragment == PV A-fragment layout).
// ---------------------------------------------------------------------------
#define QSTH 136
#define KSTH 136
#define VSTH 72

#define OFFH_K (128 * QSTH)
#define OFFH_V (OFFH_K + 2 * 64 * KSTH)
#define ATT_HALFS (OFFH_V + 2 * 64 * VSTH)   // 44032 halfs = 88064 B

__global__ __launch_bounds__(256, 2)
void attn_fp16_kernel(int b)
{
    extern __shared__ __half smh[];
    __half* Qh = smh;

    const int tid  = threadIdx.x;
    const int lane = tid & 31;
    const int warp = tid >> 5;
    const int g    = lane >> 2;
    const int t    = lane & 3;
    const int qt   = (gridDim.x - 1) - blockIdx.x;   // heavy blocks first
    const int hh   = blockIdx.y;
    const int rowBase = b * TT + qt * 128;

    auto issueKV = [&](int j, int s) {
        __half* Kt = smh + OFFH_K + s * 64 * KSTH;
        __half* Vt = smh + OFFH_V + s * 64 * VSTH;
        const int kbase = b * TT + j * 64;
#pragma unroll
        for (int i = 0; i < 4; i++) {
            int idx = tid + i * 256;
            int r = idx >> 4, c = idx & 15;
            uint32_t d = sptr(Kt + r * KSTH + c * 8);
            if (c < 8) cp16(d, g_kvh + (size_t)(kbase + r) * 2048 + hh * 64 + c * 8);
            else       cp16(d, g_krh + (size_t)(kbase + r) * 64 + (c - 8) * 8);
        }
#pragma unroll
        for (int i = 0; i < 2; i++) {
            int idx = tid + i * 256;
            int r = idx >> 3, c = idx & 7;
            cp16(sptr(Vt + r * VSTH + c * 8),
                 g_kvh + (size_t)(kbase + r) * 2048 + 1024 + hh * 64 + c * 8);
        }
        cp_commit();
    };

#pragma unroll
    for (int i = 0; i < 8; i++) {
        int idx = tid + i * 256;
        int r = idx >> 4, c = idx & 15;
        uint32_t d = sptr(Qh + r * QSTH + c * 8);
        if (c < 8) cp16(d, g_qh  + (size_t)(rowBase + r) * 1024 + hh * 64 + c * 8);
        else       cp16(d, g_qrh + (size_t)(rowBase + r) * 1024 + hh * 64 + (c - 8) * 8);
    }
    issueKV(0, 0);

    const int vrow = (lane & 7) + ((lane >> 3) & 1) * 8;
    const int vcol = (lane >> 4) * 8;
    const uint32_t vLaneByte = (uint32_t)(vrow * VSTH + vcol) * 2;

    const int rloc0 = warp * 16 + g;
    float m0 = -1e30f, m1 = -1e30f, l0 = 0.f, l1 = 0.f;
    float o[8][4];
#pragma unroll
    for (int nt = 0; nt < 8; nt++)
#pragma unroll
        for (int i = 0; i < 4; i++) o[nt][i] = 0.f;

    const int nkt = 2 * qt + 2;
    for (int j = 0; j < nkt; j++) {
        const int s = j & 1;
        if (j + 1 < nkt) { issueKV(j + 1, s ^ 1); cp_wait<1>(); }
        else             { cp_wait<0>(); }
        __syncthreads();

        const __half* Kt = smh + OFFH_K + s * 64 * KSTH;
        const uint32_t vBuf = sptr(smh + OFFH_V + s * 64 * VSTH);

        // --- S = Q @ K^T ------------------------------------------------------
        float sc[8][4];
#pragma unroll
        for (int nt = 0; nt < 8; nt++)
#pragma unroll
            for (int i = 0; i < 4; i++) sc[nt][i] = 0.f;

#pragma unroll
        for (int ks = 0; ks < 8; ks++) {
            const int kb = ks * 16 + 2 * t;
            uint32_t a0 = *reinterpret_cast<const uint32_t*>(&Qh[(rloc0)     * QSTH + kb]);
            uint32_t a1 = *reinterpret_cast<const uint32_t*>(&Qh[(rloc0 + 8) * QSTH + kb]);
            uint32_t a2 = *reinterpret_cast<const uint32_t*>(&Qh[(rloc0)     * QSTH + kb + 8]);
            uint32_t a3 = *reinterpret_cast<const uint32_t*>(&Qh[(rloc0 + 8) * QSTH + kb + 8]);
#pragma unroll
            for (int nt = 0; nt < 8; nt++) {
                uint32_t b0 = *reinterpret_cast<const uint32_t*>(&Kt[(nt * 8 + g) * KSTH + kb]);
                uint32_t b1 = *reinterpret_cast<const uint32_t*>(&Kt[(nt * 8 + g) * KSTH + kb + 8]);
                mmah4(sc[nt], a0, a1, a2, a3, b0, b1);
            }
        }

        // --- causal mask -------------------------------------------------------
        if (j >= 2 * qt) {
            int rg0 = qt * 128 + rloc0;
            int k0 = j * 64;
#pragma unroll
            for (int nt = 0; nt < 8; nt++) {
                int cg = k0 + nt * 8 + 2 * t;
                if (cg     > rg0)     sc[nt][0] = -1e30f;
                if (cg + 1 > rg0)     sc[nt][1] = -1e30f;
                if (cg     > rg0 + 8) sc[nt][2] = -1e30f;
                if (cg + 1 > rg0 + 8) sc[nt][3] = -1e30f;
            }
        }

        // --- online softmax, P packed directly into PV A-fragments ------------
        float mx0 = -1e30f, mx1 = -1e30f;
#pragma unroll
        for (int nt = 0; nt < 8; nt++) {
            mx0 = fmaxf(mx0, fmaxf(sc[nt][0], sc[nt][1]));
            mx1 = fmaxf(mx1, fmaxf(sc[nt][2], sc[nt][3]));
        }
        mx0 = fmaxf(mx0, __shfl_xor_sync(0xffffffffu, mx0, 1));
        mx0 = fmaxf(mx0, __shfl_xor_sync(0xffffffffu, mx0, 2));
        mx1 = fmaxf(mx1, __shfl_xor_sync(0xffffffffu, mx1, 1));
        mx1 = fmaxf(mx1, __shfl_xor_sync(0xffffffffu, mx1, 2));

        float mn0 = fmaxf(m0, mx0), mn1 = fmaxf(m1, mx1);
        float al0 = __expf(m0 - mn0), al1 = __expf(m1 - mn1);
        m0 = mn0; m1 = mn1;

        uint32_t pa[8], pb[8];
        float sum0 = 0.f, sum1 = 0.f;
#pragma unroll
        for (int nt = 0; nt < 8; nt++) {
            float p0 = __expf(sc[nt][0] - mn0);
            float p1 = __expf(sc[nt][1] - mn0);
            float p2 = __expf(sc[nt][2] - mn1);
            float p3 = __expf(sc[nt][3] - mn1);
            sum0 += p0 + p1; sum1 += p2 + p3;
            pa[nt] = h2pack(p0, p1);
            pb[nt] = h2pack(p2, p3);
        }
        sum0 += __shfl_xor_sync(0xffffffffu, sum0, 1);
        sum0 += __shfl_xor_sync(0xffffffffu, sum0, 2);
        sum1 += __shfl_xor_sync(0xffffffffu, sum1, 1);
        sum1 += __shfl_xor_sync(0xffffffffu, sum1, 2);
        l0 = l0 * al0 + sum0;
        l1 = l1 * al1 + sum1;

#pragma unroll
        for (int nt = 0; nt < 8; nt++) {
            o[nt][0] *= al0; o[nt][1] *= al0;
            o[nt][2] *= al1; o[nt][3] *= al1;
        }

        // --- O += P @ V (P from registers; V via ldmatrix.trans) ---------------
#pragma unroll
        for (int ks = 0; ks < 4; ks++) {
            uint32_t a0 = pa[2 * ks];
            uint32_t a1 = pb[2 * ks];
            uint32_t a2 = pa[2 * ks + 1];
            uint32_t a3 = pb[2 * ks + 1];
#pragma unroll
            for (int ntp = 0; ntp < 4; ntp++) {
                uint32_t b0, b1, b2, b3;
                ldsm4t(b0, b1, b2, b3,
                       vBuf + vLaneByte + (uint32_t)(ks * 16 * VSTH + ntp * 16) * 2);
                mmah4(o[2*ntp],     a0, a1, a2, a3, b0, b1);
                mmah4(o[2*ntp + 1], a0, a1, a2, a3, b2, b3);
            }
        }
        __syncthreads();
    }

    float inv0 = 1.0f / l0, inv1 = 1.0f / l1;
    int rg = rowBase + rloc0;
#pragma unroll
    for (int nt = 0; nt < 8; nt++) {
        int col = hh * 64 + nt * 8 + 2 * t;
        *reinterpret_cast<uint32_t*>(&g_ath[(size_t)rg       * 1024 + col]) =
            h2pack(o[nt][0] * inv0, o[nt][1] * inv0);
        *reinterpret_cast<uint32_t*>(&g_ath[(size_t)(rg + 8) * 1024 + col]) =
            h2pack(o[nt][2] * inv1, o[nt][3] * inv1);
    }
}

// ---------------------------------------------------------------------------
// Launch — fork/join; attention split per batch, wo split per row-half.
// ---------------------------------------------------------------------------
extern "C" void kernel_launch(void* const* d_in, const int* in_sizes, int n_in,
                              void* d_out, int out_size)
{
    (void)in_sizes; (void)n_in; (void)out_size;
    const float* x   = (const float*)d_in[0];
    const float* w1  = (const float*)d_in[1];
    const float* b1  = (const float*)d_in[2];
    const float* wkr = (const float*)d_in[3];
    const float* bkr = (const float*)d_in[4];
    const float* wqr = (const float*)d_in[5];
    const float* bqr = (const float*)d_in[6];
    const float* wkv = (const float*)d_in[7];
    const float* bkv = (const float*)d_in[8];
    const float* wq  = (const float*)d_in[9];
    const float* bq  = (const float*)d_in[10];
    const float* wo  = (const float*)d_in[11];
    const float* bo  = (const float*)d_in[12];
    float* out = (float*)d_out;
    const float scale = 0.08838834764831845f;   // 128^-0.5

    __half *qh_, *qrh_, *krh_, *kvh_, *ath_, *xh_, *hh_;
    __half *w1f_, *wkrf_, *wqrf_, *wkvf_, *wqf_, *wof_;
    cudaGetSymbolAddress((void**)&qh_,  g_qh);
    cudaGetSymbolAddress((void**)&qrh_, g_qrh);
    cudaGetSymbolAddress((void**)&krh_, g_krh);
    cudaGetSymbolAddress((void**)&kvh_, g_kvh);
    cudaGetSymbolAddress((void**)&ath_, g_ath);
    cudaGetSymbolAddress((void**)&xh_,  g_xh);
    cudaGetSymbolAddress((void**)&hh_,  g_hh);
    cudaGetSymbolAddress((void**)&w1f_,  g_w1f);
    cudaGetSymbolAddress((void**)&wkrf_, g_wkrf);
    cudaGetSymbolAddress((void**)&wqrf_, g_wqrf);
    cudaGetSymbolAddress((void**)&wkvf_, g_wkvf);
    cudaGetSymbolAddress((void**)&wqf_,  g_wqf);
    cudaGetSymbolAddress((void**)&wof_,  g_wof);

    const int SMG_128 = 3 * (128 * 40 + 128 * 40) * 2;   // 61440 (3-stage)
    const int SMG_64  = 3 * (128 * 40 + 64 * 40) * 2;    // 46080
    const int SMAT    = ATT_HALFS * 2;                    // 88064
    cudaFuncSetAttribute(gemm_f16<128, 0, 0>,    cudaFuncAttributeMaxDynamicSharedMemorySize, SMG_128);
    cudaFuncSetAttribute(gemm_f16<128, 2, 0>,    cudaFuncAttributeMaxDynamicSharedMemorySize, SMG_128);
    cudaFuncSetAttribute(gemm_f16<128, 3, 1024>, cudaFuncAttributeMaxDynamicSharedMemorySize, SMG_128);
    cudaFuncSetAttribute(gemm_f16<64,  3, 64>,   cudaFuncAttributeMaxDynamicSharedMemorySize, SMG_64);
    cudaFuncSetAttribute(attn_fp16_kernel, cudaFuncAttributeMaxDynamicSharedMemorySize, SMAT);

    static cudaStream_t s1 = nullptr, s2 = nullptr, s3 = nullptr;
    static cudaEvent_t evFork, evX, evH, evD1, evD2, evD3, evWoS, evW1;
    if (s1 == nullptr) {
        cudaStreamCreateWithFlags(&s1, cudaStreamNonBlocking);
        cudaStreamCreateWithFlags(&s2, cudaStreamNonBlocking);
        cudaStreamCreateWithFlags(&s3, cudaStreamNonBlocking);
        cudaEventCreateWithFlags(&evFork, cudaEventDisableTiming);
        cudaEventCreateWithFlags(&evX,    cudaEventDisableTiming);
        cudaEventCreateWithFlags(&evH,    cudaEventDisableTiming);
        cudaEventCreateWithFlags(&evD1,   cudaEventDisableTiming);
        cudaEventCreateWithFlags(&evD2,   cudaEventDisableTiming);
        cudaEventCreateWithFlags(&evD3,   cudaEventDisableTiming);
        cudaEventCreateWithFlags(&evWoS,  cudaEventDisableTiming);
        cudaEventCreateWithFlags(&evW1,   cudaEventDisableTiming);
    }

    dim3 wsb(32, 8);

    // fork
    cudaEventRecord(evFork, 0);
    cudaStreamWaitEvent(s1, evFork, 0);
    cudaStreamWaitEvent(s2, evFork, 0);
    cudaStreamWaitEvent(s3, evFork, 0);

    // main: w1 transpose; s1: x convert (feeds h GEMM)
    wsplit_kernel<<<dim3(1024/32, 1024/32), wsb, 0, 0>>>(w1, 1024, 1024, w1f_);
    aconv_kernel<<<(MR * 1024 / 4 + 255) / 256, 256, 0, s1>>>(
        (const float4*)x, (uint2*)xh_, MR * 1024 / 4);
    cudaEventRecord(evX, s1);

    // other weight transposes overlap h GEMM
    wsplit_kernel<<<dim3(1024/32, 1024/32), wsb, 0, s1>>>(wqr, 1024, 1024, wqrf_);
    wsplit_kernel<<<dim3(2048/32, 512/32),  wsb, 0, s2>>>(wkv, 512,  2048, wkvf_);
    wsplit_kernel<<<dim3(1024/32, 512/32),  wsb, 0, s3>>>(wq,  512,  1024, wqf_);
    wsplit_kernel<<<dim3(64/32,   1024/32), wsb, 0, s3>>>(wkr, 1024, 64,   wkrf_);
    wsplit_kernel<<<dim3(1024/32, 1024/32), wsb, 0, s3>>>(wo,  1024, 1024, wof_);
    cudaEventRecord(evWoS, s3);

    // 1) h = x @ w1 + b1 -> fp16 (main stream)
    cudaStreamWaitEvent(0, evX, 0);
    gemm_f16<128, 2, 0><<<dim3(8, 32), 256, SMG_128, 0>>>(
        1024, 1024, 0, xh_, 1024, w1f_, b1, 1.f, nullptr, hh_);
    cudaEventRecord(evH, 0);

    // 3) qr = rope((h @ wqr + bqr) * scale) -> fp16   (s1)
    cudaStreamWaitEvent(s1, evH, 0);
    gemm_f16<128, 3, 1024><<<dim3(8, 32), 256, SMG_128, s1>>>(
        1024, 1024, 0, hh_, 1024, wqrf_, bqr, scale, nullptr, qrh_);
    cudaEventRecord(evD1, s1);

    // 4) kv = cKV @ wkv + bkv -> fp16                 (s2)
    cudaStreamWaitEvent(s2, evH, 0);
    gemm_f16<128, 2, 0><<<dim3(16, 32), 256, SMG_128, s2>>>(
        2048, 512, 0, hh_, 1024, wkvf_, bkv, 1.f, nullptr, kvh_);
    cudaEventRecord(evD2, s2);

    // 5) q = (cq @ wq + bq) * scale ; 2) kr = rope(h @ wkr + bkr)   (s3)
    cudaStreamWaitEvent(s3, evH, 0);
    gemm_f16<128, 2, 0><<<dim3(8, 32), 256, SMG_128, s3>>>(
        1024, 512, 0, hh_ + 512, 1024, wqf_, bq, scale, nullptr, qh_);
    gemm_f16<64, 3, 64><<<dim3(1, 32), 256, SMG_64, s3>>>(
        64, 1024, 0, hh_, 1024, wkrf_, bkr, 1.f, nullptr, krh_);
    cudaEventRecord(evD3, s3);

    // join on producers for both attention launches
    cudaStreamWaitEvent(0, evD1, 0);
    cudaStreamWaitEvent(0, evD2, 0);
    cudaStreamWaitEvent(0, evD3, 0);
    cudaStreamWaitEvent(s1, evD2, 0);   // s1 already ordered after evD1 (its own work)
    cudaStreamWaitEvent(s1, evD3, 0);

    // 6) attention per batch: b=0 on main, b=1 on s1 (run concurrently)
    attn_fp16_kernel<<<dim3(16, NH, 1), 256, SMAT, 0>>>(0);
    attn_fp16_kernel<<<dim3(16, NH, 1), 256, SMAT, s1>>>(1);

    // 7) wo halves start as soon as their batch's attention finishes
    cudaStreamWaitEvent(0, evWoS, 0);
    gemm_f16<128, 0, 0><<<dim3(8, 16), 256, SMG_128, 0>>>(
        1024, 1024, 0, ath_, 1024, wof_, bo, 1.f, out, nullptr);
    cudaStreamWaitEvent(s1, evWoS, 0);
    gemm_f16<128, 0, 0><<<dim3(8, 16), 256, SMG_128, s1>>>(
        1024, 1024, TT, ath_, 1024, wof_, bo, 1.f, out, nullptr);
    cudaEventRecord(evW1, s1);

    // final join
    cudaStreamWaitEvent(0, evW1, 0);
}